// round 3
// baseline (speedup 1.0000x reference)
#include <cuda_runtime.h>
#include <cuda_bf16.h>
#include <cstdint>

// Geometry:
//  stage0 in : [5][256][3][16][32]
//  y1 (stem) : 16ch @16x32, NP0 = 5*256*512 = 655360
//  block1    : 64ch @8x16,  NP1 = 5*256*128 = 163840
//  block2    : 256ch@4x8,   NP2 = 5*256*32  = 40960
// Activation layout: chan-major t[c*NP + (((f*256+b)*H+h)*W+w)]

#define NP0 655360
#define NP1 163840
#define NP2 40960

// ------------------------- device scratch ----------------------------------
__device__ float g_y1[16 * NP0];
__device__ float g_u1[64 * NP1];
__device__ float g_v1[64 * NP1];
__device__ float g_h1[64 * NP1];
__device__ float g_w1[64 * NP1];
__device__ float g_u2[256 * NP2];
__device__ float g_v2[256 * NP2];
__device__ float g_h2[256 * NP2];
__device__ float g_w2[256 * NP2];
__device__ float g_gmax[256 * 256];

__device__ float g_psum[1310720];
__device__ float g_psq [1310720];

// folded BN affine: offsets bn1:0(16) b1a:16 b1b:80 b1c:144 b1d:208
//                   b2a:272 b2b:528 b2c:784 b2d:1040   (total 1296)
__device__ float g_scale[1296];
__device__ float g_shift[1296];

__device__ float g_wt_b1c1[16 * 64];
__device__ float g_wt_b1ds[16 * 64];
__device__ float g_wt_b1c3[64 * 64];
__device__ float g_wt_b2c1[64 * 256];
__device__ float g_wt_b2ds[64 * 256];
__device__ float g_wt_b2c3[256 * 256];
__device__ float g_a2_b1 [448 * 64];     // [(c*7+t)][o]
__device__ float g_a2_b2 [1792 * 256];

// ------------------------- prep kernels ------------------------------------
__global__ void transpose_k(const float* __restrict__ src, float* __restrict__ dst,
                            int O, int C) {
    int i = blockIdx.x * 256 + threadIdx.x;
    if (i < O * C) { int o = i / C, c = i % C; dst[c * O + o] = src[i]; }
}

// hex weights [O][C][3][3] -> A2[(c*7+t)][O]; kept taps are flat 3x3 idx 1..7
__global__ void hexgather_k(const float* __restrict__ src, float* __restrict__ dst,
                            int O, int C) {
    int i = blockIdx.x * 256 + threadIdx.x;
    if (i < O * C * 7) {
        int o = i % O;
        int kt = i / O;
        int c = kt / 7, t = kt % 7;
        dst[i] = src[(o * C + c) * 9 + t + 1];
    }
}

// ------------------------- stem --------------------------------------------
__global__ __launch_bounds__(256) void stem_kernel(
    const float* __restrict__ x, const float* __restrict__ wc,
    float* __restrict__ y1, float* __restrict__ psum, float* __restrict__ psq) {
    __shared__ float wsh[432];
    __shared__ float wpS[16][8], wpQ[16][8];
    int tid = threadIdx.x;
    for (int e = tid; e < 432; e += 256) wsh[e] = wc[e];
    __syncthreads();

    int pos = blockIdx.x * 256 + tid;
    int w = pos & 31, h = (pos >> 5) & 15, b = (pos >> 9) & 255, f = pos >> 17;

    float acc[16];
#pragma unroll
    for (int o = 0; o < 16; o++) acc[o] = 0.f;

#pragma unroll
    for (int t = 0; t < 7; t++) {
        int kf = t + 1;
        int dy = kf / 3 - 1, dx = kf % 3 - 1;
        int hh = h + dy;
        float xv0 = 0.f, xv1 = 0.f, xv2 = 0.f;
        if (hh >= 0 && hh < 16) {
            int ww = w + dx, ff = f;
            if (ww < 0)       { ff = (f + 4) % 5; ww = 31; }
            else if (ww > 31) { ff = (f + 1) % 5; ww = 0;  }
            int base = (ff * 256 + b) * 1536 + hh * 32 + ww;   // c stride 512
            xv0 = x[base];
            xv1 = x[base + 512];
            xv2 = x[base + 1024];
        }
#pragma unroll
        for (int o = 0; o < 16; o++) {
            acc[o] += wsh[(o * 3 + 0) * 9 + kf] * xv0
                    + wsh[(o * 3 + 1) * 9 + kf] * xv1
                    + wsh[(o * 3 + 2) * 9 + kf] * xv2;
        }
    }

    int lane = tid & 31, warp = tid >> 5;
#pragma unroll
    for (int o = 0; o < 16; o++) {
        float val = fmaxf(acc[o], 0.f);
        y1[o * NP0 + pos] = val;
        float s = val, q2 = val * val;
#pragma unroll
        for (int d = 16; d; d >>= 1) {
            s  += __shfl_xor_sync(0xFFFFFFFFu, s,  d);
            q2 += __shfl_xor_sync(0xFFFFFFFFu, q2, d);
        }
        if (lane == 0) { wpS[o][warp] = s; wpQ[o][warp] = q2; }
    }
    __syncthreads();
    if (tid < 16) {
        float s = 0.f, q = 0.f;
#pragma unroll
        for (int wpi = 0; wpi < 8; wpi++) { s += wpS[tid][wpi]; q += wpQ[tid][wpi]; }
        psum[blockIdx.x * 16 + tid] = s;
        psq [blockIdx.x * 16 + tid] = q;
    }
}

// ------------------------- BN param fold ------------------------------------
__global__ void bn_param(const float* __restrict__ ps, const float* __restrict__ pq,
                         int nparts, int cstride, int coff, float invN,
                         const float* __restrict__ g, const float* __restrict__ b,
                         float* __restrict__ sc, float* __restrict__ sh) {
    int c = blockIdx.x, tid = threadIdx.x;
    float s = 0.f, q = 0.f;
    for (int p = tid; p < nparts; p += 256) {
        s += ps[(size_t)p * cstride + coff + c];
        q += pq[(size_t)p * cstride + coff + c];
    }
    __shared__ float rs[256], rq[256];
    rs[tid] = s; rq[tid] = q;
    __syncthreads();
    for (int d = 128; d; d >>= 1) {
        if (tid < d) { rs[tid] += rs[tid + d]; rq[tid] += rq[tid + d]; }
        __syncthreads();
    }
    if (tid == 0) {
        float mean = rs[0] * invN;
        float var  = rq[0] * invN - mean * mean;
        float k = g[c] * rsqrtf(var + 1e-5f);
        sc[c] = k;
        sh[c] = b[c] - mean * k;
    }
}

// -------------- resblock entry: dual 1x1 conv + fused 2x2 maxpool -----------
// input act: DUAL ? relu(s1*xa+t1 + s2*xb+t2) : (s1*xa+t1).
// outputs raw (pre-BN) u (main path), v (downsample) + per-channel stats.
template <int CIN, int COUT, int HIN, int WIN, bool DUAL>
__global__ __launch_bounds__(256) void entry_kernel(
    const float* __restrict__ xa, const float* __restrict__ xb,
    const float* __restrict__ w1t, const float* __restrict__ w2t,
    const float* __restrict__ s1, const float* __restrict__ t1,
    const float* __restrict__ s2, const float* __restrict__ t2,
    float* __restrict__ u, float* __restrict__ v,
    float* __restrict__ psum, float* __restrict__ psq) {
    constexpr int HO = HIN / 2, WO = WIN / 2;
    constexpr int NPIN  = 5 * 256 * HIN * WIN;
    constexpr int NPOUT = 5 * 256 * HO * WO;

    __shared__ __align__(16) float actsh[CIN * 64];
    __shared__ __align__(16) float wsh[CIN * 64];
    __shared__ float stage[64 * 17];

    int tid = threadIdx.x;
    int q0 = blockIdx.x * 16;

    // 16 output positions -> 64 input positions (4 pooled candidates each)
    for (int e = tid; e < CIN * 64; e += 256) {
        int c = e >> 6, lp = e & 63;
        int q = q0 + (lp >> 2), sub = lp & 3;
        int w = q % WO;
        int h = (q / WO) % HO;
        int fb = q / (WO * HO);
        int p = (fb * HIN + 2 * h + (sub >> 1)) * WIN + 2 * w + (sub & 1);
        float val = s1[c] * xa[(size_t)c * NPIN + p] + t1[c];
        if (DUAL) {
            val += s2[c] * xb[(size_t)c * NPIN + p] + t2[c];
            val = fmaxf(val, 0.f);
        }
        actsh[e] = val;
    }

    int ob = (tid & 15) * 4;   // 4 output channels
    int ql = tid >> 4;         // 1 output position

    for (int path = 0; path < 2; path++) {
        const float* wt = path ? w2t : w1t;
        float* outp = path ? v : u;
        for (int oc = 0; oc < COUT; oc += 64) {
            __syncthreads();
            for (int e = tid; e < CIN * 64; e += 256) {
                int c = e >> 6, o = e & 63;
                wsh[e] = wt[c * COUT + oc + o];
            }
            __syncthreads();

            float acc[4][4];
#pragma unroll
            for (int i = 0; i < 4; i++)
#pragma unroll
                for (int j = 0; j < 4; j++) acc[i][j] = 0.f;

#pragma unroll 8
            for (int c = 0; c < CIN; c++) {
                float4 a = *(const float4*)(wsh + c * 64 + ob);
                float4 bq = *(const float4*)(actsh + c * 64 + ql * 4);
                float av[4] = {a.x, a.y, a.z, a.w};
                float bv[4] = {bq.x, bq.y, bq.z, bq.w};
#pragma unroll
                for (int i = 0; i < 4; i++)
#pragma unroll
                    for (int j = 0; j < 4; j++) acc[i][j] += av[i] * bv[j];
            }
#pragma unroll
            for (int i = 0; i < 4; i++) {
                float val = fmaxf(fmaxf(acc[i][0], acc[i][1]),
                                  fmaxf(acc[i][2], acc[i][3]));
                outp[(size_t)(oc + ob + i) * NPOUT + q0 + ql] = val;
                stage[(ob + i) * 17 + ql] = val;
            }
            __syncthreads();
            if (tid < 64) {
                float s = 0.f, q = 0.f;
#pragma unroll
                for (int k = 0; k < 16; k++) {
                    float vv = stage[tid * 17 + k];
                    s += vv; q += vv * vv;
                }
                psum[(size_t)blockIdx.x * (2 * COUT) + path * COUT + oc + tid] = s;
                psq [(size_t)blockIdx.x * (2 * COUT) + path * COUT + oc + tid] = q;
            }
        }
    }
}

// ------------------ unified implicit-GEMM conv ------------------------------
// act = relu(sa[c]*x + ta[c]); TAPS=7 hexconv (chart-wrap nbr table), TAPS=1 1x1.
template <int CIN, int COUT, int H, int W, int TAPS, int CB>
__global__ __launch_bounds__(256) void gemm_conv(
    const float* __restrict__ xin, const float* __restrict__ a2,
    const float* __restrict__ sa, const float* __restrict__ ta,
    float* __restrict__ out, float* __restrict__ psum, float* __restrict__ psq) {
    constexpr int NP = 5 * 256 * H * W;
    constexpr int KC = CB * TAPS;

    __shared__ __align__(16) float Ash[KC * 64];
    __shared__ __align__(16) float Bsh[KC * 64];
    __shared__ int nbr[TAPS * 64];
    __shared__ float partS[64 * 16], partQ[64 * 16];

    int tid = threadIdx.x;
    int q0 = blockIdx.x * 64;
    int o0 = blockIdx.y * 64;

    for (int e = tid; e < TAPS * 64; e += 256) {
        int t = e >> 6, ql = e & 63;
        int q = q0 + ql;
        int pos;
        if (TAPS == 1) pos = q;
        else {
            int w = q % W;
            int h = (q / W) % H;
            int b = (q / (W * H)) & 255;
            int f = q / (W * H * 256);
            int kf = t + 1;
            int dy = kf / 3 - 1, dx = kf % 3 - 1;
            int hh = h + dy, ww = w + dx, ff = f;
            if (hh < 0 || hh >= H) pos = -1;
            else {
                if (ww < 0)      { ff = (f + 4) % 5; ww = W - 1; }
                else if (ww >= W){ ff = (f + 1) % 5; ww = 0;     }
                pos = ((ff * 256 + b) * H + hh) * W + ww;
            }
        }
        nbr[e] = pos;
    }
    __syncthreads();

    float acc[4][4];
#pragma unroll
    for (int i = 0; i < 4; i++)
#pragma unroll
        for (int j = 0; j < 4; j++) acc[i][j] = 0.f;

    int ob = (tid & 15) * 4;
    int qb = (tid >> 4) * 4;

    for (int c0 = 0; c0 < CIN; c0 += CB) {
        for (int e = tid; e < KC * 64; e += 256) {
            int kk = e >> 6, o = e & 63;
            Ash[e] = a2[(size_t)(c0 * TAPS + kk) * COUT + o0 + o];
        }
        for (int e = tid; e < KC * 64; e += 256) {
            int kk = e >> 6, ql = e & 63;
            int cl = kk / TAPS, t = kk % TAPS;
            int c = c0 + cl;
            int pos = nbr[t * 64 + ql];
            float val = 0.f;
            if (pos >= 0)
                val = fmaxf(sa[c] * xin[(size_t)c * NP + pos] + ta[c], 0.f);
            Bsh[e] = val;
        }
        __syncthreads();
#pragma unroll
        for (int kk = 0; kk < KC; kk++) {
            float4 a = *(const float4*)(Ash + kk * 64 + ob);
            float4 b = *(const float4*)(Bsh + kk * 64 + qb);
            float av[4] = {a.x, a.y, a.z, a.w};
            float bv[4] = {b.x, b.y, b.z, b.w};
#pragma unroll
            for (int i = 0; i < 4; i++)
#pragma unroll
                for (int j = 0; j < 4; j++) acc[i][j] += av[i] * bv[j];
        }
        __syncthreads();
    }

    int qg = tid >> 4;
#pragma unroll
    for (int i = 0; i < 4; i++) {
        float4 st = {acc[i][0], acc[i][1], acc[i][2], acc[i][3]};
        *(float4*)(out + (size_t)(o0 + ob + i) * NP + q0 + qb) = st;
        float s = acc[i][0] + acc[i][1] + acc[i][2] + acc[i][3];
        float q = acc[i][0]*acc[i][0] + acc[i][1]*acc[i][1]
                + acc[i][2]*acc[i][2] + acc[i][3]*acc[i][3];
        partS[(ob + i) * 16 + qg] = s;
        partQ[(ob + i) * 16 + qg] = q;
    }
    __syncthreads();
    if (tid < 64) {
        float s = 0.f, q = 0.f;
#pragma unroll
        for (int k = 0; k < 16; k++) { s += partS[tid * 16 + k]; q += partQ[tid * 16 + k]; }
        psum[(size_t)blockIdx.x * COUT + o0 + tid] = s;
        psq [(size_t)blockIdx.x * COUT + o0 + tid] = q;
    }
}

// ------------- final: BN+add+relu, global max over charts+spatial -----------
__global__ __launch_bounds__(256) void maxfin_k(
    const float* __restrict__ w2, const float* __restrict__ v2,
    const float* __restrict__ scC, const float* __restrict__ shC,
    const float* __restrict__ scD, const float* __restrict__ shD,
    float* __restrict__ gmax) {
    int o = blockIdx.x, tid = threadIdx.x;
    __shared__ int mx[256];
    mx[tid] = 0;
    __syncthreads();
    float a = scC[o], c_ = shC[o], d = scD[o], e = shD[o];
    const float* wp = w2 + (size_t)o * NP2;
    const float* vp = v2 + (size_t)o * NP2;
    for (int i = tid; i < NP2; i += 256) {
        float val = fmaxf(a * wp[i] + c_ + d * vp[i] + e, 0.f);
#pragma unroll
        for (int s = 16; s; s >>= 1)
            val = fmaxf(val, __shfl_xor_sync(0xFFFFFFFFu, val, s));
        if ((tid & 31) == 0)
            atomicMax(&mx[(i >> 5) & 255], __float_as_int(val));  // batch = (i>>5)&255
    }
    __syncthreads();
    gmax[tid * 256 + o] = __int_as_float(mx[tid]);  // tid = batch
}

__global__ void fc_k(const float* __restrict__ gmax, const float* __restrict__ fw,
                     const float* __restrict__ fb, float* __restrict__ out) {
    int b = blockIdx.x, tid = threadIdx.x;
    __shared__ float m[256];
    m[tid] = gmax[b * 256 + tid];
    __syncthreads();
    if (tid < 10) {
        float acc = fb[tid];
        for (int o = 0; o < 256; o++) acc += m[o] * fw[tid * 256 + o];
        out[b * 10 + tid] = acc;
    }
}

// ------------------------- launch ------------------------------------------
extern "C" void kernel_launch(void* const* d_in, const int* in_sizes, int n_in,
                              void* d_out, int out_size) {
    (void)n_in; (void)out_size;

    const float* x = (const float*)d_in[0];

    float *y1,*u1,*v1,*h1,*w1,*u2,*v2,*h2,*w2,*gmax,*ps,*pq,*sc,*sh;
    float *t_b1c1,*t_b1ds,*t_b1c3,*t_b2c1,*t_b2ds,*t_b2c3,*a2b1,*a2b2;
    cudaGetSymbolAddress((void**)&y1, g_y1);
    cudaGetSymbolAddress((void**)&u1, g_u1);
    cudaGetSymbolAddress((void**)&v1, g_v1);
    cudaGetSymbolAddress((void**)&h1, g_h1);
    cudaGetSymbolAddress((void**)&w1, g_w1);
    cudaGetSymbolAddress((void**)&u2, g_u2);
    cudaGetSymbolAddress((void**)&v2, g_v2);
    cudaGetSymbolAddress((void**)&h2, g_h2);
    cudaGetSymbolAddress((void**)&w2, g_w2);
    cudaGetSymbolAddress((void**)&gmax, g_gmax);
    cudaGetSymbolAddress((void**)&ps, g_psum);
    cudaGetSymbolAddress((void**)&pq, g_psq);
    cudaGetSymbolAddress((void**)&sc, g_scale);
    cudaGetSymbolAddress((void**)&sh, g_shift);
    cudaGetSymbolAddress((void**)&t_b1c1, g_wt_b1c1);
    cudaGetSymbolAddress((void**)&t_b1ds, g_wt_b1ds);
    cudaGetSymbolAddress((void**)&t_b1c3, g_wt_b1c3);
    cudaGetSymbolAddress((void**)&t_b2c1, g_wt_b2c1);
    cudaGetSymbolAddress((void**)&t_b2ds, g_wt_b2ds);
    cudaGetSymbolAddress((void**)&t_b2c3, g_wt_b2c3);
    cudaGetSymbolAddress((void**)&a2b1, g_a2_b1);
    cudaGetSymbolAddress((void**)&a2b2, g_a2_b2);

    // ---- input index tables: disambiguate metadata order at runtime ----
    // dict order (setup_inputs insertion): in_sizes[5] == 64*64*9 (b1_hexw)
    // signature order:                     in_sizes[5] == 64     (b1_g_a)
    int I_b1c1, I_b1hex, I_b1c3, I_b1ds;
    int I_b1ga, I_b1ba, I_b1gb, I_b1bb, I_b1gc, I_b1bc, I_b1gd, I_b1bd;
    int I_b2c1, I_b2hex, I_b2c3, I_b2ds;
    int I_b2ga, I_b2ba, I_b2gb, I_b2bb, I_b2gc, I_b2bc, I_b2gd, I_b2bd;
    int I_fcw, I_fcb;
    if (in_sizes[5] == 36864) {
        // dict order
        I_b1c1 = 4;  I_b1hex = 5;  I_b1c3 = 6;  I_b1ds = 7;
        I_b1ga = 8;  I_b1ba = 9;  I_b1gb = 10; I_b1bb = 11;
        I_b1gc = 12; I_b1bc = 13; I_b1gd = 14; I_b1bd = 15;
        I_b2c1 = 16; I_b2hex = 17; I_b2c3 = 18; I_b2ds = 19;
        I_b2ga = 20; I_b2ba = 21; I_b2gb = 22; I_b2bb = 23;
        I_b2gc = 24; I_b2bc = 25; I_b2gd = 26; I_b2bd = 27;
        I_fcw = 28;  I_fcb = 29;
    } else {
        // signature order
        I_b1c1 = 4;  I_b1ga = 5;  I_b1ba = 6;  I_b1hex = 7;
        I_b1gb = 8;  I_b1bb = 9;  I_b1c3 = 10; I_b1gc = 11; I_b1bc = 12;
        I_b1ds = 13; I_b1gd = 14; I_b1bd = 15;
        I_b2c1 = 16; I_b2ga = 17; I_b2ba = 18; I_b2hex = 19;
        I_b2gb = 20; I_b2bb = 21; I_b2c3 = 22; I_b2gc = 23; I_b2bc = 24;
        I_b2ds = 25; I_b2gd = 26; I_b2bd = 27;
        I_fcw = 28;  I_fcb = 29;
    }

    // weight prep
    transpose_k<<<4,   256>>>((const float*)d_in[I_b1c1], t_b1c1, 64, 16);
    transpose_k<<<4,   256>>>((const float*)d_in[I_b1ds], t_b1ds, 64, 16);
    transpose_k<<<16,  256>>>((const float*)d_in[I_b1c3], t_b1c3, 64, 64);
    transpose_k<<<64,  256>>>((const float*)d_in[I_b2c1], t_b2c1, 256, 64);
    transpose_k<<<64,  256>>>((const float*)d_in[I_b2ds], t_b2ds, 256, 64);
    transpose_k<<<256, 256>>>((const float*)d_in[I_b2c3], t_b2c3, 256, 256);
    hexgather_k<<<112, 256>>>((const float*)d_in[I_b1hex], a2b1, 64, 64);
    hexgather_k<<<1792,256>>>((const float*)d_in[I_b2hex], a2b2, 256, 256);

    // stem + bn1 fold
    stem_kernel<<<NP0 / 256, 256>>>(x, (const float*)d_in[1], y1, ps, pq);
    bn_param<<<16, 256>>>(ps, pq, NP0 / 256, 16, 0, 1.f / NP0,
                          (const float*)d_in[2], (const float*)d_in[3], sc + 0, sh + 0);

    // block1 entry (y1 w/ bn1 affine) -> u1, v1
    entry_kernel<16, 64, 16, 32, false><<<NP1 / 16, 256>>>(
        y1, nullptr, t_b1c1, t_b1ds, sc + 0, sh + 0, nullptr, nullptr, u1, v1, ps, pq);
    bn_param<<<64, 256>>>(ps, pq, NP1 / 16, 128, 0,  1.f / NP1,
                          (const float*)d_in[I_b1ga], (const float*)d_in[I_b1ba], sc + 16,  sh + 16);
    bn_param<<<64, 256>>>(ps, pq, NP1 / 16, 128, 64, 1.f / NP1,
                          (const float*)d_in[I_b1gd], (const float*)d_in[I_b1bd], sc + 208, sh + 208);

    // block1 hexconv (relu(bnA(u1))) -> h1
    gemm_conv<64, 64, 8, 16, 7, 8><<<dim3(NP1 / 64, 1), 256>>>(
        u1, a2b1, sc + 16, sh + 16, h1, ps, pq);
    bn_param<<<64, 256>>>(ps, pq, NP1 / 64, 64, 0, 1.f / NP1,
                          (const float*)d_in[I_b1gb], (const float*)d_in[I_b1bb], sc + 80, sh + 80);

    // block1 conv3 1x1 (relu(bnB(h1))) -> w1
    gemm_conv<64, 64, 8, 16, 1, 32><<<dim3(NP1 / 64, 1), 256>>>(
        h1, t_b1c3, sc + 80, sh + 80, w1, ps, pq);
    bn_param<<<64, 256>>>(ps, pq, NP1 / 64, 64, 0, 1.f / NP1,
                          (const float*)d_in[I_b1gc], (const float*)d_in[I_b1bc], sc + 144, sh + 144);

    // block2 entry (relu(bnC(w1)+bnD(v1))) -> u2, v2
    entry_kernel<64, 256, 8, 16, true><<<NP2 / 16, 256>>>(
        w1, v1, t_b2c1, t_b2ds, sc + 144, sh + 144, sc + 208, sh + 208, u2, v2, ps, pq);
    bn_param<<<256, 256>>>(ps, pq, NP2 / 16, 512, 0,   1.f / NP2,
                           (const float*)d_in[I_b2ga], (const float*)d_in[I_b2ba], sc + 272,  sh + 272);
    bn_param<<<256, 256>>>(ps, pq, NP2 / 16, 512, 256, 1.f / NP2,
                           (const float*)d_in[I_b2gd], (const float*)d_in[I_b2bd], sc + 1040, sh + 1040);

    // block2 hexconv -> h2
    gemm_conv<256, 256, 4, 8, 7, 8><<<dim3(NP2 / 64, 4), 256>>>(
        u2, a2b2, sc + 272, sh + 272, h2, ps, pq);
    bn_param<<<256, 256>>>(ps, pq, NP2 / 64, 256, 0, 1.f / NP2,
                           (const float*)d_in[I_b2gb], (const float*)d_in[I_b2bb], sc + 528, sh + 528);

    // block2 conv3 1x1 -> w2
    gemm_conv<256, 256, 4, 8, 1, 32><<<dim3(NP2 / 64, 4), 256>>>(
        h2, t_b2c3, sc + 528, sh + 528, w2, ps, pq);
    bn_param<<<256, 256>>>(ps, pq, NP2 / 64, 256, 0, 1.f / NP2,
                           (const float*)d_in[I_b2gc], (const float*)d_in[I_b2bc], sc + 784, sh + 784);

    // tail: bn+add+relu+globalmax, fc
    maxfin_k<<<256, 256>>>(w2, v2, sc + 784, sh + 784, sc + 1040, sh + 1040, gmax);
    fc_k<<<256, 256>>>(gmax, (const float*)d_in[I_fcw], (const float*)d_in[I_fcb], (float*)d_out);
}

// round 7
// speedup vs baseline: 1.0757x; 1.0757x over previous
#include <cuda_runtime.h>
#include <cuda_bf16.h>
#include <cstdint>

// Geometry:
//  stage0 in : [5][256][3][16][32]
//  y1 (stem) : 16ch @16x32, NP0 = 5*256*512 = 655360
//  block1    : 64ch @8x16,  NP1 = 5*256*128 = 163840
//  block2    : 256ch@4x8,   NP2 = 5*256*32  = 40960
// Activation layout: chan-major t[c*NP + (((f*256+b)*H+h)*W+w)]

#define NP0 655360
#define NP1 163840
#define NP2 40960

// ------------------------- device scratch ----------------------------------
__device__ float g_y1[16 * NP0];
__device__ float g_u1[64 * NP1];
__device__ float g_v1[64 * NP1];
__device__ float g_h1[64 * NP1];
__device__ float g_w1[64 * NP1];
__device__ float g_u2[256 * NP2];
__device__ float g_v2[256 * NP2];
__device__ float g_h2[256 * NP2];
__device__ float g_w2[256 * NP2];
__device__ float g_gmax[256 * 256];

__device__ float g_psum[1310720];
__device__ float g_psq [1310720];

__device__ float g_scale[1296];
__device__ float g_shift[1296];

__device__ float g_wt_b1c1[16 * 64];
__device__ float g_wt_b1ds[16 * 64];
__device__ float g_wt_b1c3[64 * 64];
__device__ float g_wt_b2c1[64 * 256];
__device__ float g_wt_b2ds[64 * 256];
__device__ float g_wt_b2c3[256 * 256];
__device__ float g_a2_b1 [448 * 64];     // [(c*7+t)][o]

// split bf16 hex weights for block2 mma path: [o][c*8+t], tap7 = 0
__device__ __nv_bfloat16 g_whex_hi[256 * 2048];
__device__ __nv_bfloat16 g_whex_lo[256 * 2048];
// split bf16 activations relu(aff(u2)): [c][q]
__device__ __nv_bfloat16 g_abf_hi[256 * NP2];
__device__ __nv_bfloat16 g_abf_lo[256 * NP2];

// ------------------------- mma helpers -------------------------------------
__device__ __forceinline__ uint32_t smem_u32(const void* p) {
    uint32_t a;
    asm("{ .reg .u64 t; cvta.to.shared.u64 t, %1; cvt.u32.u64 %0, t; }"
        : "=r"(a) : "l"(p));
    return a;
}
__device__ __forceinline__ void ldmA(uint32_t* a, uint32_t addr) {
    asm volatile("ldmatrix.sync.aligned.m8n8.x4.shared.b16 {%0,%1,%2,%3}, [%4];"
        : "=r"(a[0]), "=r"(a[1]), "=r"(a[2]), "=r"(a[3]) : "r"(addr));
}
__device__ __forceinline__ void ldmB(uint32_t* b, uint32_t addr) {
    asm volatile("ldmatrix.sync.aligned.m8n8.x2.shared.b16 {%0,%1}, [%2];"
        : "=r"(b[0]), "=r"(b[1]) : "r"(addr));
}
__device__ __forceinline__ void mma16816(float* d, const uint32_t* a, const uint32_t* b) {
    asm volatile(
        "mma.sync.aligned.m16n8k16.row.col.f32.bf16.bf16.f32 "
        "{%0,%1,%2,%3}, {%4,%5,%6,%7}, {%8,%9}, {%0,%1,%2,%3};"
        : "+f"(d[0]), "+f"(d[1]), "+f"(d[2]), "+f"(d[3])
        : "r"(a[0]), "r"(a[1]), "r"(a[2]), "r"(a[3]), "r"(b[0]), "r"(b[1]));
}

// ------------------------- prep kernels ------------------------------------
__global__ void transpose_k(const float* __restrict__ src, float* __restrict__ dst,
                            int O, int C) {
    int i = blockIdx.x * 256 + threadIdx.x;
    if (i < O * C) { int o = i / C, c = i % C; dst[c * O + o] = src[i]; }
}

__global__ void hexgather_k(const float* __restrict__ src, float* __restrict__ dst,
                            int O, int C) {
    int i = blockIdx.x * 256 + threadIdx.x;
    if (i < O * C * 7) {
        int o = i % O;
        int kt = i / O;
        int c = kt / 7, t = kt % 7;
        dst[i] = src[(o * C + c) * 9 + t + 1];
    }
}

// [O][C][3][3] fp32 -> split bf16 [o][c*8+t] (tap7 zero)
__global__ void hexsplit_k(const float* __restrict__ src,
                           __nv_bfloat16* __restrict__ hi, __nv_bfloat16* __restrict__ lo,
                           int O, int C) {
    int i = blockIdx.x * 256 + threadIdx.x;
    if (i < O * C * 8) {
        int t = i & 7;
        int c = (i >> 3) % C;
        int o = i / (8 * C);
        float w = (t < 7) ? src[(o * C + c) * 9 + t + 1] : 0.f;
        __nv_bfloat16 h = __float2bfloat16(w);
        hi[i] = h;
        lo[i] = __float2bfloat16(w - __bfloat162float(h));
    }
}

// act = relu(sc*u2+sh) -> bf16 hi/lo planes [c][q]
__global__ __launch_bounds__(256) void actsplit_k(
    const float* __restrict__ u2, const float* __restrict__ sc,
    const float* __restrict__ sh,
    __nv_bfloat16* __restrict__ hi, __nv_bfloat16* __restrict__ lo) {
    int c = blockIdx.y;
    int q = blockIdx.x * 256 + threadIdx.x;
    size_t i = (size_t)c * NP2 + q;
    float v = fmaxf(sc[c] * u2[i] + sh[c], 0.f);
    __nv_bfloat16 h = __float2bfloat16(v);
    hi[i] = h;
    lo[i] = __float2bfloat16(v - __bfloat162float(h));
}

// ------------------------- stem --------------------------------------------
__global__ __launch_bounds__(256) void stem_kernel(
    const float* __restrict__ x, const float* __restrict__ wc,
    float* __restrict__ y1, float* __restrict__ psum, float* __restrict__ psq) {
    __shared__ float wsh[432];
    __shared__ float wpS[16][8], wpQ[16][8];
    int tid = threadIdx.x;
    for (int e = tid; e < 432; e += 256) wsh[e] = wc[e];
    __syncthreads();

    int pos = blockIdx.x * 256 + tid;
    int w = pos & 31, h = (pos >> 5) & 15, b = (pos >> 9) & 255, f = pos >> 17;

    float acc[16];
#pragma unroll
    for (int o = 0; o < 16; o++) acc[o] = 0.f;

#pragma unroll
    for (int t = 0; t < 7; t++) {
        int kf = t + 1;
        int dy = kf / 3 - 1, dx = kf % 3 - 1;
        int hh = h + dy;
        float xv0 = 0.f, xv1 = 0.f, xv2 = 0.f;
        if (hh >= 0 && hh < 16) {
            int ww = w + dx, ff = f;
            if (ww < 0)       { ff = (f + 4) % 5; ww = 31; }
            else if (ww > 31) { ff = (f + 1) % 5; ww = 0;  }
            int base = (ff * 256 + b) * 1536 + hh * 32 + ww;
            xv0 = x[base];
            xv1 = x[base + 512];
            xv2 = x[base + 1024];
        }
#pragma unroll
        for (int o = 0; o < 16; o++) {
            acc[o] += wsh[(o * 3 + 0) * 9 + kf] * xv0
                    + wsh[(o * 3 + 1) * 9 + kf] * xv1
                    + wsh[(o * 3 + 2) * 9 + kf] * xv2;
        }
    }

    int lane = tid & 31, warp = tid >> 5;
#pragma unroll
    for (int o = 0; o < 16; o++) {
        float val = fmaxf(acc[o], 0.f);
        y1[o * NP0 + pos] = val;
        float s = val, q2 = val * val;
#pragma unroll
        for (int d = 16; d; d >>= 1) {
            s  += __shfl_xor_sync(0xFFFFFFFFu, s,  d);
            q2 += __shfl_xor_sync(0xFFFFFFFFu, q2, d);
        }
        if (lane == 0) { wpS[o][warp] = s; wpQ[o][warp] = q2; }
    }
    __syncthreads();
    if (tid < 16) {
        float s = 0.f, q = 0.f;
#pragma unroll
        for (int wpi = 0; wpi < 8; wpi++) { s += wpS[tid][wpi]; q += wpQ[tid][wpi]; }
        psum[blockIdx.x * 16 + tid] = s;
        psq [blockIdx.x * 16 + tid] = q;
    }
}

// ------------------------- BN param fold ------------------------------------
__global__ void bn_param(const float* __restrict__ ps, const float* __restrict__ pq,
                         int nparts, int cstride, int coff, float invN,
                         const float* __restrict__ g, const float* __restrict__ b,
                         float* __restrict__ sc, float* __restrict__ sh) {
    int c = blockIdx.x, tid = threadIdx.x;
    float s = 0.f, q = 0.f;
    for (int p = tid; p < nparts; p += 256) {
        s += ps[(size_t)p * cstride + coff + c];
        q += pq[(size_t)p * cstride + coff + c];
    }
    __shared__ float rs[256], rq[256];
    rs[tid] = s; rq[tid] = q;
    __syncthreads();
    for (int d = 128; d; d >>= 1) {
        if (tid < d) { rs[tid] += rs[tid + d]; rq[tid] += rq[tid + d]; }
        __syncthreads();
    }
    if (tid == 0) {
        float mean = rs[0] * invN;
        float var  = rq[0] * invN - mean * mean;
        float k = g[c] * rsqrtf(var + 1e-5f);
        sc[c] = k;
        sh[c] = b[c] - mean * k;
    }
}

// -------------- resblock entry: dual 1x1 conv + fused 2x2 maxpool -----------
template <int CIN, int COUT, int HIN, int WIN, bool DUAL>
__global__ __launch_bounds__(256) void entry_kernel(
    const float* __restrict__ xa, const float* __restrict__ xb,
    const float* __restrict__ w1t, const float* __restrict__ w2t,
    const float* __restrict__ s1, const float* __restrict__ t1,
    const float* __restrict__ s2, const float* __restrict__ t2,
    float* __restrict__ u, float* __restrict__ v,
    float* __restrict__ psum, float* __restrict__ psq) {
    constexpr int HO = HIN / 2, WO = WIN / 2;
    constexpr int NPIN  = 5 * 256 * HIN * WIN;
    constexpr int NPOUT = 5 * 256 * HO * WO;

    __shared__ __align__(16) float actsh[CIN * 64];
    __shared__ __align__(16) float wsh[CIN * 64];
    __shared__ float stage[64 * 17];

    int tid = threadIdx.x;
    int q0 = blockIdx.x * 16;

    for (int e = tid; e < CIN * 64; e += 256) {
        int c = e >> 6, lp = e & 63;
        int q = q0 + (lp >> 2), sub = lp & 3;
        int w = q % WO;
        int h = (q / WO) % HO;
        int fb = q / (WO * HO);
        int p = (fb * HIN + 2 * h + (sub >> 1)) * WIN + 2 * w + (sub & 1);
        float val = s1[c] * xa[(size_t)c * NPIN + p] + t1[c];
        if (DUAL) {
            val += s2[c] * xb[(size_t)c * NPIN + p] + t2[c];
            val = fmaxf(val, 0.f);
        }
        actsh[e] = val;
    }

    int ob = (tid & 15) * 4;
    int ql = tid >> 4;

    for (int path = 0; path < 2; path++) {
        const float* wt = path ? w2t : w1t;
        float* outp = path ? v : u;
        for (int oc = 0; oc < COUT; oc += 64) {
            __syncthreads();
            for (int e = tid; e < CIN * 64; e += 256) {
                int c = e >> 6, o = e & 63;
                wsh[e] = wt[c * COUT + oc + o];
            }
            __syncthreads();

            float acc[4][4];
#pragma unroll
            for (int i = 0; i < 4; i++)
#pragma unroll
                for (int j = 0; j < 4; j++) acc[i][j] = 0.f;

#pragma unroll 8
            for (int c = 0; c < CIN; c++) {
                float4 a = *(const float4*)(wsh + c * 64 + ob);
                float4 bq = *(const float4*)(actsh + c * 64 + ql * 4);
                float av[4] = {a.x, a.y, a.z, a.w};
                float bv[4] = {bq.x, bq.y, bq.z, bq.w};
#pragma unroll
                for (int i = 0; i < 4; i++)
#pragma unroll
                    for (int j = 0; j < 4; j++) acc[i][j] += av[i] * bv[j];
            }
#pragma unroll
            for (int i = 0; i < 4; i++) {
                float val = fmaxf(fmaxf(acc[i][0], acc[i][1]),
                                  fmaxf(acc[i][2], acc[i][3]));
                outp[(size_t)(oc + ob + i) * NPOUT + q0 + ql] = val;
                stage[(ob + i) * 17 + ql] = val;
            }
            __syncthreads();
            if (tid < 64) {
                float s = 0.f, q = 0.f;
#pragma unroll
                for (int k = 0; k < 16; k++) {
                    float vv = stage[tid * 17 + k];
                    s += vv; q += vv * vv;
                }
                psum[(size_t)blockIdx.x * (2 * COUT) + path * COUT + oc + tid] = s;
                psq [(size_t)blockIdx.x * (2 * COUT) + path * COUT + oc + tid] = q;
            }
        }
    }
}

// ------------------ unified implicit-GEMM conv (SIMT path) ------------------
template <int CIN, int COUT, int H, int W, int TAPS, int CB>
__global__ __launch_bounds__(256) void gemm_conv(
    const float* __restrict__ xin, const float* __restrict__ a2,
    const float* __restrict__ sa, const float* __restrict__ ta,
    float* __restrict__ out, float* __restrict__ psum, float* __restrict__ psq) {
    constexpr int NP = 5 * 256 * H * W;
    constexpr int KC = CB * TAPS;

    __shared__ __align__(16) float Ash[KC * 64];
    __shared__ __align__(16) float Bsh[KC * 64];
    __shared__ int nbr[TAPS * 64];
    __shared__ float partS[64 * 16], partQ[64 * 16];

    int tid = threadIdx.x;
    int q0 = blockIdx.x * 64;
    int o0 = blockIdx.y * 64;

    for (int e = tid; e < TAPS * 64; e += 256) {
        int t = e >> 6, ql = e & 63;
        int q = q0 + ql;
        int pos;
        if (TAPS == 1) pos = q;
        else {
            int w = q % W;
            int h = (q / W) % H;
            int b = (q / (W * H)) & 255;
            int f = q / (W * H * 256);
            int kf = t + 1;
            int dy = kf / 3 - 1, dx = kf % 3 - 1;
            int hh = h + dy, ww = w + dx, ff = f;
            if (hh < 0 || hh >= H) pos = -1;
            else {
                if (ww < 0)      { ff = (f + 4) % 5; ww = W - 1; }
                else if (ww >= W){ ff = (f + 1) % 5; ww = 0;     }
                pos = ((ff * 256 + b) * H + hh) * W + ww;
            }
        }
        nbr[e] = pos;
    }
    __syncthreads();

    float acc[4][4];
#pragma unroll
    for (int i = 0; i < 4; i++)
#pragma unroll
        for (int j = 0; j < 4; j++) acc[i][j] = 0.f;

    int ob = (tid & 15) * 4;
    int qb = (tid >> 4) * 4;

    for (int c0 = 0; c0 < CIN; c0 += CB) {
        for (int e = tid; e < KC * 64; e += 256) {
            int kk = e >> 6, o = e & 63;
            Ash[e] = a2[(size_t)(c0 * TAPS + kk) * COUT + o0 + o];
        }
        for (int e = tid; e < KC * 64; e += 256) {
            int kk = e >> 6, ql = e & 63;
            int cl = kk / TAPS, t = kk % TAPS;
            int c = c0 + cl;
            int pos = nbr[t * 64 + ql];
            float val = 0.f;
            if (pos >= 0)
                val = fmaxf(sa[c] * xin[(size_t)c * NP + pos] + ta[c], 0.f);
            Bsh[e] = val;
        }
        __syncthreads();
#pragma unroll
        for (int kk = 0; kk < KC; kk++) {
            float4 a = *(const float4*)(Ash + kk * 64 + ob);
            float4 b = *(const float4*)(Bsh + kk * 64 + qb);
            float av[4] = {a.x, a.y, a.z, a.w};
            float bv[4] = {b.x, b.y, b.z, b.w};
#pragma unroll
            for (int i = 0; i < 4; i++)
#pragma unroll
                for (int j = 0; j < 4; j++) acc[i][j] += av[i] * bv[j];
        }
        __syncthreads();
    }

    int qg = tid >> 4;
#pragma unroll
    for (int i = 0; i < 4; i++) {
        float4 st = {acc[i][0], acc[i][1], acc[i][2], acc[i][3]};
        *(float4*)(out + (size_t)(o0 + ob + i) * NP + q0 + qb) = st;
        float s = acc[i][0] + acc[i][1] + acc[i][2] + acc[i][3];
        float q = acc[i][0]*acc[i][0] + acc[i][1]*acc[i][1]
                + acc[i][2]*acc[i][2] + acc[i][3]*acc[i][3];
        partS[(ob + i) * 16 + qg] = s;
        partQ[(ob + i) * 16 + qg] = q;
    }
    __syncthreads();
    if (tid < 64) {
        float s = 0.f, q = 0.f;
#pragma unroll
        for (int k = 0; k < 16; k++) { s += partS[tid * 16 + k]; q += partQ[tid * 16 + k]; }
        psum[(size_t)blockIdx.x * COUT + o0 + tid] = s;
        psq [(size_t)blockIdx.x * COUT + o0 + tid] = q;
    }
}

// ------------------ mma.sync split-bf16 hexconv for block2 ------------------
// D[q=128 tile, o=128 tile] = act[q, k] * W[o, k], k = c*8+t (tap7 = 0), K=2048
#define MOF_NBR  0
#define MOF_AH   3584
#define MOF_AL   (MOF_AH + 18432)
#define MOF_BH   (MOF_AL + 18432)
#define MOF_BL   (MOF_BH + 18432)
#define MOF_PS   (MOF_BL + 18432)
#define MOF_PQ   (MOF_PS + 4096)
#define MMA_SMEM (MOF_PQ + 4096)
#define LDA 72

__global__ __launch_bounds__(256) void mma_hex2_k(
    const __nv_bfloat16* __restrict__ ahi, const __nv_bfloat16* __restrict__ alo,
    const __nv_bfloat16* __restrict__ whi, const __nv_bfloat16* __restrict__ wlo,
    float* __restrict__ out, float* __restrict__ psum, float* __restrict__ psq) {
    constexpr int H = 4, W = 8;
    extern __shared__ __align__(16) char smem[];
    uint32_t sb = smem_u32(smem);
    int tid = threadIdx.x;
    int wid = tid >> 5, lane = tid & 31;
    int q0 = blockIdx.x * 128;
    int o0 = blockIdx.y * 128;

    int* nbr = (int*)(smem + MOF_NBR);
    for (int e = tid; e < 7 * 128; e += 256) {
        int t = e >> 7, ql = e & 127;
        int q = q0 + ql;
        int w = q % W;
        int h = (q / W) % H;
        int b = (q / (W * H)) & 255;
        int f = q / (W * H * 256);
        int kf = t + 1;
        int dy = kf / 3 - 1, dx = kf % 3 - 1;
        int hh = h + dy, ww = w + dx, ff = f;
        int pos;
        if (hh < 0 || hh >= H) pos = -1;
        else {
            if (ww < 0)      { ff = (f + 4) % 5; ww = W - 1; }
            else if (ww >= W){ ff = (f + 1) % 5; ww = 0;     }
            pos = ((ff * 256 + b) * H + hh) * W + ww;
        }
        nbr[t * 128 + ql] = pos;
    }
    __syncthreads();

    float acc[16][4];
#pragma unroll
    for (int nt = 0; nt < 16; nt++)
#pragma unroll
        for (int j = 0; j < 4; j++) acc[nt][j] = 0.f;

    // ldmatrix base addresses
    int m0 = wid * 16;
    int grp = lane >> 3;
    int rowA = m0 + (lane & 7) + (grp & 1) * 8;
    int colA8 = (grp >> 1) * 8;
    uint32_t aBaseH = sb + MOF_AH + (uint32_t)(rowA * LDA + colA8) * 2;
    uint32_t aBaseL = sb + MOF_AL + (uint32_t)(rowA * LDA + colA8) * 2;
    int rowB = (lane & 7);
    int colB8 = ((lane >> 3) & 1) * 8;
    uint32_t bBaseH = sb + MOF_BH + (uint32_t)(rowB * LDA + colB8) * 2;
    uint32_t bBaseL = sb + MOF_BL + (uint32_t)(rowB * LDA + colB8) * 2;

    __nv_bfloat16* AH = (__nv_bfloat16*)(smem + MOF_AH);
    __nv_bfloat16* AL = (__nv_bfloat16*)(smem + MOF_AL);
    __nv_bfloat16* BH = (__nv_bfloat16*)(smem + MOF_BH);
    __nv_bfloat16* BL = (__nv_bfloat16*)(smem + MOF_BL);

    for (int ci = 0; ci < 32; ci++) {          // K chunk of 64 = 8 channels
        // stage A: [128 q][64 k] hi/lo, gathered
#pragma unroll
        for (int it = 0; it < 32; it++) {
            int e = it * 256 + tid;            // 0..8191
            int kk = e >> 7, q = e & 127;
            int c = ci * 8 + (kk >> 3);
            int t = kk & 7;
            __nv_bfloat16 vh = __float2bfloat16(0.f), vl = vh;
            if (t < 7) {
                int pos = nbr[t * 128 + q];
                if (pos >= 0) {
                    size_t gi = (size_t)c * NP2 + pos;
                    vh = ahi[gi];
                    vl = alo[gi];
                }
            }
            AH[q * LDA + kk] = vh;
            AL[q * LDA + kk] = vl;
        }
        // stage B: [128 o][64 k] hi/lo, vectorized
#pragma unroll
        for (int it = 0; it < 4; it++) {
            int e = it * 256 + tid;            // 0..1023
            int o = e >> 3, j = e & 7;
            size_t src = (size_t)(o0 + o) * 2048 + ci * 64 + j * 8;
            *(uint4*)(BH + o * LDA + j * 8) = *(const uint4*)(whi + src);
            *(uint4*)(BL + o * LDA + j * 8) = *(const uint4*)(wlo + src);
        }
        __syncthreads();

#pragma unroll
        for (int ks = 0; ks < 4; ks++) {
            uint32_t aH[4], aL[4];
            ldmA(aH, aBaseH + ks * 32);        // ks*16 cols * 2B
            ldmA(aL, aBaseL + ks * 32);
#pragma unroll
            for (int nt = 0; nt < 16; nt++) {
                uint32_t bH[2], bL[2];
                uint32_t boff = (uint32_t)(nt * 8 * LDA) * 2 + ks * 32;
                ldmB(bH, bBaseH + boff);
                ldmB(bL, bBaseL + boff);
                mma16816(acc[nt], aH, bH);
                mma16816(acc[nt], aL, bH);
                mma16816(acc[nt], aH, bL);
            }
        }
        __syncthreads();
    }

    // epilogue: stores + deterministic per-channel stats
    float* pS = (float*)(smem + MOF_PS);       // [8 warps][128 cols]
    float* pQ = (float*)(smem + MOF_PQ);
    int r = lane >> 2;
    int cp = (lane & 3) << 1;
#pragma unroll
    for (int nt = 0; nt < 16; nt++) {
        int c0c = nt * 8 + cp;
        int qrow = q0 + m0 + r;
        out[(size_t)(o0 + c0c    ) * NP2 + qrow    ] = acc[nt][0];
        out[(size_t)(o0 + c0c + 1) * NP2 + qrow    ] = acc[nt][1];
        out[(size_t)(o0 + c0c    ) * NP2 + qrow + 8] = acc[nt][2];
        out[(size_t)(o0 + c0c + 1) * NP2 + qrow + 8] = acc[nt][3];
        float s0 = acc[nt][0] + acc[nt][2];
        float s1 = acc[nt][1] + acc[nt][3];
        float t0 = acc[nt][0]*acc[nt][0] + acc[nt][2]*acc[nt][2];
        float t1 = acc[nt][1]*acc[nt][1] + acc[nt][3]*acc[nt][3];
#pragma unroll
        for (int d = 4; d <= 16; d <<= 1) {
            s0 += __shfl_xor_sync(0xFFFFFFFFu, s0, d);
            s1 += __shfl_xor_sync(0xFFFFFFFFu, s1, d);
            t0 += __shfl_xor_sync(0xFFFFFFFFu, t0, d);
            t1 += __shfl_xor_sync(0xFFFFFFFFu, t1, d);
        }
        if (r == 0) {
            pS[wid * 128 + c0c]     = s0;
            pS[wid * 128 + c0c + 1] = s1;
            pQ[wid * 128 + c0c]     = t0;
            pQ[wid * 128 + c0c + 1] = t1;
        }
    }
    __syncthreads();
    if (tid < 128) {
        float s = 0.f, q = 0.f;
#pragma unroll
        for (int w = 0; w < 8; w++) { s += pS[w * 128 + tid]; q += pQ[w * 128 + tid]; }
        psum[(size_t)blockIdx.x * 256 + o0 + tid] = s;
        psq [(size_t)blockIdx.x * 256 + o0 + tid] = q;
    }
}

// ------------- final: BN+add+relu, global max over charts+spatial -----------
__global__ __launch_bounds__(256) void maxfin_k(
    const float* __restrict__ w2, const float* __restrict__ v2,
    const float* __restrict__ scC, const float* __restrict__ shC,
    const float* __restrict__ scD, const float* __restrict__ shD,
    float* __restrict__ gmax) {
    int o = blockIdx.x, tid = threadIdx.x;
    __shared__ int mx[256];
    mx[tid] = 0;
    __syncthreads();
    float a = scC[o], c_ = shC[o], d = scD[o], e = shD[o];
    const float* wp = w2 + (size_t)o * NP2;
    const float* vp = v2 + (size_t)o * NP2;
    for (int i = tid; i < NP2; i += 256) {
        float val = fmaxf(a * wp[i] + c_ + d * vp[i] + e, 0.f);
#pragma unroll
        for (int s = 16; s; s >>= 1)
            val = fmaxf(val, __shfl_xor_sync(0xFFFFFFFFu, val, s));
        if ((tid & 31) == 0)
            atomicMax(&mx[(i >> 5) & 255], __float_as_int(val));
    }
    __syncthreads();
    gmax[tid * 256 + o] = __int_as_float(mx[tid]);
}

__global__ void fc_k(const float* __restrict__ gmax, const float* __restrict__ fw,
                     const float* __restrict__ fb, float* __restrict__ out) {
    int b = blockIdx.x, tid = threadIdx.x;
    __shared__ float m[256];
    m[tid] = gmax[b * 256 + tid];
    __syncthreads();
    if (tid < 10) {
        float acc = fb[tid];
        for (int o = 0; o < 256; o++) acc += m[o] * fw[tid * 256 + o];
        out[b * 10 + tid] = acc;
    }
}

// ------------------------- launch ------------------------------------------
extern "C" void kernel_launch(void* const* d_in, const int* in_sizes, int n_in,
                              void* d_out, int out_size) {
    (void)n_in; (void)out_size;

    const float* x = (const float*)d_in[0];

    float *y1,*u1,*v1,*h1,*w1,*u2,*v2,*h2,*w2,*gmax,*ps,*pq,*sc,*sh;
    float *t_b1c1,*t_b1ds,*t_b1c3,*t_b2c1,*t_b2ds,*t_b2c3,*a2b1;
    __nv_bfloat16 *whi, *wlo, *ahi, *alo;
    cudaGetSymbolAddress((void**)&y1, g_y1);
    cudaGetSymbolAddress((void**)&u1, g_u1);
    cudaGetSymbolAddress((void**)&v1, g_v1);
    cudaGetSymbolAddress((void**)&h1, g_h1);
    cudaGetSymbolAddress((void**)&w1, g_w1);
    cudaGetSymbolAddress((void**)&u2, g_u2);
    cudaGetSymbolAddress((void**)&v2, g_v2);
    cudaGetSymbolAddress((void**)&h2, g_h2);
    cudaGetSymbolAddress((void**)&w2, g_w2);
    cudaGetSymbolAddress((void**)&gmax, g_gmax);
    cudaGetSymbolAddress((void**)&ps, g_psum);
    cudaGetSymbolAddress((void**)&pq, g_psq);
    cudaGetSymbolAddress((void**)&sc, g_scale);
    cudaGetSymbolAddress((void**)&sh, g_shift);
    cudaGetSymbolAddress((void**)&t_b1c1, g_wt_b1c1);
    cudaGetSymbolAddress((void**)&t_b1ds, g_wt_b1ds);
    cudaGetSymbolAddress((void**)&t_b1c3, g_wt_b1c3);
    cudaGetSymbolAddress((void**)&t_b2c1, g_wt_b2c1);
    cudaGetSymbolAddress((void**)&t_b2ds, g_wt_b2ds);
    cudaGetSymbolAddress((void**)&t_b2c3, g_wt_b2c3);
    cudaGetSymbolAddress((void**)&a2b1, g_a2_b1);
    cudaGetSymbolAddress((void**)&whi, g_whex_hi);
    cudaGetSymbolAddress((void**)&wlo, g_whex_lo);
    cudaGetSymbolAddress((void**)&ahi, g_abf_hi);
    cudaGetSymbolAddress((void**)&alo, g_abf_lo);

    // input index tables (runtime disambiguation of metadata order)
    int I_b1c1, I_b1hex, I_b1c3, I_b1ds;
    int I_b1ga, I_b1ba, I_b1gb, I_b1bb, I_b1gc, I_b1bc, I_b1gd, I_b1bd;
    int I_b2c1, I_b2hex, I_b2c3, I_b2ds;
    int I_b2ga, I_b2ba, I_b2gb, I_b2bb, I_b2gc, I_b2bc, I_b2gd, I_b2bd;
    int I_fcw, I_fcb;
    if (in_sizes[5] == 36864) {
        I_b1c1 = 4;  I_b1hex = 5;  I_b1c3 = 6;  I_b1ds = 7;
        I_b1ga = 8;  I_b1ba = 9;  I_b1gb = 10; I_b1bb = 11;
        I_b1gc = 12; I_b1bc = 13; I_b1gd = 14; I_b1bd = 15;
        I_b2c1 = 16; I_b2hex = 17; I_b2c3 = 18; I_b2ds = 19;
        I_b2ga = 20; I_b2ba = 21; I_b2gb = 22; I_b2bb = 23;
        I_b2gc = 24; I_b2bc = 25; I_b2gd = 26; I_b2bd = 27;
        I_fcw = 28;  I_fcb = 29;
    } else {
        I_b1c1 = 4;  I_b1ga = 5;  I_b1ba = 6;  I_b1hex = 7;
        I_b1gb = 8;  I_b1bb = 9;  I_b1c3 = 10; I_b1gc = 11; I_b1bc = 12;
        I_b1ds = 13; I_b1gd = 14; I_b1bd = 15;
        I_b2c1 = 16; I_b2ga = 17; I_b2ba = 18; I_b2hex = 19;
        I_b2gb = 20; I_b2bb = 21; I_b2c3 = 22; I_b2gc = 23; I_b2bc = 24;
        I_b2ds = 25; I_b2gd = 26; I_b2bd = 27;
        I_fcw = 28;  I_fcb = 29;
    }

    // weight prep
    transpose_k<<<4,   256>>>((const float*)d_in[I_b1c1], t_b1c1, 64, 16);
    transpose_k<<<4,   256>>>((const float*)d_in[I_b1ds], t_b1ds, 64, 16);
    transpose_k<<<16,  256>>>((const float*)d_in[I_b1c3], t_b1c3, 64, 64);
    transpose_k<<<64,  256>>>((const float*)d_in[I_b2c1], t_b2c1, 256, 64);
    transpose_k<<<64,  256>>>((const float*)d_in[I_b2ds], t_b2ds, 256, 64);
    transpose_k<<<256, 256>>>((const float*)d_in[I_b2c3], t_b2c3, 256, 256);
    hexgather_k<<<112, 256>>>((const float*)d_in[I_b1hex], a2b1, 64, 64);
    hexsplit_k<<<2048, 256>>>((const float*)d_in[I_b2hex], whi, wlo, 256, 256);

    // stem + bn1 fold
    stem_kernel<<<NP0 / 256, 256>>>(x, (const float*)d_in[1], y1, ps, pq);
    bn_param<<<16, 256>>>(ps, pq, NP0 / 256, 16, 0, 1.f / NP0,
                          (const float*)d_in[2], (const float*)d_in[3], sc + 0, sh + 0);

    // block1 entry
    entry_kernel<16, 64, 16, 32, false><<<NP1 / 16, 256>>>(
        y1, nullptr, t_b1c1, t_b1ds, sc + 0, sh + 0, nullptr, nullptr, u1, v1, ps, pq);
    bn_param<<<64, 256>>>(ps, pq, NP1 / 16, 128, 0,  1.f / NP1,
                          (const float*)d_in[I_b1ga], (const float*)d_in[I_b1ba], sc + 16,  sh + 16);
    bn_param<<<64, 256>>>(ps, pq, NP1 / 16, 128, 64, 1.f / NP1,
                          (const float*)d_in[I_b1gd], (const float*)d_in[I_b1bd], sc + 208, sh + 208);

    // block1 hexconv
    gemm_conv<64, 64, 8, 16, 7, 8><<<dim3(NP1 / 64, 1), 256>>>(
        u1, a2b1, sc + 16, sh + 16, h1, ps, pq);
    bn_param<<<64, 256>>>(ps, pq, NP1 / 64, 64, 0, 1.f / NP1,
                          (const float*)d_in[I_b1gb], (const float*)d_in[I_b1bb], sc + 80, sh + 80);

    // block1 conv3 1x1
    gemm_conv<64, 64, 8, 16, 1, 32><<<dim3(NP1 / 64, 1), 256>>>(
        h1, t_b1c3, sc + 80, sh + 80, w1, ps, pq);
    bn_param<<<64, 256>>>(ps, pq, NP1 / 64, 64, 0, 1.f / NP1,
                          (const float*)d_in[I_b1gc], (const float*)d_in[I_b1bc], sc + 144, sh + 144);

    // block2 entry
    entry_kernel<64, 256, 8, 16, true><<<NP2 / 16, 256>>>(
        w1, v1, t_b2c1, t_b2ds, sc + 144, sh + 144, sc + 208, sh + 208, u2, v2, ps, pq);
    bn_param<<<256, 256>>>(ps, pq, NP2 / 16, 512, 0,   1.f / NP2,
                           (const float*)d_in[I_b2ga], (const float*)d_in[I_b2ba], sc + 272,  sh + 272);
    bn_param<<<256, 256>>>(ps, pq, NP2 / 16, 512, 256, 1.f / NP2,
                           (const float*)d_in[I_b2gd], (const float*)d_in[I_b2bd], sc + 1040, sh + 1040);

    // block2 hexconv — mma.sync split-bf16 path
    actsplit_k<<<dim3(NP2 / 256, 256), 256>>>(u2, sc + 272, sh + 272, ahi, alo);
    cudaFuncSetAttribute(mma_hex2_k, cudaFuncAttributeMaxDynamicSharedMemorySize, MMA_SMEM);
    mma_hex2_k<<<dim3(NP2 / 128, 2), 256, MMA_SMEM>>>(ahi, alo, whi, wlo, h2, ps, pq);
    bn_param<<<256, 256>>>(ps, pq, NP2 / 128, 256, 0, 1.f / NP2,
                           (const float*)d_in[I_b2gb], (const float*)d_in[I_b2bb], sc + 528, sh + 528);

    // block2 conv3 1x1
    gemm_conv<256, 256, 4, 8, 1, 32><<<dim3(NP2 / 64, 4), 256>>>(
        h2, t_b2c3, sc + 528, sh + 528, w2, ps, pq);
    bn_param<<<256, 256>>>(ps, pq, NP2 / 64, 256, 0, 1.f / NP2,
                           (const float*)d_in[I_b2gc], (const float*)d_in[I_b2bc], sc + 784, sh + 784);

    // tail
    maxfin_k<<<256, 256>>>(w2, v2, sc + 784, sh + 784, sc + 1040, sh + 1040, gmax);
    fc_k<<<256, 256>>>(gmax, (const float*)d_in[I_fcw], (const float*)d_in[I_fcb], (float*)d_out);
}

// round 8
// speedup vs baseline: 1.1793x; 1.0963x over previous
#include <cuda_runtime.h>
#include <cuda_bf16.h>
#include <cstdint>

// Geometry:
//  stage0 in : [5][256][3][16][32]
//  y1 (stem) : 16ch @16x32, NP0 = 5*256*512 = 655360
//  block1    : 64ch @8x16,  NP1 = 5*256*128 = 163840
//  block2    : 256ch@4x8,   NP2 = 5*256*32  = 40960
// Activation layout: chan-major t[c*NP + (((f*256+b)*H+h)*W+w)]

#define NP0 655360
#define NP1 163840
#define NP2 40960

// ------------------------- device scratch ----------------------------------
__device__ float g_y1[16 * NP0];
__device__ float g_u1[64 * NP1];
__device__ float g_v1[64 * NP1];
__device__ float g_h1[64 * NP1];
__device__ float g_w1[64 * NP1];
__device__ float g_u2[256 * NP2];
__device__ float g_v2[256 * NP2];
__device__ float g_h2[256 * NP2];
__device__ float g_w2[256 * NP2];
__device__ float g_gmax[256 * 256];

__device__ float g_psum[1310720];
__device__ float g_psq [1310720];

__device__ float g_scale[1296];
__device__ float g_shift[1296];

__device__ float g_wt_b1c1[16 * 64];
__device__ float g_wt_b1ds[16 * 64];
__device__ float g_wt_b1c3[64 * 64];

// split bf16 weights
__device__ __nv_bfloat16 g_whex_hi[256 * 2048];   // b2 hex [o][c*8+t]
__device__ __nv_bfloat16 g_whex_lo[256 * 2048];
__device__ __nv_bfloat16 g_wb1h_hi[64 * 512];     // b1 hex [o][c*8+t]
__device__ __nv_bfloat16 g_wb1h_lo[64 * 512];
__device__ __nv_bfloat16 g_went_hi[512 * 64];     // entry [o(512)][c(64)]
__device__ __nv_bfloat16 g_went_lo[512 * 64];
__device__ __nv_bfloat16 g_wc3_hi [256 * 256];    // b2 c3 [o][c]
__device__ __nv_bfloat16 g_wc3_lo [256 * 256];

// split bf16 activation planes (reused sequentially; 64*NP1 == 256*NP2)
__device__ __nv_bfloat16 g_abf_hi[10485760];
__device__ __nv_bfloat16 g_abf_lo[10485760];

// ------------------------- mma helpers -------------------------------------
__device__ __forceinline__ uint32_t smem_u32(const void* p) {
    uint32_t a;
    asm("{ .reg .u64 t; cvta.to.shared.u64 t, %1; cvt.u32.u64 %0, t; }"
        : "=r"(a) : "l"(p));
    return a;
}
__device__ __forceinline__ void ldmA(uint32_t* a, uint32_t addr) {
    asm volatile("ldmatrix.sync.aligned.m8n8.x4.shared.b16 {%0,%1,%2,%3}, [%4];"
        : "=r"(a[0]), "=r"(a[1]), "=r"(a[2]), "=r"(a[3]) : "r"(addr));
}
__device__ __forceinline__ void ldmB(uint32_t* b, uint32_t addr) {
    asm volatile("ldmatrix.sync.aligned.m8n8.x2.shared.b16 {%0,%1}, [%2];"
        : "=r"(b[0]), "=r"(b[1]) : "r"(addr));
}
__device__ __forceinline__ void mma16816(float* d, const uint32_t* a, const uint32_t* b) {
    asm volatile(
        "mma.sync.aligned.m16n8k16.row.col.f32.bf16.bf16.f32 "
        "{%0,%1,%2,%3}, {%4,%5,%6,%7}, {%8,%9}, {%0,%1,%2,%3};"
        : "+f"(d[0]), "+f"(d[1]), "+f"(d[2]), "+f"(d[3])
        : "r"(a[0]), "r"(a[1]), "r"(a[2]), "r"(a[3]), "r"(b[0]), "r"(b[1]));
}
#define LDA 72

// ------------------------- prep kernels ------------------------------------
__global__ void transpose_k(const float* __restrict__ src, float* __restrict__ dst,
                            int O, int C) {
    int i = blockIdx.x * 256 + threadIdx.x;
    if (i < O * C) { int o = i / C, c = i % C; dst[c * O + o] = src[i]; }
}

// [O][C][3][3] fp32 -> split bf16 [o][c*8+t] (tap7 zero)
__global__ void hexsplit_k(const float* __restrict__ src,
                           __nv_bfloat16* __restrict__ hi, __nv_bfloat16* __restrict__ lo,
                           int O, int C) {
    int i = blockIdx.x * 256 + threadIdx.x;
    if (i < O * C * 8) {
        int t = i & 7;
        int c = (i >> 3) % C;
        int o = i / (8 * C);
        float w = (t < 7) ? src[(o * C + c) * 9 + t + 1] : 0.f;
        __nv_bfloat16 h = __float2bfloat16(w);
        hi[i] = h;
        lo[i] = __float2bfloat16(w - __bfloat162float(h));
    }
}

// [O][C] fp32 -> split bf16 rows at rowoff (row stride C)
__global__ void split1x1_k(const float* __restrict__ src,
                           __nv_bfloat16* __restrict__ hi, __nv_bfloat16* __restrict__ lo,
                           int O, int C, int rowoff) {
    int i = blockIdx.x * 256 + threadIdx.x;
    if (i < O * C) {
        float w = src[i];
        __nv_bfloat16 h = __float2bfloat16(w);
        int o = i / C, c = i % C;
        hi[(rowoff + o) * C + c] = h;
        lo[(rowoff + o) * C + c] = __float2bfloat16(w - __bfloat162float(h));
    }
}

// act = relu(sc*x+sh) -> bf16 hi/lo planes [c][q]
__global__ __launch_bounds__(256) void actsplit_k(
    const float* __restrict__ x, const float* __restrict__ sc,
    const float* __restrict__ sh,
    __nv_bfloat16* __restrict__ hi, __nv_bfloat16* __restrict__ lo, int NP) {
    int c = blockIdx.y;
    int q = blockIdx.x * 256 + threadIdx.x;
    size_t i = (size_t)c * NP + q;
    float v = fmaxf(sc[c] * x[i] + sh[c], 0.f);
    __nv_bfloat16 h = __float2bfloat16(v);
    hi[i] = h;
    lo[i] = __float2bfloat16(v - __bfloat162float(h));
}

// act = relu(s1*a+t1 + s2*b+t2)
__global__ __launch_bounds__(256) void actsplit2_k(
    const float* __restrict__ xa, const float* __restrict__ xb,
    const float* __restrict__ s1, const float* __restrict__ t1,
    const float* __restrict__ s2, const float* __restrict__ t2,
    __nv_bfloat16* __restrict__ hi, __nv_bfloat16* __restrict__ lo, int NP) {
    int c = blockIdx.y;
    int q = blockIdx.x * 256 + threadIdx.x;
    size_t i = (size_t)c * NP + q;
    float v = fmaxf(s1[c] * xa[i] + t1[c] + s2[c] * xb[i] + t2[c], 0.f);
    __nv_bfloat16 h = __float2bfloat16(v);
    hi[i] = h;
    lo[i] = __float2bfloat16(v - __bfloat162float(h));
}

// ------------------------- stem --------------------------------------------
__global__ __launch_bounds__(256) void stem_kernel(
    const float* __restrict__ x, const float* __restrict__ wc,
    float* __restrict__ y1, float* __restrict__ psum, float* __restrict__ psq) {
    __shared__ float wsh[432];
    __shared__ float wpS[16][8], wpQ[16][8];
    int tid = threadIdx.x;
    for (int e = tid; e < 432; e += 256) wsh[e] = wc[e];
    __syncthreads();

    int pos = blockIdx.x * 256 + tid;
    int w = pos & 31, h = (pos >> 5) & 15, b = (pos >> 9) & 255, f = pos >> 17;

    float acc[16];
#pragma unroll
    for (int o = 0; o < 16; o++) acc[o] = 0.f;

#pragma unroll
    for (int t = 0; t < 7; t++) {
        int kf = t + 1;
        int dy = kf / 3 - 1, dx = kf % 3 - 1;
        int hh = h + dy;
        float xv0 = 0.f, xv1 = 0.f, xv2 = 0.f;
        if (hh >= 0 && hh < 16) {
            int ww = w + dx, ff = f;
            if (ww < 0)       { ff = (f + 4) % 5; ww = 31; }
            else if (ww > 31) { ff = (f + 1) % 5; ww = 0;  }
            int base = (ff * 256 + b) * 1536 + hh * 32 + ww;
            xv0 = x[base];
            xv1 = x[base + 512];
            xv2 = x[base + 1024];
        }
#pragma unroll
        for (int o = 0; o < 16; o++) {
            acc[o] += wsh[(o * 3 + 0) * 9 + kf] * xv0
                    + wsh[(o * 3 + 1) * 9 + kf] * xv1
                    + wsh[(o * 3 + 2) * 9 + kf] * xv2;
        }
    }

    int lane = tid & 31, warp = tid >> 5;
#pragma unroll
    for (int o = 0; o < 16; o++) {
        float val = fmaxf(acc[o], 0.f);
        y1[o * NP0 + pos] = val;
        float s = val, q2 = val * val;
#pragma unroll
        for (int d = 16; d; d >>= 1) {
            s  += __shfl_xor_sync(0xFFFFFFFFu, s,  d);
            q2 += __shfl_xor_sync(0xFFFFFFFFu, q2, d);
        }
        if (lane == 0) { wpS[o][warp] = s; wpQ[o][warp] = q2; }
    }
    __syncthreads();
    if (tid < 16) {
        float s = 0.f, q = 0.f;
#pragma unroll
        for (int wpi = 0; wpi < 8; wpi++) { s += wpS[tid][wpi]; q += wpQ[tid][wpi]; }
        psum[blockIdx.x * 16 + tid] = s;
        psq [blockIdx.x * 16 + tid] = q;
    }
}

// ------------------------- BN param fold ------------------------------------
__global__ void bn_param(const float* __restrict__ ps, const float* __restrict__ pq,
                         int nparts, int cstride, int coff, float invN,
                         const float* __restrict__ g, const float* __restrict__ b,
                         float* __restrict__ sc, float* __restrict__ sh) {
    int c = blockIdx.x, tid = threadIdx.x;
    float s = 0.f, q = 0.f;
    for (int p = tid; p < nparts; p += 256) {
        s += ps[(size_t)p * cstride + coff + c];
        q += pq[(size_t)p * cstride + coff + c];
    }
    __shared__ float rs[256], rq[256];
    rs[tid] = s; rq[tid] = q;
    __syncthreads();
    for (int d = 128; d; d >>= 1) {
        if (tid < d) { rs[tid] += rs[tid + d]; rq[tid] += rq[tid + d]; }
        __syncthreads();
    }
    if (tid == 0) {
        float mean = rs[0] * invN;
        float var  = rq[0] * invN - mean * mean;
        float k = g[c] * rsqrtf(var + 1e-5f);
        sc[c] = k;
        sh[c] = b[c] - mean * k;
    }
}

// -------------- resblock entry (SIMT, used for block1 only) -----------------
template <int CIN, int COUT, int HIN, int WIN, bool DUAL>
__global__ __launch_bounds__(256) void entry_kernel(
    const float* __restrict__ xa, const float* __restrict__ xb,
    const float* __restrict__ w1t, const float* __restrict__ w2t,
    const float* __restrict__ s1, const float* __restrict__ t1,
    const float* __restrict__ s2, const float* __restrict__ t2,
    float* __restrict__ u, float* __restrict__ v,
    float* __restrict__ psum, float* __restrict__ psq) {
    constexpr int HO = HIN / 2, WO = WIN / 2;
    constexpr int NPIN  = 5 * 256 * HIN * WIN;
    constexpr int NPOUT = 5 * 256 * HO * WO;

    __shared__ __align__(16) float actsh[CIN * 64];
    __shared__ __align__(16) float wsh[CIN * 64];
    __shared__ float stage[64 * 17];

    int tid = threadIdx.x;
    int q0 = blockIdx.x * 16;

    for (int e = tid; e < CIN * 64; e += 256) {
        int c = e >> 6, lp = e & 63;
        int q = q0 + (lp >> 2), sub = lp & 3;
        int w = q % WO;
        int h = (q / WO) % HO;
        int fb = q / (WO * HO);
        int p = (fb * HIN + 2 * h + (sub >> 1)) * WIN + 2 * w + (sub & 1);
        float val = s1[c] * xa[(size_t)c * NPIN + p] + t1[c];
        if (DUAL) {
            val += s2[c] * xb[(size_t)c * NPIN + p] + t2[c];
            val = fmaxf(val, 0.f);
        }
        actsh[e] = val;
    }

    int ob = (tid & 15) * 4;
    int ql = tid >> 4;

    for (int path = 0; path < 2; path++) {
        const float* wt = path ? w2t : w1t;
        float* outp = path ? v : u;
        for (int oc = 0; oc < COUT; oc += 64) {
            __syncthreads();
            for (int e = tid; e < CIN * 64; e += 256) {
                int c = e >> 6, o = e & 63;
                wsh[e] = wt[c * COUT + oc + o];
            }
            __syncthreads();

            float acc[4][4];
#pragma unroll
            for (int i = 0; i < 4; i++)
#pragma unroll
                for (int j = 0; j < 4; j++) acc[i][j] = 0.f;

#pragma unroll 8
            for (int c = 0; c < CIN; c++) {
                float4 a = *(const float4*)(wsh + c * 64 + ob);
                float4 bq = *(const float4*)(actsh + c * 64 + ql * 4);
                float av[4] = {a.x, a.y, a.z, a.w};
                float bv[4] = {bq.x, bq.y, bq.z, bq.w};
#pragma unroll
                for (int i = 0; i < 4; i++)
#pragma unroll
                    for (int j = 0; j < 4; j++) acc[i][j] += av[i] * bv[j];
            }
#pragma unroll
            for (int i = 0; i < 4; i++) {
                float val = fmaxf(fmaxf(acc[i][0], acc[i][1]),
                                  fmaxf(acc[i][2], acc[i][3]));
                outp[(size_t)(oc + ob + i) * NPOUT + q0 + ql] = val;
                stage[(ob + i) * 17 + ql] = val;
            }
            __syncthreads();
            if (tid < 64) {
                float s = 0.f, q = 0.f;
#pragma unroll
                for (int k = 0; k < 16; k++) {
                    float vv = stage[tid * 17 + k];
                    s += vv; q += vv * vv;
                }
                psum[(size_t)blockIdx.x * (2 * COUT) + path * COUT + oc + tid] = s;
                psq [(size_t)blockIdx.x * (2 * COUT) + path * COUT + oc + tid] = q;
            }
        }
    }
}

// ------------------ SIMT implicit-GEMM (block1 c3 only) ---------------------
template <int CIN, int COUT, int H, int W, int TAPS, int CB>
__global__ __launch_bounds__(256) void gemm_conv(
    const float* __restrict__ xin, const float* __restrict__ a2,
    const float* __restrict__ sa, const float* __restrict__ ta,
    float* __restrict__ out, float* __restrict__ psum, float* __restrict__ psq) {
    constexpr int NP = 5 * 256 * H * W;
    constexpr int KC = CB * TAPS;

    __shared__ __align__(16) float Ash[KC * 64];
    __shared__ __align__(16) float Bsh[KC * 64];
    __shared__ int nbr[TAPS * 64];
    __shared__ float partS[64 * 16], partQ[64 * 16];

    int tid = threadIdx.x;
    int q0 = blockIdx.x * 64;
    int o0 = blockIdx.y * 64;

    for (int e = tid; e < TAPS * 64; e += 256) {
        int t = e >> 6, ql = e & 63;
        int q = q0 + ql;
        int pos;
        if (TAPS == 1) pos = q;
        else {
            int w = q % W;
            int h = (q / W) % H;
            int b = (q / (W * H)) & 255;
            int f = q / (W * H * 256);
            int kf = t + 1;
            int dy = kf / 3 - 1, dx = kf % 3 - 1;
            int hh = h + dy, ww = w + dx, ff = f;
            if (hh < 0 || hh >= H) pos = -1;
            else {
                if (ww < 0)      { ff = (f + 4) % 5; ww = W - 1; }
                else if (ww >= W){ ff = (f + 1) % 5; ww = 0;     }
                pos = ((ff * 256 + b) * H + hh) * W + ww;
            }
        }
        nbr[e] = pos;
    }
    __syncthreads();

    float acc[4][4];
#pragma unroll
    for (int i = 0; i < 4; i++)
#pragma unroll
        for (int j = 0; j < 4; j++) acc[i][j] = 0.f;

    int ob = (tid & 15) * 4;
    int qb = (tid >> 4) * 4;

    for (int c0 = 0; c0 < CIN; c0 += CB) {
        for (int e = tid; e < KC * 64; e += 256) {
            int kk = e >> 6, o = e & 63;
            Ash[e] = a2[(size_t)(c0 * TAPS + kk) * COUT + o0 + o];
        }
        for (int e = tid; e < KC * 64; e += 256) {
            int kk = e >> 6, ql = e & 63;
            int cl = kk / TAPS, t = kk % TAPS;
            int c = c0 + cl;
            int pos = nbr[t * 64 + ql];
            float val = 0.f;
            if (pos >= 0)
                val = fmaxf(sa[c] * xin[(size_t)c * NP + pos] + ta[c], 0.f);
            Bsh[e] = val;
        }
        __syncthreads();
#pragma unroll
        for (int kk = 0; kk < KC; kk++) {
            float4 a = *(const float4*)(Ash + kk * 64 + ob);
            float4 b = *(const float4*)(Bsh + kk * 64 + qb);
            float av[4] = {a.x, a.y, a.z, a.w};
            float bv[4] = {b.x, b.y, b.z, b.w};
#pragma unroll
            for (int i = 0; i < 4; i++)
#pragma unroll
                for (int j = 0; j < 4; j++) acc[i][j] += av[i] * bv[j];
        }
        __syncthreads();
    }

    int qg = tid >> 4;
#pragma unroll
    for (int i = 0; i < 4; i++) {
        float4 st = {acc[i][0], acc[i][1], acc[i][2], acc[i][3]};
        *(float4*)(out + (size_t)(o0 + ob + i) * NP + q0 + qb) = st;
        float s = acc[i][0] + acc[i][1] + acc[i][2] + acc[i][3];
        float q = acc[i][0]*acc[i][0] + acc[i][1]*acc[i][1]
                + acc[i][2]*acc[i][2] + acc[i][3]*acc[i][3];
        partS[(ob + i) * 16 + qg] = s;
        partQ[(ob + i) * 16 + qg] = q;
    }
    __syncthreads();
    if (tid < 64) {
        float s = 0.f, q = 0.f;
#pragma unroll
        for (int k = 0; k < 16; k++) { s += partS[tid * 16 + k]; q += partQ[tid * 16 + k]; }
        psum[(size_t)blockIdx.x * COUT + o0 + tid] = s;
        psq [(size_t)blockIdx.x * COUT + o0 + tid] = q;
    }
}

// ---------------- generic mma.sync split-bf16 conv/GEMM ---------------------
// D[m=128 rows, o=NTILE cols] = A[m, k] * W[o, k]
// A from bf16 hi/lo planes [c][pos]; TAPS=7 hex gather (k=c*8+t) or TAPS=1.
// POOL: m = 4*qout+sub pooled rows, epilogue maxes groups of 4 rows.
// Outputs: occ < OSPLIT -> outU[occ], else outV[occ-OSPLIT]. Stats [block][NSTR].
template <int KTOT, int NTILE, int TAPS, bool POOL, int HIN, int WIN,
          int NPIN, int NPOUT, int NSTR, int OSPLIT>
__global__ __launch_bounds__(256) void mma_conv_k(
    const __nv_bfloat16* __restrict__ ahi, const __nv_bfloat16* __restrict__ alo,
    const __nv_bfloat16* __restrict__ whi, const __nv_bfloat16* __restrict__ wlo,
    float* __restrict__ outU, float* __restrict__ outV,
    float* __restrict__ psum, float* __restrict__ psq) {
    constexpr int NT = NTILE / 8;
    constexpr int NCHUNK = KTOT / 64;
    constexpr int OF_AH = 3584;
    constexpr int OF_AL = OF_AH + 18432;
    constexpr int OF_BH = OF_AL + 18432;
    constexpr int OF_BL = OF_BH + NTILE * 144;
    constexpr int OF_PS = OF_BL + NTILE * 144;
    constexpr int OF_PQ = OF_PS + NTILE * 32;

    extern __shared__ __align__(16) char smem[];
    uint32_t sb = smem_u32(smem);
    int tid = threadIdx.x;
    int wid = tid >> 5, lane = tid & 31;
    int q0 = blockIdx.x * 128;
    int o0 = blockIdx.y * NTILE;

    int* nbr = (int*)(smem);
    for (int e = tid; e < TAPS * 128; e += 256) {
        int t = e >> 7, ql = e & 127;
        int m = q0 + ql;
        int pos;
        if (POOL) {
            constexpr int WO = WIN / 2, HO = HIN / 2;
            int qq = m >> 2, sub = m & 3;
            int w = qq % WO;
            int h = (qq / WO) % HO;
            int fb = qq / (WO * HO);
            pos = (fb * HIN + 2 * h + (sub >> 1)) * WIN + 2 * w + (sub & 1);
        } else if (TAPS == 1) {
            pos = m;
        } else {
            int w = m % WIN;
            int h = (m / WIN) % HIN;
            int b = (m / (WIN * HIN)) & 255;
            int f = m / (WIN * HIN * 256);
            int kf = t + 1;
            int dy = kf / 3 - 1, dx = kf % 3 - 1;
            int hh = h + dy, ww = w + dx, ff = f;
            if (hh < 0 || hh >= HIN) pos = -1;
            else {
                if (ww < 0)        { ff = (f + 4) % 5; ww = WIN - 1; }
                else if (ww >= WIN){ ff = (f + 1) % 5; ww = 0;       }
                pos = ((ff * 256 + b) * HIN + hh) * WIN + ww;
            }
        }
        nbr[t * 128 + ql] = pos;
    }
    __syncthreads();

    float acc[NT][4];
#pragma unroll
    for (int nt = 0; nt < NT; nt++)
#pragma unroll
        for (int j = 0; j < 4; j++) acc[nt][j] = 0.f;

    int m0 = wid * 16;
    int grp = lane >> 3;
    int rowA = m0 + (lane & 7) + (grp & 1) * 8;
    int colA8 = (grp >> 1) * 8;
    uint32_t aBaseH = sb + OF_AH + (uint32_t)(rowA * LDA + colA8) * 2;
    uint32_t aBaseL = sb + OF_AL + (uint32_t)(rowA * LDA + colA8) * 2;
    int rowB = (lane & 7);
    int colB8 = ((lane >> 3) & 1) * 8;
    uint32_t bBaseH = sb + OF_BH + (uint32_t)(rowB * LDA + colB8) * 2;
    uint32_t bBaseL = sb + OF_BL + (uint32_t)(rowB * LDA + colB8) * 2;

    __nv_bfloat16* AH = (__nv_bfloat16*)(smem + OF_AH);
    __nv_bfloat16* AL = (__nv_bfloat16*)(smem + OF_AL);
    __nv_bfloat16* BH = (__nv_bfloat16*)(smem + OF_BH);
    __nv_bfloat16* BL = (__nv_bfloat16*)(smem + OF_BL);

    for (int ci = 0; ci < NCHUNK; ci++) {
        // stage A: [128 m][64 k]
#pragma unroll
        for (int it = 0; it < 32; it++) {
            int e = it * 256 + tid;
            int kk = e >> 7, q = e & 127;
            __nv_bfloat16 vh = __float2bfloat16(0.f), vl = vh;
            if (TAPS == 7) {
                int c = ci * 8 + (kk >> 3);
                int t = kk & 7;
                if (t < 7) {
                    int pos = nbr[t * 128 + q];
                    if (pos >= 0) {
                        size_t gi = (size_t)c * NPIN + pos;
                        vh = ahi[gi];
                        vl = alo[gi];
                    }
                }
            } else {
                int c = ci * 64 + kk;
                int pos = nbr[q];
                size_t gi = (size_t)c * NPIN + pos;
                vh = ahi[gi];
                vl = alo[gi];
            }
            AH[q * LDA + kk] = vh;
            AL[q * LDA + kk] = vl;
        }
        // stage B: [NTILE o][64 k]
#pragma unroll
        for (int it = 0; it < NTILE / 32; it++) {
            int e = it * 256 + tid;
            int o = e >> 3, j = e & 7;
            size_t src = (size_t)(o0 + o) * KTOT + ci * 64 + j * 8;
            *(uint4*)(BH + o * LDA + j * 8) = *(const uint4*)(whi + src);
            *(uint4*)(BL + o * LDA + j * 8) = *(const uint4*)(wlo + src);
        }
        __syncthreads();

#pragma unroll
        for (int ks = 0; ks < 4; ks++) {
            uint32_t aH[4], aL[4];
            ldmA(aH, aBaseH + ks * 32);
            ldmA(aL, aBaseL + ks * 32);
#pragma unroll
            for (int nt = 0; nt < NT; nt++) {
                uint32_t bH[2], bL[2];
                uint32_t boff = (uint32_t)(nt * 8 * LDA) * 2 + ks * 32;
                ldmB(bH, bBaseH + boff);
                ldmB(bL, bBaseL + boff);
                mma16816(acc[nt], aH, bH);
                mma16816(acc[nt], aL, bH);
                mma16816(acc[nt], aH, bL);
            }
        }
        __syncthreads();
    }

    float* pS = (float*)(smem + OF_PS);
    float* pQ = (float*)(smem + OF_PQ);

    if (!POOL) {
        int r = lane >> 2;
        int cp = (lane & 3) << 1;
#pragma unroll
        for (int nt = 0; nt < NT; nt++) {
            int c0c = nt * 8 + cp;
            int qrow = q0 + m0 + r;
            int oc0 = o0 + c0c;
            float* d0 = (oc0 < OSPLIT) ? (outU + (size_t)oc0 * NPOUT)
                                       : (outV + (size_t)(oc0 - OSPLIT) * NPOUT);
            float* d1 = (oc0 + 1 < OSPLIT) ? (outU + (size_t)(oc0 + 1) * NPOUT)
                                           : (outV + (size_t)(oc0 + 1 - OSPLIT) * NPOUT);
            d0[qrow]     = acc[nt][0];
            d1[qrow]     = acc[nt][1];
            d0[qrow + 8] = acc[nt][2];
            d1[qrow + 8] = acc[nt][3];
            float s0 = acc[nt][0] + acc[nt][2];
            float s1 = acc[nt][1] + acc[nt][3];
            float t0 = acc[nt][0]*acc[nt][0] + acc[nt][2]*acc[nt][2];
            float t1 = acc[nt][1]*acc[nt][1] + acc[nt][3]*acc[nt][3];
#pragma unroll
            for (int d = 4; d <= 16; d <<= 1) {
                s0 += __shfl_xor_sync(0xFFFFFFFFu, s0, d);
                s1 += __shfl_xor_sync(0xFFFFFFFFu, s1, d);
                t0 += __shfl_xor_sync(0xFFFFFFFFu, t0, d);
                t1 += __shfl_xor_sync(0xFFFFFFFFu, t1, d);
            }
            if (r == 0) {
                pS[wid * NTILE + c0c]     = s0;
                pS[wid * NTILE + c0c + 1] = s1;
                pQ[wid * NTILE + c0c]     = t0;
                pQ[wid * NTILE + c0c + 1] = t1;
            }
        }
    } else {
        // pooled epilogue: rows r in groups of 4 -> max
        int cp = (lane & 3) << 1;
        bool writer = ((lane >> 2) & 3) == 0;
        int gsel = lane >> 4;                   // 0: g0/g2, 1: g1/g3
        int qout0 = blockIdx.x * 32 + wid * 4;
#pragma unroll
        for (int nt = 0; nt < NT; nt++) {
            float v0 = acc[nt][0], v1 = acc[nt][1];
            float v2 = acc[nt][2], v3 = acc[nt][3];
#pragma unroll
            for (int d = 4; d <= 8; d <<= 1) {
                v0 = fmaxf(v0, __shfl_xor_sync(0xFFFFFFFFu, v0, d));
                v1 = fmaxf(v1, __shfl_xor_sync(0xFFFFFFFFu, v1, d));
                v2 = fmaxf(v2, __shfl_xor_sync(0xFFFFFFFFu, v2, d));
                v3 = fmaxf(v3, __shfl_xor_sync(0xFFFFFFFFu, v3, d));
            }
            if (writer) {
                int oc0 = o0 + nt * 8 + cp;
                float* d0 = (oc0 < OSPLIT) ? (outU + (size_t)oc0 * NPOUT)
                                           : (outV + (size_t)(oc0 - OSPLIT) * NPOUT);
                float* d1 = (oc0 + 1 < OSPLIT) ? (outU + (size_t)(oc0 + 1) * NPOUT)
                                               : (outV + (size_t)(oc0 + 1 - OSPLIT) * NPOUT);
                int qa = qout0 + gsel;
                int qb2 = qout0 + 2 + gsel;
                d0[qa]  = v0;
                d1[qa]  = v1;
                d0[qb2] = v2;
                d1[qb2] = v3;
            }
            float s0 = v0 + v2, s1 = v1 + v3;
            float t0 = v0 * v0 + v2 * v2, t1 = v1 * v1 + v3 * v3;
            s0 += __shfl_xor_sync(0xFFFFFFFFu, s0, 16);
            s1 += __shfl_xor_sync(0xFFFFFFFFu, s1, 16);
            t0 += __shfl_xor_sync(0xFFFFFFFFu, t0, 16);
            t1 += __shfl_xor_sync(0xFFFFFFFFu, t1, 16);
            if (lane < 4) {
                pS[wid * NTILE + nt * 8 + cp]     = s0;
                pS[wid * NTILE + nt * 8 + cp + 1] = s1;
                pQ[wid * NTILE + nt * 8 + cp]     = t0;
                pQ[wid * NTILE + nt * 8 + cp + 1] = t1;
            }
        }
    }
    __syncthreads();
    if (tid < NTILE) {
        float s = 0.f, q = 0.f;
#pragma unroll
        for (int w = 0; w < 8; w++) { s += pS[w * NTILE + tid]; q += pQ[w * NTILE + tid]; }
        psum[(size_t)blockIdx.x * NSTR + o0 + tid] = s;
        psq [(size_t)blockIdx.x * NSTR + o0 + tid] = q;
    }
}

// ------------- final: BN+add+relu, global max over charts+spatial -----------
__global__ __launch_bounds__(256) void maxfin_k(
    const float* __restrict__ w2, const float* __restrict__ v2,
    const float* __restrict__ scC, const float* __restrict__ shC,
    const float* __restrict__ scD, const float* __restrict__ shD,
    float* __restrict__ gmax) {
    int o = blockIdx.x, tid = threadIdx.x;
    __shared__ int mx[256];
    mx[tid] = 0;
    __syncthreads();
    float a = scC[o], c_ = shC[o], d = scD[o], e = shD[o];
    const float* wp = w2 + (size_t)o * NP2;
    const float* vp = v2 + (size_t)o * NP2;
    for (int i = tid; i < NP2; i += 256) {
        float val = fmaxf(a * wp[i] + c_ + d * vp[i] + e, 0.f);
#pragma unroll
        for (int s = 16; s; s >>= 1)
            val = fmaxf(val, __shfl_xor_sync(0xFFFFFFFFu, val, s));
        if ((tid & 31) == 0)
            atomicMax(&mx[(i >> 5) & 255], __float_as_int(val));
    }
    __syncthreads();
    gmax[tid * 256 + o] = __int_as_float(mx[tid]);
}

__global__ void fc_k(const float* __restrict__ gmax, const float* __restrict__ fw,
                     const float* __restrict__ fb, float* __restrict__ out) {
    int b = blockIdx.x, tid = threadIdx.x;
    __shared__ float m[256];
    m[tid] = gmax[b * 256 + tid];
    __syncthreads();
    if (tid < 10) {
        float acc = fb[tid];
        for (int o = 0; o < 256; o++) acc += m[o] * fw[tid * 256 + o];
        out[b * 10 + tid] = acc;
    }
}

// ------------------------- launch ------------------------------------------
#define SM128 85504
#define SM64  62976

extern "C" void kernel_launch(void* const* d_in, const int* in_sizes, int n_in,
                              void* d_out, int out_size) {
    (void)n_in; (void)out_size;

    const float* x = (const float*)d_in[0];

    float *y1,*u1,*v1,*h1,*w1,*u2,*v2,*h2,*w2,*gmax,*ps,*pq,*sc,*sh;
    float *t_b1c1,*t_b1ds,*t_b1c3;
    __nv_bfloat16 *whex_hi,*whex_lo,*wb1h_hi,*wb1h_lo,*went_hi,*went_lo,*wc3_hi,*wc3_lo;
    __nv_bfloat16 *ahi,*alo;
    cudaGetSymbolAddress((void**)&y1, g_y1);
    cudaGetSymbolAddress((void**)&u1, g_u1);
    cudaGetSymbolAddress((void**)&v1, g_v1);
    cudaGetSymbolAddress((void**)&h1, g_h1);
    cudaGetSymbolAddress((void**)&w1, g_w1);
    cudaGetSymbolAddress((void**)&u2, g_u2);
    cudaGetSymbolAddress((void**)&v2, g_v2);
    cudaGetSymbolAddress((void**)&h2, g_h2);
    cudaGetSymbolAddress((void**)&w2, g_w2);
    cudaGetSymbolAddress((void**)&gmax, g_gmax);
    cudaGetSymbolAddress((void**)&ps, g_psum);
    cudaGetSymbolAddress((void**)&pq, g_psq);
    cudaGetSymbolAddress((void**)&sc, g_scale);
    cudaGetSymbolAddress((void**)&sh, g_shift);
    cudaGetSymbolAddress((void**)&t_b1c1, g_wt_b1c1);
    cudaGetSymbolAddress((void**)&t_b1ds, g_wt_b1ds);
    cudaGetSymbolAddress((void**)&t_b1c3, g_wt_b1c3);
    cudaGetSymbolAddress((void**)&whex_hi, g_whex_hi);
    cudaGetSymbolAddress((void**)&whex_lo, g_whex_lo);
    cudaGetSymbolAddress((void**)&wb1h_hi, g_wb1h_hi);
    cudaGetSymbolAddress((void**)&wb1h_lo, g_wb1h_lo);
    cudaGetSymbolAddress((void**)&went_hi, g_went_hi);
    cudaGetSymbolAddress((void**)&went_lo, g_went_lo);
    cudaGetSymbolAddress((void**)&wc3_hi, g_wc3_hi);
    cudaGetSymbolAddress((void**)&wc3_lo, g_wc3_lo);
    cudaGetSymbolAddress((void**)&ahi, g_abf_hi);
    cudaGetSymbolAddress((void**)&alo, g_abf_lo);

    // input index tables (runtime disambiguation of metadata order)
    int I_b1c1, I_b1hex, I_b1c3, I_b1ds;
    int I_b1ga, I_b1ba, I_b1gb, I_b1bb, I_b1gc, I_b1bc, I_b1gd, I_b1bd;
    int I_b2c1, I_b2hex, I_b2c3, I_b2ds;
    int I_b2ga, I_b2ba, I_b2gb, I_b2bb, I_b2gc, I_b2bc, I_b2gd, I_b2bd;
    int I_fcw, I_fcb;
    if (in_sizes[5] == 36864) {
        I_b1c1 = 4;  I_b1hex = 5;  I_b1c3 = 6;  I_b1ds = 7;
        I_b1ga = 8;  I_b1ba = 9;  I_b1gb = 10; I_b1bb = 11;
        I_b1gc = 12; I_b1bc = 13; I_b1gd = 14; I_b1bd = 15;
        I_b2c1 = 16; I_b2hex = 17; I_b2c3 = 18; I_b2ds = 19;
        I_b2ga = 20; I_b2ba = 21; I_b2gb = 22; I_b2bb = 23;
        I_b2gc = 24; I_b2bc = 25; I_b2gd = 26; I_b2bd = 27;
        I_fcw = 28;  I_fcb = 29;
    } else {
        I_b1c1 = 4;  I_b1ga = 5;  I_b1ba = 6;  I_b1hex = 7;
        I_b1gb = 8;  I_b1bb = 9;  I_b1c3 = 10; I_b1gc = 11; I_b1bc = 12;
        I_b1ds = 13; I_b1gd = 14; I_b1bd = 15;
        I_b2c1 = 16; I_b2ga = 17; I_b2ba = 18; I_b2hex = 19;
        I_b2gb = 20; I_b2bb = 21; I_b2c3 = 22; I_b2gc = 23; I_b2bc = 24;
        I_b2ds = 25; I_b2gd = 26; I_b2bd = 27;
        I_fcw = 28;  I_fcb = 29;
    }

    // set smem limits for mma instantiations
    cudaFuncSetAttribute(mma_conv_k<512, 64, 7, false, 8, 16, NP1, NP1, 64, 64>,
                         cudaFuncAttributeMaxDynamicSharedMemorySize, SM64);
    cudaFuncSetAttribute(mma_conv_k<64, 128, 1, true, 8, 16, NP1, NP2, 512, 256>,
                         cudaFuncAttributeMaxDynamicSharedMemorySize, SM128);
    cudaFuncSetAttribute(mma_conv_k<2048, 128, 7, false, 4, 8, NP2, NP2, 256, 256>,
                         cudaFuncAttributeMaxDynamicSharedMemorySize, SM128);
    cudaFuncSetAttribute(mma_conv_k<256, 128, 1, false, 4, 8, NP2, NP2, 256, 256>,
                         cudaFuncAttributeMaxDynamicSharedMemorySize, SM128);

    // weight prep
    transpose_k<<<4,   256>>>((const float*)d_in[I_b1c1], t_b1c1, 64, 16);
    transpose_k<<<4,   256>>>((const float*)d_in[I_b1ds], t_b1ds, 64, 16);
    transpose_k<<<16,  256>>>((const float*)d_in[I_b1c3], t_b1c3, 64, 64);
    hexsplit_k<<<2048, 256>>>((const float*)d_in[I_b2hex], whex_hi, whex_lo, 256, 256);
    hexsplit_k<<<128,  256>>>((const float*)d_in[I_b1hex], wb1h_hi, wb1h_lo, 64, 64);
    split1x1_k<<<64,  256>>>((const float*)d_in[I_b2c1], went_hi, went_lo, 256, 64, 0);
    split1x1_k<<<64,  256>>>((const float*)d_in[I_b2ds], went_hi, went_lo, 256, 64, 256);
    split1x1_k<<<256, 256>>>((const float*)d_in[I_b2c3], wc3_hi, wc3_lo, 256, 256, 0);

    // stem + bn1 fold
    stem_kernel<<<NP0 / 256, 256>>>(x, (const float*)d_in[1], y1, ps, pq);
    bn_param<<<16, 256>>>(ps, pq, NP0 / 256, 16, 0, 1.f / NP0,
                          (const float*)d_in[2], (const float*)d_in[3], sc + 0, sh + 0);

    // block1 entry (SIMT)
    entry_kernel<16, 64, 16, 32, false><<<NP1 / 16, 256>>>(
        y1, nullptr, t_b1c1, t_b1ds, sc + 0, sh + 0, nullptr, nullptr, u1, v1, ps, pq);
    bn_param<<<64, 256>>>(ps, pq, NP1 / 16, 128, 0,  1.f / NP1,
                          (const float*)d_in[I_b1ga], (const float*)d_in[I_b1ba], sc + 16,  sh + 16);
    bn_param<<<64, 256>>>(ps, pq, NP1 / 16, 128, 64, 1.f / NP1,
                          (const float*)d_in[I_b1gd], (const float*)d_in[I_b1bd], sc + 208, sh + 208);

    // block1 hexconv (mma)
    actsplit_k<<<dim3(NP1 / 256, 64), 256>>>(u1, sc + 16, sh + 16, ahi, alo, NP1);
    mma_conv_k<512, 64, 7, false, 8, 16, NP1, NP1, 64, 64>
        <<<dim3(NP1 / 128, 1), 256, SM64>>>(ahi, alo, wb1h_hi, wb1h_lo, h1, nullptr, ps, pq);
    bn_param<<<64, 256>>>(ps, pq, NP1 / 128, 64, 0, 1.f / NP1,
                          (const float*)d_in[I_b1gb], (const float*)d_in[I_b1bb], sc + 80, sh + 80);

    // block1 conv3 1x1 (SIMT)
    gemm_conv<64, 64, 8, 16, 1, 32><<<dim3(NP1 / 64, 1), 256>>>(
        h1, t_b1c3, sc + 80, sh + 80, w1, ps, pq);
    bn_param<<<64, 256>>>(ps, pq, NP1 / 64, 64, 0, 1.f / NP1,
                          (const float*)d_in[I_b1gc], (const float*)d_in[I_b1bc], sc + 144, sh + 144);

    // block2 entry (mma, dual input, pooled, N=512 = main||ds)
    actsplit2_k<<<dim3(NP1 / 256, 64), 256>>>(w1, v1, sc + 144, sh + 144,
                                              sc + 208, sh + 208, ahi, alo, NP1);
    mma_conv_k<64, 128, 1, true, 8, 16, NP1, NP2, 512, 256>
        <<<dim3(NP1 / 128, 4), 256, SM128>>>(ahi, alo, went_hi, went_lo, u2, v2, ps, pq);
    bn_param<<<256, 256>>>(ps, pq, NP1 / 128, 512, 0,   1.f / NP2,
                           (const float*)d_in[I_b2ga], (const float*)d_in[I_b2ba], sc + 272,  sh + 272);
    bn_param<<<256, 256>>>(ps, pq, NP1 / 128, 512, 256, 1.f / NP2,
                           (const float*)d_in[I_b2gd], (const float*)d_in[I_b2bd], sc + 1040, sh + 1040);

    // block2 hexconv (mma)
    actsplit_k<<<dim3(NP2 / 256, 256), 256>>>(u2, sc + 272, sh + 272, ahi, alo, NP2);
    mma_conv_k<2048, 128, 7, false, 4, 8, NP2, NP2, 256, 256>
        <<<dim3(NP2 / 128, 2), 256, SM128>>>(ahi, alo, whex_hi, whex_lo, h2, nullptr, ps, pq);
    bn_param<<<256, 256>>>(ps, pq, NP2 / 128, 256, 0, 1.f / NP2,
                           (const float*)d_in[I_b2gb], (const float*)d_in[I_b2bb], sc + 528, sh + 528);

    // block2 conv3 1x1 (mma)
    actsplit_k<<<dim3(NP2 / 256, 256), 256>>>(h2, sc + 528, sh + 528, ahi, alo, NP2);
    mma_conv_k<256, 128, 1, false, 4, 8, NP2, NP2, 256, 256>
        <<<dim3(NP2 / 128, 2), 256, SM128>>>(ahi, alo, wc3_hi, wc3_lo, w2, nullptr, ps, pq);
    bn_param<<<256, 256>>>(ps, pq, NP2 / 128, 256, 0, 1.f / NP2,
                           (const float*)d_in[I_b2gc], (const float*)d_in[I_b2bc], sc + 784, sh + 784);

    // tail
    maxfin_k<<<256, 256>>>(w2, v2, sc + 784, sh + 784, sc + 1040, sh + 1040, gmax);
    fc_k<<<256, 256>>>(gmax, (const float*)d_in[I_fcw], (const float*)d_in[I_fcb], (float*)d_out);
}

// round 10
// speedup vs baseline: 1.8965x; 1.6081x over previous
#include <cuda_runtime.h>
#include <cuda_bf16.h>
#include <cstdint>

// Geometry:
//  stage0 in : [5][256][3][16][32]
//  y1 (stem) : 16ch @16x32, NP0 = 5*256*512 = 655360
//  block1    : 64ch @8x16,  NP1 = 5*256*128 = 163840
//  block2    : 256ch@4x8,   NP2 = 5*256*32  = 40960
// fp32 activations: chan-major t[c*NP + pos]; bf16 planes: position-major [pos][C]

#define NP0 655360
#define NP1 163840
#define NP2 40960

// ------------------------- device scratch ----------------------------------
__device__ float g_y1[16 * NP0];
__device__ float g_u1[64 * NP1];
__device__ float g_v1[64 * NP1];
__device__ float g_h1[64 * NP1];
__device__ float g_w1[64 * NP1];
__device__ float g_u2[256 * NP2];
__device__ float g_v2[256 * NP2];
__device__ float g_h2[256 * NP2];
__device__ float g_w2[256 * NP2];
__device__ float g_gmax[256 * 256];

__device__ float g_psum[1310720];
__device__ float g_psq [1310720];

__device__ float g_scale[1296];
__device__ float g_shift[1296];

__device__ float g_wt_b1c1[16 * 64];
__device__ float g_wt_b1ds[16 * 64];
__device__ float g_wt_b1c3[64 * 64];

// split bf16 weights (hex: k = chunk*64 + t*8 + cl, tap7 = 0)
__device__ __nv_bfloat16 g_whex_hi[256 * 2048];
__device__ __nv_bfloat16 g_whex_lo[256 * 2048];
__device__ __nv_bfloat16 g_wb1h_hi[64 * 512];
__device__ __nv_bfloat16 g_wb1h_lo[64 * 512];
__device__ __nv_bfloat16 g_went_hi[512 * 64];
__device__ __nv_bfloat16 g_went_lo[512 * 64];
__device__ __nv_bfloat16 g_wc3_hi [256 * 256];
__device__ __nv_bfloat16 g_wc3_lo [256 * 256];

// split bf16 activation planes, position-major [pos][C] (reused sequentially)
__device__ __nv_bfloat16 g_abf_hi[10485760];
__device__ __nv_bfloat16 g_abf_lo[10485760];

// ------------------------- mma helpers -------------------------------------
__device__ __forceinline__ uint32_t smem_u32(const void* p) {
    uint32_t a;
    asm("{ .reg .u64 t; cvta.to.shared.u64 t, %1; cvt.u32.u64 %0, t; }"
        : "=r"(a) : "l"(p));
    return a;
}
__device__ __forceinline__ void ldmA(uint32_t* a, uint32_t addr) {
    asm volatile("ldmatrix.sync.aligned.m8n8.x4.shared.b16 {%0,%1,%2,%3}, [%4];"
        : "=r"(a[0]), "=r"(a[1]), "=r"(a[2]), "=r"(a[3]) : "r"(addr));
}
__device__ __forceinline__ void ldmB(uint32_t* b, uint32_t addr) {
    asm volatile("ldmatrix.sync.aligned.m8n8.x2.shared.b16 {%0,%1}, [%2];"
        : "=r"(b[0]), "=r"(b[1]) : "r"(addr));
}
__device__ __forceinline__ void mma16816(float* d, const uint32_t* a, const uint32_t* b) {
    asm volatile(
        "mma.sync.aligned.m16n8k16.row.col.f32.bf16.bf16.f32 "
        "{%0,%1,%2,%3}, {%4,%5,%6,%7}, {%8,%9}, {%0,%1,%2,%3};"
        : "+f"(d[0]), "+f"(d[1]), "+f"(d[2]), "+f"(d[3])
        : "r"(a[0]), "r"(a[1]), "r"(a[2]), "r"(a[3]), "r"(b[0]), "r"(b[1]));
}
#define LDA 72

// ------------------------- prep kernels ------------------------------------
__global__ void transpose_k(const float* __restrict__ src, float* __restrict__ dst,
                            int O, int C) {
    int i = blockIdx.x * 256 + threadIdx.x;
    if (i < O * C) { int o = i / C, c = i % C; dst[c * O + o] = src[i]; }
}

// [O][C][3][3] fp32 -> split bf16 [o][(c/8)*64 + t*8 + (c%8)] (tap7 zero)
__global__ void hexsplit_k(const float* __restrict__ src,
                           __nv_bfloat16* __restrict__ hi, __nv_bfloat16* __restrict__ lo,
                           int O, int C) {
    int i = blockIdx.x * 256 + threadIdx.x;
    if (i < O * C * 8) {
        int t = i & 7;
        int c = (i >> 3) % C;
        int o = i / (8 * C);
        float w = (t < 7) ? src[(o * C + c) * 9 + t + 1] : 0.f;
        __nv_bfloat16 h = __float2bfloat16(w);
        int k = (c >> 3) * 64 + t * 8 + (c & 7);
        hi[(size_t)o * (C * 8) + k] = h;
        lo[(size_t)o * (C * 8) + k] = __float2bfloat16(w - __bfloat162float(h));
    }
}

// [O][C] fp32 -> split bf16 rows at rowoff (row stride C)
__global__ void split1x1_k(const float* __restrict__ src,
                           __nv_bfloat16* __restrict__ hi, __nv_bfloat16* __restrict__ lo,
                           int O, int C, int rowoff) {
    int i = blockIdx.x * 256 + threadIdx.x;
    if (i < O * C) {
        float w = src[i];
        __nv_bfloat16 h = __float2bfloat16(w);
        int o = i / C, c = i % C;
        hi[(rowoff + o) * C + c] = h;
        lo[(rowoff + o) * C + c] = __float2bfloat16(w - __bfloat162float(h));
    }
}

// relu(sc*x+sh), chan-major fp32 -> position-major bf16 hi/lo [q][C]
__global__ __launch_bounds__(256) void actsplitT_k(
    const float* __restrict__ x, const float* __restrict__ sc,
    const float* __restrict__ sh,
    __nv_bfloat16* __restrict__ hi, __nv_bfloat16* __restrict__ lo, int NP, int C) {
    __shared__ float tile[32][33];
    int q0 = blockIdx.x * 32, c0 = blockIdx.y * 32;
    int tq = threadIdx.x & 31, tc = threadIdx.x >> 5;
#pragma unroll
    for (int i = 0; i < 4; i++) {
        int c = c0 + tc + i * 8;
        tile[tc + i * 8][tq] = fmaxf(sc[c] * x[(size_t)c * NP + q0 + tq] + sh[c], 0.f);
    }
    __syncthreads();
    int tcw = threadIdx.x & 31, tqw = threadIdx.x >> 5;
#pragma unroll
    for (int i = 0; i < 4; i++) {
        float v = tile[tcw][tqw + i * 8];
        __nv_bfloat16 h = __float2bfloat16(v);
        size_t idx = (size_t)(q0 + tqw + i * 8) * C + c0 + tcw;
        hi[idx] = h;
        lo[idx] = __float2bfloat16(v - __bfloat162float(h));
    }
}

// relu(s1*a+t1 + s2*b+t2) -> position-major bf16
__global__ __launch_bounds__(256) void actsplit2T_k(
    const float* __restrict__ xa, const float* __restrict__ xb,
    const float* __restrict__ s1, const float* __restrict__ t1,
    const float* __restrict__ s2, const float* __restrict__ t2,
    __nv_bfloat16* __restrict__ hi, __nv_bfloat16* __restrict__ lo, int NP, int C) {
    __shared__ float tile[32][33];
    int q0 = blockIdx.x * 32, c0 = blockIdx.y * 32;
    int tq = threadIdx.x & 31, tc = threadIdx.x >> 5;
#pragma unroll
    for (int i = 0; i < 4; i++) {
        int c = c0 + tc + i * 8;
        size_t gi = (size_t)c * NP + q0 + tq;
        tile[tc + i * 8][tq] =
            fmaxf(s1[c] * xa[gi] + t1[c] + s2[c] * xb[gi] + t2[c], 0.f);
    }
    __syncthreads();
    int tcw = threadIdx.x & 31, tqw = threadIdx.x >> 5;
#pragma unroll
    for (int i = 0; i < 4; i++) {
        float v = tile[tcw][tqw + i * 8];
        __nv_bfloat16 h = __float2bfloat16(v);
        size_t idx = (size_t)(q0 + tqw + i * 8) * C + c0 + tcw;
        hi[idx] = h;
        lo[idx] = __float2bfloat16(v - __bfloat162float(h));
    }
}

// ------------------------- stem --------------------------------------------
__global__ __launch_bounds__(256) void stem_kernel(
    const float* __restrict__ x, const float* __restrict__ wc,
    float* __restrict__ y1, float* __restrict__ psum, float* __restrict__ psq) {
    __shared__ float wsh[432];
    __shared__ float wpS[16][8], wpQ[16][8];
    int tid = threadIdx.x;
    for (int e = tid; e < 432; e += 256) wsh[e] = wc[e];
    __syncthreads();

    int pos = blockIdx.x * 256 + tid;
    int w = pos & 31, h = (pos >> 5) & 15, b = (pos >> 9) & 255, f = pos >> 17;

    float acc[16];
#pragma unroll
    for (int o = 0; o < 16; o++) acc[o] = 0.f;

#pragma unroll
    for (int t = 0; t < 7; t++) {
        int kf = t + 1;
        int dy = kf / 3 - 1, dx = kf % 3 - 1;
        int hh = h + dy;
        float xv0 = 0.f, xv1 = 0.f, xv2 = 0.f;
        if (hh >= 0 && hh < 16) {
            int ww = w + dx, ff = f;
            if (ww < 0)       { ff = (f + 4) % 5; ww = 31; }
            else if (ww > 31) { ff = (f + 1) % 5; ww = 0;  }
            int base = (ff * 256 + b) * 1536 + hh * 32 + ww;
            xv0 = x[base];
            xv1 = x[base + 512];
            xv2 = x[base + 1024];
        }
#pragma unroll
        for (int o = 0; o < 16; o++) {
            acc[o] += wsh[(o * 3 + 0) * 9 + kf] * xv0
                    + wsh[(o * 3 + 1) * 9 + kf] * xv1
                    + wsh[(o * 3 + 2) * 9 + kf] * xv2;
        }
    }

    int lane = tid & 31, warp = tid >> 5;
#pragma unroll
    for (int o = 0; o < 16; o++) {
        float val = fmaxf(acc[o], 0.f);
        y1[o * NP0 + pos] = val;
        float s = val, q2 = val * val;
#pragma unroll
        for (int d = 16; d; d >>= 1) {
            s  += __shfl_xor_sync(0xFFFFFFFFu, s,  d);
            q2 += __shfl_xor_sync(0xFFFFFFFFu, q2, d);
        }
        if (lane == 0) { wpS[o][warp] = s; wpQ[o][warp] = q2; }
    }
    __syncthreads();
    if (tid < 16) {
        float s = 0.f, q = 0.f;
#pragma unroll
        for (int wpi = 0; wpi < 8; wpi++) { s += wpS[tid][wpi]; q += wpQ[tid][wpi]; }
        psum[blockIdx.x * 16 + tid] = s;
        psq [blockIdx.x * 16 + tid] = q;
    }
}

// ------------------------- BN param fold ------------------------------------
__global__ void bn_param(const float* __restrict__ ps, const float* __restrict__ pq,
                         int nparts, int cstride, int coff, float invN,
                         const float* __restrict__ g, const float* __restrict__ b,
                         float* __restrict__ sc, float* __restrict__ sh) {
    int c = blockIdx.x, tid = threadIdx.x;
    float s = 0.f, q = 0.f;
    for (int p = tid; p < nparts; p += 256) {
        s += ps[(size_t)p * cstride + coff + c];
        q += pq[(size_t)p * cstride + coff + c];
    }
    __shared__ float rs[256], rq[256];
    rs[tid] = s; rq[tid] = q;
    __syncthreads();
    for (int d = 128; d; d >>= 1) {
        if (tid < d) { rs[tid] += rs[tid + d]; rq[tid] += rq[tid + d]; }
        __syncthreads();
    }
    if (tid == 0) {
        float mean = rs[0] * invN;
        float var  = rq[0] * invN - mean * mean;
        float k = g[c] * rsqrtf(var + 1e-5f);
        sc[c] = k;
        sh[c] = b[c] - mean * k;
    }
}

// -------------- resblock entry (SIMT, block1 only) --------------------------
template <int CIN, int COUT, int HIN, int WIN, bool DUAL>
__global__ __launch_bounds__(256) void entry_kernel(
    const float* __restrict__ xa, const float* __restrict__ xb,
    const float* __restrict__ w1t, const float* __restrict__ w2t,
    const float* __restrict__ s1, const float* __restrict__ t1,
    const float* __restrict__ s2, const float* __restrict__ t2,
    float* __restrict__ u, float* __restrict__ v,
    float* __restrict__ psum, float* __restrict__ psq) {
    constexpr int HO = HIN / 2, WO = WIN / 2;
    constexpr int NPIN  = 5 * 256 * HIN * WIN;
    constexpr int NPOUT = 5 * 256 * HO * WO;

    __shared__ __align__(16) float actsh[CIN * 64];
    __shared__ __align__(16) float wsh[CIN * 64];
    __shared__ float stage[64 * 17];

    int tid = threadIdx.x;
    int q0 = blockIdx.x * 16;

    for (int e = tid; e < CIN * 64; e += 256) {
        int c = e >> 6, lp = e & 63;
        int q = q0 + (lp >> 2), sub = lp & 3;
        int w = q % WO;
        int h = (q / WO) % HO;
        int fb = q / (WO * HO);
        int p = (fb * HIN + 2 * h + (sub >> 1)) * WIN + 2 * w + (sub & 1);
        float val = s1[c] * xa[(size_t)c * NPIN + p] + t1[c];
        if (DUAL) {
            val += s2[c] * xb[(size_t)c * NPIN + p] + t2[c];
            val = fmaxf(val, 0.f);
        }
        actsh[e] = val;
    }

    int ob = (tid & 15) * 4;
    int ql = tid >> 4;

    for (int path = 0; path < 2; path++) {
        const float* wt = path ? w2t : w1t;
        float* outp = path ? v : u;
        for (int oc = 0; oc < COUT; oc += 64) {
            __syncthreads();
            for (int e = tid; e < CIN * 64; e += 256) {
                int c = e >> 6, o = e & 63;
                wsh[e] = wt[c * COUT + oc + o];
            }
            __syncthreads();

            float acc[4][4];
#pragma unroll
            for (int i = 0; i < 4; i++)
#pragma unroll
                for (int j = 0; j < 4; j++) acc[i][j] = 0.f;

#pragma unroll 8
            for (int c = 0; c < CIN; c++) {
                float4 a = *(const float4*)(wsh + c * 64 + ob);
                float4 bq = *(const float4*)(actsh + c * 64 + ql * 4);
                float av[4] = {a.x, a.y, a.z, a.w};
                float bv[4] = {bq.x, bq.y, bq.z, bq.w};
#pragma unroll
                for (int i = 0; i < 4; i++)
#pragma unroll
                    for (int j = 0; j < 4; j++) acc[i][j] += av[i] * bv[j];
            }
#pragma unroll
            for (int i = 0; i < 4; i++) {
                float val = fmaxf(fmaxf(acc[i][0], acc[i][1]),
                                  fmaxf(acc[i][2], acc[i][3]));
                outp[(size_t)(oc + ob + i) * NPOUT + q0 + ql] = val;
                stage[(ob + i) * 17 + ql] = val;
            }
            __syncthreads();
            if (tid < 64) {
                float s = 0.f, q = 0.f;
#pragma unroll
                for (int k = 0; k < 16; k++) {
                    float vv = stage[tid * 17 + k];
                    s += vv; q += vv * vv;
                }
                psum[(size_t)blockIdx.x * (2 * COUT) + path * COUT + oc + tid] = s;
                psq [(size_t)blockIdx.x * (2 * COUT) + path * COUT + oc + tid] = q;
            }
        }
    }
}

// ------------------ SIMT implicit-GEMM (block1 c3 only) ---------------------
template <int CIN, int COUT, int H, int W, int TAPS, int CB>
__global__ __launch_bounds__(256) void gemm_conv(
    const float* __restrict__ xin, const float* __restrict__ a2,
    const float* __restrict__ sa, const float* __restrict__ ta,
    float* __restrict__ out, float* __restrict__ psum, float* __restrict__ psq) {
    constexpr int NP = 5 * 256 * H * W;
    constexpr int KC = CB * TAPS;

    __shared__ __align__(16) float Ash[KC * 64];
    __shared__ __align__(16) float Bsh[KC * 64];
    __shared__ int nbr[TAPS * 64];
    __shared__ float partS[64 * 16], partQ[64 * 16];

    int tid = threadIdx.x;
    int q0 = blockIdx.x * 64;
    int o0 = blockIdx.y * 64;

    for (int e = tid; e < TAPS * 64; e += 256) {
        int t = e >> 6, ql = e & 63;
        int q = q0 + ql;
        int pos;
        if (TAPS == 1) pos = q;
        else {
            int w = q % W;
            int h = (q / W) % H;
            int b = (q / (W * H)) & 255;
            int f = q / (W * H * 256);
            int kf = t + 1;
            int dy = kf / 3 - 1, dx = kf % 3 - 1;
            int hh = h + dy, ww = w + dx, ff = f;
            if (hh < 0 || hh >= H) pos = -1;
            else {
                if (ww < 0)      { ff = (f + 4) % 5; ww = W - 1; }
                else if (ww >= W){ ff = (f + 1) % 5; ww = 0;     }
                pos = ((ff * 256 + b) * H + hh) * W + ww;
            }
        }
        nbr[e] = pos;
    }
    __syncthreads();

    float acc[4][4];
#pragma unroll
    for (int i = 0; i < 4; i++)
#pragma unroll
        for (int j = 0; j < 4; j++) acc[i][j] = 0.f;

    int ob = (tid & 15) * 4;
    int qb = (tid >> 4) * 4;

    for (int c0 = 0; c0 < CIN; c0 += CB) {
        for (int e = tid; e < KC * 64; e += 256) {
            int kk = e >> 6, o = e & 63;
            Ash[e] = a2[(size_t)(c0 * TAPS + kk) * COUT + o0 + o];
        }
        for (int e = tid; e < KC * 64; e += 256) {
            int kk = e >> 6, ql = e & 63;
            int cl = kk / TAPS, t = kk % TAPS;
            int c = c0 + cl;
            int pos = nbr[t * 64 + ql];
            float val = 0.f;
            if (pos >= 0)
                val = fmaxf(sa[c] * xin[(size_t)c * NP + pos] + ta[c], 0.f);
            Bsh[e] = val;
        }
        __syncthreads();
#pragma unroll
        for (int kk = 0; kk < KC; kk++) {
            float4 a = *(const float4*)(Ash + kk * 64 + ob);
            float4 b = *(const float4*)(Bsh + kk * 64 + qb);
            float av[4] = {a.x, a.y, a.z, a.w};
            float bv[4] = {b.x, b.y, b.z, b.w};
#pragma unroll
            for (int i = 0; i < 4; i++)
#pragma unroll
                for (int j = 0; j < 4; j++) acc[i][j] += av[i] * bv[j];
        }
        __syncthreads();
    }

    int qg = tid >> 4;
#pragma unroll
    for (int i = 0; i < 4; i++) {
        float4 st = {acc[i][0], acc[i][1], acc[i][2], acc[i][3]};
        *(float4*)(out + (size_t)(o0 + ob + i) * NP + q0 + qb) = st;
        float s = acc[i][0] + acc[i][1] + acc[i][2] + acc[i][3];
        float q = acc[i][0]*acc[i][0] + acc[i][1]*acc[i][1]
                + acc[i][2]*acc[i][2] + acc[i][3]*acc[i][3];
        partS[(ob + i) * 16 + qg] = s;
        partQ[(ob + i) * 16 + qg] = q;
    }
    __syncthreads();
    if (tid < 64) {
        float s = 0.f, q = 0.f;
#pragma unroll
        for (int k = 0; k < 16; k++) { s += partS[tid * 16 + k]; q += partQ[tid * 16 + k]; }
        psum[(size_t)blockIdx.x * COUT + o0 + tid] = s;
        psq [(size_t)blockIdx.x * COUT + o0 + tid] = q;
    }
}

// ---------------- generic mma.sync split-bf16 conv/GEMM ---------------------
// D[m=128, o=NTILE] = A[m, k] * W[o, k]; A from position-major bf16 planes [pos][CDIM].
// TAPS=7: k = chunk*64 + t*8 + cl (uint4 gather per tap); TAPS=1: k = c.
// POOL: rows are 4 pool candidates per output; epilogue maxes them.
template <int KTOT, int NTILE, int TAPS, bool POOL, int HIN, int WIN,
          int NPOUT, int NSTR, int OSPLIT, int CDIM>
__global__ __launch_bounds__(256) void mma_conv_k(
    const __nv_bfloat16* __restrict__ ahi, const __nv_bfloat16* __restrict__ alo,
    const __nv_bfloat16* __restrict__ whi, const __nv_bfloat16* __restrict__ wlo,
    float* __restrict__ outU, float* __restrict__ outV,
    float* __restrict__ psum, float* __restrict__ psq) {
    constexpr int NT = NTILE / 8;
    constexpr int NCHUNK = KTOT / 64;
    constexpr int OF_AH = 3584;
    constexpr int OF_AL = OF_AH + 18432;
    constexpr int OF_BH = OF_AL + 18432;
    constexpr int OF_BL = OF_BH + NTILE * 144;
    constexpr int OF_PS = OF_BL + NTILE * 144;
    constexpr int OF_PQ = OF_PS + NTILE * 32;

    extern __shared__ __align__(16) char smem[];
    uint32_t sb = smem_u32(smem);
    int tid = threadIdx.x;
    int wid = tid >> 5, lane = tid & 31;
    int q0 = blockIdx.x * 128;
    int o0 = blockIdx.y * NTILE;

    int* nbr = (int*)(smem);
    for (int e = tid; e < TAPS * 128; e += 256) {
        int t = e >> 7, ql = e & 127;
        int m = q0 + ql;
        int pos;
        if (POOL) {
            constexpr int WO = WIN / 2, HO = HIN / 2;
            int qq = m >> 2, sub = m & 3;
            int w = qq % WO;
            int h = (qq / WO) % HO;
            int fb = qq / (WO * HO);
            pos = (fb * HIN + 2 * h + (sub >> 1)) * WIN + 2 * w + (sub & 1);
        } else if (TAPS == 1) {
            pos = m;
        } else {
            int w = m % WIN;
            int h = (m / WIN) % HIN;
            int b = (m / (WIN * HIN)) & 255;
            int f = m / (WIN * HIN * 256);
            int kf = t + 1;
            int dy = kf / 3 - 1, dx = kf % 3 - 1;
            int hh = h + dy, ww = w + dx, ff = f;
            if (hh < 0 || hh >= HIN) pos = -1;
            else {
                if (ww < 0)        { ff = (f + 4) % 5; ww = WIN - 1; }
                else if (ww >= WIN){ ff = (f + 1) % 5; ww = 0;       }
                pos = ((ff * 256 + b) * HIN + hh) * WIN + ww;
            }
        }
        nbr[t * 128 + ql] = pos;
    }
    __syncthreads();

    float acc[NT][4];
#pragma unroll
    for (int nt = 0; nt < NT; nt++)
#pragma unroll
        for (int j = 0; j < 4; j++) acc[nt][j] = 0.f;

    int m0 = wid * 16;
    int grp = lane >> 3;
    int rowA = m0 + (lane & 7) + (grp & 1) * 8;
    int colA8 = (grp >> 1) * 8;
    uint32_t aBaseH = sb + OF_AH + (uint32_t)(rowA * LDA + colA8) * 2;
    uint32_t aBaseL = sb + OF_AL + (uint32_t)(rowA * LDA + colA8) * 2;
    int rowB = (lane & 7);
    int colB8 = ((lane >> 3) & 1) * 8;
    uint32_t bBaseH = sb + OF_BH + (uint32_t)(rowB * LDA + colB8) * 2;
    uint32_t bBaseL = sb + OF_BL + (uint32_t)(rowB * LDA + colB8) * 2;

    __nv_bfloat16* AH = (__nv_bfloat16*)(smem + OF_AH);
    __nv_bfloat16* AL = (__nv_bfloat16*)(smem + OF_AL);
    __nv_bfloat16* BH = (__nv_bfloat16*)(smem + OF_BH);
    __nv_bfloat16* BL = (__nv_bfloat16*)(smem + OF_BL);

#pragma unroll 1
    for (int ci = 0; ci < NCHUNK; ci++) {
        // stage A: [128 m][64 k], vectorized uint4 (8 bf16 per op)
#pragma unroll
        for (int it = 0; it < 4; it++) {
            int e = it * 256 + tid;            // 0..1023
            int q = e >> 3, g = e & 7;
            uint4 vh = {0u, 0u, 0u, 0u}, vl = {0u, 0u, 0u, 0u};
            if (TAPS == 7) {
                if (g < 7) {
                    int pos = nbr[g * 128 + q];
                    if (pos >= 0) {
                        size_t base = (size_t)pos * CDIM + ci * 8;
                        vh = *(const uint4*)(ahi + base);
                        vl = *(const uint4*)(alo + base);
                    }
                }
            } else {
                int pos = nbr[q];
                size_t base = (size_t)pos * CDIM + ci * 64 + g * 8;
                vh = *(const uint4*)(ahi + base);
                vl = *(const uint4*)(alo + base);
            }
            *(uint4*)(AH + q * LDA + g * 8) = vh;
            *(uint4*)(AL + q * LDA + g * 8) = vl;
        }
        // stage B: [NTILE o][64 k]
#pragma unroll
        for (int it = 0; it < NTILE / 32; it++) {
            int e = it * 256 + tid;
            int o = e >> 3, j = e & 7;
            size_t src = (size_t)(o0 + o) * KTOT + ci * 64 + j * 8;
            *(uint4*)(BH + o * LDA + j * 8) = *(const uint4*)(whi + src);
            *(uint4*)(BL + o * LDA + j * 8) = *(const uint4*)(wlo + src);
        }
        __syncthreads();

#pragma unroll
        for (int ks = 0; ks < 4; ks++) {
            uint32_t aH[4], aL[4];
            ldmA(aH, aBaseH + ks * 32);
            ldmA(aL, aBaseL + ks * 32);
#pragma unroll
            for (int nt = 0; nt < NT; nt++) {
                uint32_t bH[2], bL[2];
                uint32_t boff = (uint32_t)(nt * 8 * LDA) * 2 + ks * 32;
                ldmB(bH, bBaseH + boff);
                ldmB(bL, bBaseL + boff);
                mma16816(acc[nt], aH, bH);
                mma16816(acc[nt], aL, bH);
                mma16816(acc[nt], aH, bL);
            }
        }
        __syncthreads();
    }

    float* pS = (float*)(smem + OF_PS);
    float* pQ = (float*)(smem + OF_PQ);

    if (!POOL) {
        int r = lane >> 2;
        int cp = (lane & 3) << 1;
#pragma unroll
        for (int nt = 0; nt < NT; nt++) {
            int c0c = nt * 8 + cp;
            int qrow = q0 + m0 + r;
            int oc0 = o0 + c0c;
            float* d0 = (oc0 < OSPLIT) ? (outU + (size_t)oc0 * NPOUT)
                                       : (outV + (size_t)(oc0 - OSPLIT) * NPOUT);
            float* d1 = (oc0 + 1 < OSPLIT) ? (outU + (size_t)(oc0 + 1) * NPOUT)
                                           : (outV + (size_t)(oc0 + 1 - OSPLIT) * NPOUT);
            d0[qrow]     = acc[nt][0];
            d1[qrow]     = acc[nt][1];
            d0[qrow + 8] = acc[nt][2];
            d1[qrow + 8] = acc[nt][3];
            float s0 = acc[nt][0] + acc[nt][2];
            float s1 = acc[nt][1] + acc[nt][3];
            float t0 = acc[nt][0]*acc[nt][0] + acc[nt][2]*acc[nt][2];
            float t1 = acc[nt][1]*acc[nt][1] + acc[nt][3]*acc[nt][3];
#pragma unroll
            for (int d = 4; d <= 16; d <<= 1) {
                s0 += __shfl_xor_sync(0xFFFFFFFFu, s0, d);
                s1 += __shfl_xor_sync(0xFFFFFFFFu, s1, d);
                t0 += __shfl_xor_sync(0xFFFFFFFFu, t0, d);
                t1 += __shfl_xor_sync(0xFFFFFFFFu, t1, d);
            }
            if (r == 0) {
                pS[wid * NTILE + c0c]     = s0;
                pS[wid * NTILE + c0c + 1] = s1;
                pQ[wid * NTILE + c0c]     = t0;
                pQ[wid * NTILE + c0c + 1] = t1;
            }
        }
    } else {
        int cp = (lane & 3) << 1;
        bool writer = ((lane >> 2) & 3) == 0;
        int gsel = lane >> 4;
        int qout0 = blockIdx.x * 32 + wid * 4;
#pragma unroll
        for (int nt = 0; nt < NT; nt++) {
            float v0 = acc[nt][0], v1 = acc[nt][1];
            float v2 = acc[nt][2], v3 = acc[nt][3];
#pragma unroll
            for (int d = 4; d <= 8; d <<= 1) {
                v0 = fmaxf(v0, __shfl_xor_sync(0xFFFFFFFFu, v0, d));
                v1 = fmaxf(v1, __shfl_xor_sync(0xFFFFFFFFu, v1, d));
                v2 = fmaxf(v2, __shfl_xor_sync(0xFFFFFFFFu, v2, d));
                v3 = fmaxf(v3, __shfl_xor_sync(0xFFFFFFFFu, v3, d));
            }
            if (writer) {
                int oc0 = o0 + nt * 8 + cp;
                float* d0 = (oc0 < OSPLIT) ? (outU + (size_t)oc0 * NPOUT)
                                           : (outV + (size_t)(oc0 - OSPLIT) * NPOUT);
                float* d1 = (oc0 + 1 < OSPLIT) ? (outU + (size_t)(oc0 + 1) * NPOUT)
                                               : (outV + (size_t)(oc0 + 1 - OSPLIT) * NPOUT);
                int qa = qout0 + gsel;
                int qb2 = qout0 + 2 + gsel;
                d0[qa]  = v0;
                d1[qa]  = v1;
                d0[qb2] = v2;
                d1[qb2] = v3;
            }
            float s0 = v0 + v2, s1 = v1 + v3;
            float t0 = v0 * v0 + v2 * v2, t1 = v1 * v1 + v3 * v3;
            s0 += __shfl_xor_sync(0xFFFFFFFFu, s0, 16);
            s1 += __shfl_xor_sync(0xFFFFFFFFu, s1, 16);
            t0 += __shfl_xor_sync(0xFFFFFFFFu, t0, 16);
            t1 += __shfl_xor_sync(0xFFFFFFFFu, t1, 16);
            if (lane < 4) {
                pS[wid * NTILE + nt * 8 + cp]     = s0;
                pS[wid * NTILE + nt * 8 + cp + 1] = s1;
                pQ[wid * NTILE + nt * 8 + cp]     = t0;
                pQ[wid * NTILE + nt * 8 + cp + 1] = t1;
            }
        }
    }
    __syncthreads();
    if (tid < NTILE) {
        float s = 0.f, q = 0.f;
#pragma unroll
        for (int w = 0; w < 8; w++) { s += pS[w * NTILE + tid]; q += pQ[w * NTILE + tid]; }
        psum[(size_t)blockIdx.x * NSTR + o0 + tid] = s;
        psq [(size_t)blockIdx.x * NSTR + o0 + tid] = q;
    }
}

// ------------- final: BN+add+relu, global max over charts+spatial -----------
__global__ __launch_bounds__(256) void maxfin_k(
    const float* __restrict__ w2, const float* __restrict__ v2,
    const float* __restrict__ scC, const float* __restrict__ shC,
    const float* __restrict__ scD, const float* __restrict__ shD,
    float* __restrict__ gmax) {
    int o = blockIdx.x, tid = threadIdx.x;
    __shared__ int mx[256];
    mx[tid] = 0;
    __syncthreads();
    float a = scC[o], c_ = shC[o], d = scD[o], e = shD[o];
    const float* wp = w2 + (size_t)o * NP2;
    const float* vp = v2 + (size_t)o * NP2;
    for (int i = tid; i < NP2; i += 256) {
        float val = fmaxf(a * wp[i] + c_ + d * vp[i] + e, 0.f);
#pragma unroll
        for (int s = 16; s; s >>= 1)
            val = fmaxf(val, __shfl_xor_sync(0xFFFFFFFFu, val, s));
        if ((tid & 31) == 0)
            atomicMax(&mx[(i >> 5) & 255], __float_as_int(val));
    }
    __syncthreads();
    gmax[tid * 256 + o] = __int_as_float(mx[tid]);
}

__global__ void fc_k(const float* __restrict__ gmax, const float* __restrict__ fw,
                     const float* __restrict__ fb, float* __restrict__ out) {
    int b = blockIdx.x, tid = threadIdx.x;
    __shared__ float m[256];
    m[tid] = gmax[b * 256 + tid];
    __syncthreads();
    if (tid < 10) {
        float acc = fb[tid];
        for (int o = 0; o < 256; o++) acc += m[o] * fw[tid * 256 + o];
        out[b * 10 + tid] = acc;
    }
}

// ------------------------- launch ------------------------------------------
#define SM128 85504
#define SM64  62976

extern "C" void kernel_launch(void* const* d_in, const int* in_sizes, int n_in,
                              void* d_out, int out_size) {
    (void)n_in; (void)out_size;

    const float* x = (const float*)d_in[0];

    float *y1,*u1,*v1,*h1,*w1,*u2,*v2,*h2,*w2,*gmax,*ps,*pq,*sc,*sh;
    float *t_b1c1,*t_b1ds,*t_b1c3;
    __nv_bfloat16 *whex_hi,*whex_lo,*wb1h_hi,*wb1h_lo,*went_hi,*went_lo,*wc3_hi,*wc3_lo;
    __nv_bfloat16 *ahi,*alo;
    cudaGetSymbolAddress((void**)&y1, g_y1);
    cudaGetSymbolAddress((void**)&u1, g_u1);
    cudaGetSymbolAddress((void**)&v1, g_v1);
    cudaGetSymbolAddress((void**)&h1, g_h1);
    cudaGetSymbolAddress((void**)&w1, g_w1);
    cudaGetSymbolAddress((void**)&u2, g_u2);
    cudaGetSymbolAddress((void**)&v2, g_v2);
    cudaGetSymbolAddress((void**)&h2, g_h2);
    cudaGetSymbolAddress((void**)&w2, g_w2);
    cudaGetSymbolAddress((void**)&gmax, g_gmax);
    cudaGetSymbolAddress((void**)&ps, g_psum);
    cudaGetSymbolAddress((void**)&pq, g_psq);
    cudaGetSymbolAddress((void**)&sc, g_scale);
    cudaGetSymbolAddress((void**)&sh, g_shift);
    cudaGetSymbolAddress((void**)&t_b1c1, g_wt_b1c1);
    cudaGetSymbolAddress((void**)&t_b1ds, g_wt_b1ds);
    cudaGetSymbolAddress((void**)&t_b1c3, g_wt_b1c3);
    cudaGetSymbolAddress((void**)&whex_hi, g_whex_hi);
    cudaGetSymbolAddress((void**)&whex_lo, g_whex_lo);
    cudaGetSymbolAddress((void**)&wb1h_hi, g_wb1h_hi);
    cudaGetSymbolAddress((void**)&wb1h_lo, g_wb1h_lo);
    cudaGetSymbolAddress((void**)&went_hi, g_went_hi);
    cudaGetSymbolAddress((void**)&went_lo, g_went_lo);
    cudaGetSymbolAddress((void**)&wc3_hi, g_wc3_hi);
    cudaGetSymbolAddress((void**)&wc3_lo, g_wc3_lo);
    cudaGetSymbolAddress((void**)&ahi, g_abf_hi);
    cudaGetSymbolAddress((void**)&alo, g_abf_lo);

    // input index tables (runtime disambiguation of metadata order)
    int I_b1c1, I_b1hex, I_b1c3, I_b1ds;
    int I_b1ga, I_b1ba, I_b1gb, I_b1bb, I_b1gc, I_b1bc, I_b1gd, I_b1bd;
    int I_b2c1, I_b2hex, I_b2c3, I_b2ds;
    int I_b2ga, I_b2ba, I_b2gb, I_b2bb, I_b2gc, I_b2bc, I_b2gd, I_b2bd;
    int I_fcw, I_fcb;
    if (in_sizes[5] == 36864) {
        I_b1c1 = 4;  I_b1hex = 5;  I_b1c3 = 6;  I_b1ds = 7;
        I_b1ga = 8;  I_b1ba = 9;  I_b1gb = 10; I_b1bb = 11;
        I_b1gc = 12; I_b1bc = 13; I_b1gd = 14; I_b1bd = 15;
        I_b2c1 = 16; I_b2hex = 17; I_b2c3 = 18; I_b2ds = 19;
        I_b2ga = 20; I_b2ba = 21; I_b2gb = 22; I_b2bb = 23;
        I_b2gc = 24; I_b2bc = 25; I_b2gd = 26; I_b2bd = 27;
        I_fcw = 28;  I_fcb = 29;
    } else {
        I_b1c1 = 4;  I_b1ga = 5;  I_b1ba = 6;  I_b1hex = 7;
        I_b1gb = 8;  I_b1bb = 9;  I_b1c3 = 10; I_b1gc = 11; I_b1bc = 12;
        I_b1ds = 13; I_b1gd = 14; I_b1bd = 15;
        I_b2c1 = 16; I_b2ga = 17; I_b2ba = 18; I_b2hex = 19;
        I_b2gb = 20; I_b2bb = 21; I_b2c3 = 22; I_b2gc = 23; I_b2bc = 24;
        I_b2ds = 25; I_b2gd = 26; I_b2bd = 27;
        I_fcw = 28;  I_fcb = 29;
    }

    // set smem limits for mma instantiations
    cudaFuncSetAttribute(mma_conv_k<512, 64, 7, false, 8, 16, NP1, 64, 64, 64>,
                         cudaFuncAttributeMaxDynamicSharedMemorySize, SM64);
    cudaFuncSetAttribute(mma_conv_k<64, 128, 1, true, 8, 16, NP2, 512, 256, 64>,
                         cudaFuncAttributeMaxDynamicSharedMemorySize, SM128);
    cudaFuncSetAttribute(mma_conv_k<2048, 128, 7, false, 4, 8, NP2, 256, 256, 256>,
                         cudaFuncAttributeMaxDynamicSharedMemorySize, SM128);
    cudaFuncSetAttribute(mma_conv_k<256, 128, 1, false, 4, 8, NP2, 256, 256, 256>,
                         cudaFuncAttributeMaxDynamicSharedMemorySize, SM128);

    // weight prep
    transpose_k<<<4,   256>>>((const float*)d_in[I_b1c1], t_b1c1, 64, 16);
    transpose_k<<<4,   256>>>((const float*)d_in[I_b1ds], t_b1ds, 64, 16);
    transpose_k<<<16,  256>>>((const float*)d_in[I_b1c3], t_b1c3, 64, 64);
    hexsplit_k<<<2048, 256>>>((const float*)d_in[I_b2hex], whex_hi, whex_lo, 256, 256);
    hexsplit_k<<<128,  256>>>((const float*)d_in[I_b1hex], wb1h_hi, wb1h_lo, 64, 64);
    split1x1_k<<<64,  256>>>((const float*)d_in[I_b2c1], went_hi, went_lo, 256, 64, 0);
    split1x1_k<<<64,  256>>>((const float*)d_in[I_b2ds], went_hi, went_lo, 256, 64, 256);
    split1x1_k<<<256, 256>>>((const float*)d_in[I_b2c3], wc3_hi, wc3_lo, 256, 256, 0);

    // stem + bn1 fold
    stem_kernel<<<NP0 / 256, 256>>>(x, (const float*)d_in[1], y1, ps, pq);
    bn_param<<<16, 256>>>(ps, pq, NP0 / 256, 16, 0, 1.f / NP0,
                          (const float*)d_in[2], (const float*)d_in[3], sc + 0, sh + 0);

    // block1 entry (SIMT)
    entry_kernel<16, 64, 16, 32, false><<<NP1 / 16, 256>>>(
        y1, nullptr, t_b1c1, t_b1ds, sc + 0, sh + 0, nullptr, nullptr, u1, v1, ps, pq);
    bn_param<<<64, 256>>>(ps, pq, NP1 / 16, 128, 0,  1.f / NP1,
                          (const float*)d_in[I_b1ga], (const float*)d_in[I_b1ba], sc + 16,  sh + 16);
    bn_param<<<64, 256>>>(ps, pq, NP1 / 16, 128, 64, 1.f / NP1,
                          (const float*)d_in[I_b1gd], (const float*)d_in[I_b1bd], sc + 208, sh + 208);

    // block1 hexconv (mma)
    actsplitT_k<<<dim3(NP1 / 32, 2), 256>>>(u1, sc + 16, sh + 16, ahi, alo, NP1, 64);
    mma_conv_k<512, 64, 7, false, 8, 16, NP1, 64, 64, 64>
        <<<dim3(NP1 / 128, 1), 256, SM64>>>(ahi, alo, wb1h_hi, wb1h_lo, h1, nullptr, ps, pq);
    bn_param<<<64, 256>>>(ps, pq, NP1 / 128, 64, 0, 1.f / NP1,
                          (const float*)d_in[I_b1gb], (const float*)d_in[I_b1bb], sc + 80, sh + 80);

    // block1 conv3 1x1 (SIMT)
    gemm_conv<64, 64, 8, 16, 1, 32><<<dim3(NP1 / 64, 1), 256>>>(
        h1, t_b1c3, sc + 80, sh + 80, w1, ps, pq);
    bn_param<<<64, 256>>>(ps, pq, NP1 / 64, 64, 0, 1.f / NP1,
                          (const float*)d_in[I_b1gc], (const float*)d_in[I_b1bc], sc + 144, sh + 144);

    // block2 entry (mma, dual input, pooled, N=512 = main||ds)
    actsplit2T_k<<<dim3(NP1 / 32, 2), 256>>>(w1, v1, sc + 144, sh + 144,
                                             sc + 208, sh + 208, ahi, alo, NP1, 64);
    mma_conv_k<64, 128, 1, true, 8, 16, NP2, 512, 256, 64>
        <<<dim3(NP1 / 128, 4), 256, SM128>>>(ahi, alo, went_hi, went_lo, u2, v2, ps, pq);
    bn_param<<<256, 256>>>(ps, pq, NP1 / 128, 512, 0,   1.f / NP2,
                           (const float*)d_in[I_b2ga], (const float*)d_in[I_b2ba], sc + 272,  sh + 272);
    bn_param<<<256, 256>>>(ps, pq, NP1 / 128, 512, 256, 1.f / NP2,
                           (const float*)d_in[I_b2gd], (const float*)d_in[I_b2bd], sc + 1040, sh + 1040);

    // block2 hexconv (mma)
    actsplitT_k<<<dim3(NP2 / 32, 8), 256>>>(u2, sc + 272, sh + 272, ahi, alo, NP2, 256);
    mma_conv_k<2048, 128, 7, false, 4, 8, NP2, 256, 256, 256>
        <<<dim3(NP2 / 128, 2), 256, SM128>>>(ahi, alo, whex_hi, whex_lo, h2, nullptr, ps, pq);
    bn_param<<<256, 256>>>(ps, pq, NP2 / 128, 256, 0, 1.f / NP2,
                           (const float*)d_in[I_b2gb], (const float*)d_in[I_b2bb], sc + 528, sh + 528);

    // block2 conv3 1x1 (mma)
    actsplitT_k<<<dim3(NP2 / 32, 8), 256>>>(h2, sc + 528, sh + 528, ahi, alo, NP2, 256);
    mma_conv_k<256, 128, 1, false, 4, 8, NP2, 256, 256, 256>
        <<<dim3(NP2 / 128, 2), 256, SM128>>>(ahi, alo, wc3_hi, wc3_lo, w2, nullptr, ps, pq);
    bn_param<<<256, 256>>>(ps, pq, NP2 / 128, 256, 0, 1.f / NP2,
                           (const float*)d_in[I_b2gc], (const float*)d_in[I_b2bc], sc + 784, sh + 784);

    // tail
    maxfin_k<<<256, 256>>>(w2, v2, sc + 784, sh + 784, sc + 1040, sh + 1040, gmax);
    fc_k<<<256, 256>>>(gmax, (const float*)d_in[I_fcw], (const float*)d_in[I_fcb], (float*)d_out);
}

// round 12
// speedup vs baseline: 1.9727x; 1.0401x over previous
#include <cuda_runtime.h>
#include <cuda_bf16.h>
#include <cstdint>

// Geometry:
//  stage0 in : [5][256][3][16][32]
//  stem out  : 16ch @16x32, NP0 = 5*256*512 = 655360
//  block1    : 64ch @8x16,  NP1 = 5*256*128 = 163840
//  block2    : 256ch@4x8,   NP2 = 5*256*32  = 40960
// fp32 activations: chan-major t[c*NP + pos]; bf16 planes: position-major [pos][C]

#define NP0 655360
#define NP1 163840
#define NP2 40960

// ------------------------- device scratch ----------------------------------
__device__ float g_u1[64 * NP1];
__device__ float g_v1[64 * NP1];
__device__ float g_h1[64 * NP1];
__device__ float g_w1[64 * NP1];
__device__ float g_u2[256 * NP2];
__device__ float g_v2[256 * NP2];
__device__ float g_h2[256 * NP2];
__device__ float g_w2[256 * NP2];
__device__ float g_gmax[256 * 256];

__device__ float g_psum[1310720];
__device__ float g_psq [1310720];

__device__ float g_scale[1296];
__device__ float g_shift[1296];

// split bf16 weights (hex: k = chunk*64 + t*8 + cl, tap7 = 0)
__device__ __nv_bfloat16 g_whex_hi[256 * 2048];
__device__ __nv_bfloat16 g_whex_lo[256 * 2048];
__device__ __nv_bfloat16 g_wb1h_hi[64 * 512];
__device__ __nv_bfloat16 g_wb1h_lo[64 * 512];
__device__ __nv_bfloat16 g_went_hi[512 * 64];
__device__ __nv_bfloat16 g_went_lo[512 * 64];
__device__ __nv_bfloat16 g_wc3_hi [256 * 256];
__device__ __nv_bfloat16 g_wc3_lo [256 * 256];
__device__ __nv_bfloat16 g_wb1c3_hi[64 * 64];
__device__ __nv_bfloat16 g_wb1c3_lo[64 * 64];
// block1 entry: folded (bn1-scaled) weights [128 o][16 c] + bias
__device__ __nv_bfloat16 g_went2_hi[128 * 16];
__device__ __nv_bfloat16 g_went2_lo[128 * 16];
__device__ float g_bias2[128];

// split bf16 activation planes, position-major [pos][C] (reused sequentially)
__device__ __nv_bfloat16 g_abf_hi[10485760];
__device__ __nv_bfloat16 g_abf_lo[10485760];

// ------------------------- mma helpers -------------------------------------
__device__ __forceinline__ uint32_t smem_u32(const void* p) {
    uint32_t a;
    asm("{ .reg .u64 t; cvta.to.shared.u64 t, %1; cvt.u32.u64 %0, t; }"
        : "=r"(a) : "l"(p));
    return a;
}
__device__ __forceinline__ void ldmA(uint32_t* a, uint32_t addr) {
    asm volatile("ldmatrix.sync.aligned.m8n8.x4.shared.b16 {%0,%1,%2,%3}, [%4];"
        : "=r"(a[0]), "=r"(a[1]), "=r"(a[2]), "=r"(a[3]) : "r"(addr));
}
__device__ __forceinline__ void ldmB(uint32_t* b, uint32_t addr) {
    asm volatile("ldmatrix.sync.aligned.m8n8.x2.shared.b16 {%0,%1}, [%2];"
        : "=r"(b[0]), "=r"(b[1]) : "r"(addr));
}
__device__ __forceinline__ void mma16816(float* d, const uint32_t* a, const uint32_t* b) {
    asm volatile(
        "mma.sync.aligned.m16n8k16.row.col.f32.bf16.bf16.f32 "
        "{%0,%1,%2,%3}, {%4,%5,%6,%7}, {%8,%9}, {%0,%1,%2,%3};"
        : "+f"(d[0]), "+f"(d[1]), "+f"(d[2]), "+f"(d[3])
        : "r"(a[0]), "r"(a[1]), "r"(a[2]), "r"(a[3]), "r"(b[0]), "r"(b[1]));
}

// ------------------------- prep kernels ------------------------------------
// [O][C][3][3] fp32 -> split bf16 [o][(c/8)*64 + t*8 + (c%8)] (tap7 zero)
__global__ void hexsplit_k(const float* __restrict__ src,
                           __nv_bfloat16* __restrict__ hi, __nv_bfloat16* __restrict__ lo,
                           int O, int C) {
    int i = blockIdx.x * 256 + threadIdx.x;
    if (i < O * C * 8) {
        int t = i & 7;
        int c = (i >> 3) % C;
        int o = i / (8 * C);
        float w = (t < 7) ? src[(o * C + c) * 9 + t + 1] : 0.f;
        __nv_bfloat16 h = __float2bfloat16(w);
        int k = (c >> 3) * 64 + t * 8 + (c & 7);
        hi[(size_t)o * (C * 8) + k] = h;
        lo[(size_t)o * (C * 8) + k] = __float2bfloat16(w - __bfloat162float(h));
    }
}

// [O][C] fp32 -> split bf16 rows at rowoff (row stride C)
__global__ void split1x1_k(const float* __restrict__ src,
                           __nv_bfloat16* __restrict__ hi, __nv_bfloat16* __restrict__ lo,
                           int O, int C, int rowoff) {
    int i = blockIdx.x * 256 + threadIdx.x;
    if (i < O * C) {
        float w = src[i];
        __nv_bfloat16 h = __float2bfloat16(w);
        int o = i / C, c = i % C;
        hi[(rowoff + o) * C + c] = h;
        lo[(rowoff + o) * C + c] = __float2bfloat16(w - __bfloat162float(h));
    }
}

// fold bn1 affine into block1-entry weights: w' = w*s_c, bias = sum w*t_c
__global__ void foldentry_k(const float* __restrict__ c1w, const float* __restrict__ dsw,
                            const float* __restrict__ sc0, const float* __restrict__ sh0,
                            __nv_bfloat16* __restrict__ hi, __nv_bfloat16* __restrict__ lo,
                            float* __restrict__ bias) {
    int o = threadIdx.x;  // 128
    const float* src = (o < 64) ? (c1w + o * 16) : (dsw + (o - 64) * 16);
    float b = 0.f;
    for (int c = 0; c < 16; c++) {
        float w = src[c] * sc0[c];
        b += src[c] * sh0[c];
        __nv_bfloat16 h = __float2bfloat16(w);
        hi[o * 16 + c] = h;
        lo[o * 16 + c] = __float2bfloat16(w - __bfloat162float(h));
    }
    bias[o] = b;
}

// relu(sc*x+sh), chan-major fp32 -> position-major bf16 hi/lo [q][C]
__global__ __launch_bounds__(256) void actsplitT_k(
    const float* __restrict__ x, const float* __restrict__ sc,
    const float* __restrict__ sh,
    __nv_bfloat16* __restrict__ hi, __nv_bfloat16* __restrict__ lo, int NP, int C) {
    __shared__ float tile[32][33];
    int q0 = blockIdx.x * 32, c0 = blockIdx.y * 32;
    int tq = threadIdx.x & 31, tc = threadIdx.x >> 5;
#pragma unroll
    for (int i = 0; i < 4; i++) {
        int c = c0 + tc + i * 8;
        tile[tc + i * 8][tq] = fmaxf(sc[c] * x[(size_t)c * NP + q0 + tq] + sh[c], 0.f);
    }
    __syncthreads();
    int tcw = threadIdx.x & 31, tqw = threadIdx.x >> 5;
#pragma unroll
    for (int i = 0; i < 4; i++) {
        float v = tile[tcw][tqw + i * 8];
        __nv_bfloat16 h = __float2bfloat16(v);
        size_t idx = (size_t)(q0 + tqw + i * 8) * C + c0 + tcw;
        hi[idx] = h;
        lo[idx] = __float2bfloat16(v - __bfloat162float(h));
    }
}

// relu(s1*a+t1 + s2*b+t2) -> position-major bf16
__global__ __launch_bounds__(256) void actsplit2T_k(
    const float* __restrict__ xa, const float* __restrict__ xb,
    const float* __restrict__ s1, const float* __restrict__ t1,
    const float* __restrict__ s2, const float* __restrict__ t2,
    __nv_bfloat16* __restrict__ hi, __nv_bfloat16* __restrict__ lo, int NP, int C) {
    __shared__ float tile[32][33];
    int q0 = blockIdx.x * 32, c0 = blockIdx.y * 32;
    int tq = threadIdx.x & 31, tc = threadIdx.x >> 5;
#pragma unroll
    for (int i = 0; i < 4; i++) {
        int c = c0 + tc + i * 8;
        size_t gi = (size_t)c * NP + q0 + tq;
        tile[tc + i * 8][tq] =
            fmaxf(s1[c] * xa[gi] + t1[c] + s2[c] * xb[gi] + t2[c], 0.f);
    }
    __syncthreads();
    int tcw = threadIdx.x & 31, tqw = threadIdx.x >> 5;
#pragma unroll
    for (int i = 0; i < 4; i++) {
        float v = tile[tcw][tqw + i * 8];
        __nv_bfloat16 h = __float2bfloat16(v);
        size_t idx = (size_t)(q0 + tqw + i * 8) * C + c0 + tcw;
        hi[idx] = h;
        lo[idx] = __float2bfloat16(v - __bfloat162float(h));
    }
}

// ------------------------- stem: hexconv -> relu -> bf16 planes -------------
__global__ __launch_bounds__(256) void stem_kernel(
    const float* __restrict__ x, const float* __restrict__ wc,
    __nv_bfloat16* __restrict__ ahi, __nv_bfloat16* __restrict__ alo,
    float* __restrict__ psum, float* __restrict__ psq) {
    __shared__ float wsh[432];
    __shared__ float wpS[16][8], wpQ[16][8];
    int tid = threadIdx.x;
    for (int e = tid; e < 432; e += 256) wsh[e] = wc[e];
    __syncthreads();

    int pos = blockIdx.x * 256 + tid;
    int w = pos & 31, h = (pos >> 5) & 15, b = (pos >> 9) & 255, f = pos >> 17;

    float acc[16];
#pragma unroll
    for (int o = 0; o < 16; o++) acc[o] = 0.f;

#pragma unroll
    for (int t = 0; t < 7; t++) {
        int kf = t + 1;
        int dy = kf / 3 - 1, dx = kf % 3 - 1;
        int hh = h + dy;
        float xv0 = 0.f, xv1 = 0.f, xv2 = 0.f;
        if (hh >= 0 && hh < 16) {
            int ww = w + dx, ff = f;
            if (ww < 0)       { ff = (f + 4) % 5; ww = 31; }
            else if (ww > 31) { ff = (f + 1) % 5; ww = 0;  }
            int base = (ff * 256 + b) * 1536 + hh * 32 + ww;
            xv0 = x[base];
            xv1 = x[base + 512];
            xv2 = x[base + 1024];
        }
#pragma unroll
        for (int o = 0; o < 16; o++) {
            acc[o] += wsh[(o * 3 + 0) * 9 + kf] * xv0
                    + wsh[(o * 3 + 1) * 9 + kf] * xv1
                    + wsh[(o * 3 + 2) * 9 + kf] * xv2;
        }
    }

    __align__(16) __nv_bfloat16 h16[16];
    __align__(16) __nv_bfloat16 l16[16];
    int lane = tid & 31, warp = tid >> 5;
#pragma unroll
    for (int o = 0; o < 16; o++) {
        float val = fmaxf(acc[o], 0.f);
        __nv_bfloat16 hb = __float2bfloat16(val);
        h16[o] = hb;
        l16[o] = __float2bfloat16(val - __bfloat162float(hb));
        float s = val, q2 = val * val;
#pragma unroll
        for (int d = 16; d; d >>= 1) {
            s  += __shfl_xor_sync(0xFFFFFFFFu, s,  d);
            q2 += __shfl_xor_sync(0xFFFFFFFFu, q2, d);
        }
        if (lane == 0) { wpS[o][warp] = s; wpQ[o][warp] = q2; }
    }
    *(uint4*)(ahi + (size_t)pos * 16)     = *(uint4*)h16;
    *(uint4*)(ahi + (size_t)pos * 16 + 8) = *(uint4*)(h16 + 8);
    *(uint4*)(alo + (size_t)pos * 16)     = *(uint4*)l16;
    *(uint4*)(alo + (size_t)pos * 16 + 8) = *(uint4*)(l16 + 8);

    __syncthreads();
    if (tid < 16) {
        float s = 0.f, q = 0.f;
#pragma unroll
        for (int wpi = 0; wpi < 8; wpi++) { s += wpS[tid][wpi]; q += wpQ[tid][wpi]; }
        psum[blockIdx.x * 16 + tid] = s;
        psq [blockIdx.x * 16 + tid] = q;
    }
}

// ------------------------- BN param fold ------------------------------------
__global__ void bn_param(const float* __restrict__ ps, const float* __restrict__ pq,
                         int nparts, int cstride, int coff, float invN,
                         const float* __restrict__ g, const float* __restrict__ b,
                         float* __restrict__ sc, float* __restrict__ sh) {
    int c = blockIdx.x, tid = threadIdx.x;
    float s = 0.f, q = 0.f;
    for (int p = tid; p < nparts; p += 256) {
        s += ps[(size_t)p * cstride + coff + c];
        q += pq[(size_t)p * cstride + coff + c];
    }
    __shared__ float rs[256], rq[256];
    rs[tid] = s; rq[tid] = q;
    __syncthreads();
    for (int d = 128; d; d >>= 1) {
        if (tid < d) { rs[tid] += rs[tid + d]; rq[tid] += rq[tid + d]; }
        __syncthreads();
    }
    if (tid == 0) {
        float mean = rs[0] * invN;
        float var  = rq[0] * invN - mean * mean;
        float k = g[c] * rsqrtf(var + 1e-5f);
        sc[c] = k;
        sh[c] = b[c] - mean * k;
    }
}

// ---------------- generic mma.sync split-bf16 conv/GEMM ---------------------
// D[m=128, o=NTILE] = A[m, k] * W[o, k]; A from position-major bf16 planes [pos][CDIM].
// TAPS=7: k = chunk*64 + t*8 + cl; TAPS=1: k = c. KCH = min(KTOT,64).
// POOL: rows are 4 pool candidates per output; epilogue maxes them; bias optional.
template <int KTOT, int NTILE, int TAPS, bool POOL, int HIN, int WIN,
          int NPOUT, int NSTR, int OSPLIT, int CDIM>
__global__ __launch_bounds__(256) void mma_conv_k(
    const __nv_bfloat16* __restrict__ ahi, const __nv_bfloat16* __restrict__ alo,
    const __nv_bfloat16* __restrict__ whi, const __nv_bfloat16* __restrict__ wlo,
    const float* __restrict__ bias,
    float* __restrict__ outU, float* __restrict__ outV,
    float* __restrict__ psum, float* __restrict__ psq) {
    constexpr int NT = NTILE / 8;
    constexpr int KCH = (KTOT < 64) ? KTOT : 64;
    constexpr int NCHUNK = KTOT / KCH;
    constexpr int LDAv = KCH + 8;
    constexpr int GPR = KCH / 8;
    constexpr int KS = KCH / 16;
    constexpr int AITERS = (128 * GPR) / 256;
    constexpr int BITERS = (NTILE * GPR + 255) / 256;
    constexpr int OF_AH = 3584;
    constexpr int OF_AL = OF_AH + 128 * LDAv * 2;
    constexpr int OF_BH = OF_AL + 128 * LDAv * 2;
    constexpr int OF_BL = OF_BH + NTILE * LDAv * 2;
    constexpr int OF_PS = OF_BL + NTILE * LDAv * 2;
    constexpr int OF_PQ = OF_PS + NTILE * 32;

    extern __shared__ __align__(16) char smem[];
    uint32_t sb = smem_u32(smem);
    int tid = threadIdx.x;
    int wid = tid >> 5, lane = tid & 31;
    int q0 = blockIdx.x * 128;
    int o0 = blockIdx.y * NTILE;

    int* nbr = (int*)(smem);
    for (int e = tid; e < TAPS * 128; e += 256) {
        int t = e >> 7, ql = e & 127;
        int m = q0 + ql;
        int pos;
        if (POOL) {
            constexpr int WO = WIN / 2, HO = HIN / 2;
            int qq = m >> 2, sub = m & 3;
            int w = qq % WO;
            int h = (qq / WO) % HO;
            int fb = qq / (WO * HO);
            pos = (fb * HIN + 2 * h + (sub >> 1)) * WIN + 2 * w + (sub & 1);
        } else if (TAPS == 1) {
            pos = m;
        } else {
            int w = m % WIN;
            int h = (m / WIN) % HIN;
            int b = (m / (WIN * HIN)) & 255;
            int f = m / (WIN * HIN * 256);
            int kf = t + 1;
            int dy = kf / 3 - 1, dx = kf % 3 - 1;
            int hh = h + dy, ww = w + dx, ff = f;
            if (hh < 0 || hh >= HIN) pos = -1;
            else {
                if (ww < 0)        { ff = (f + 4) % 5; ww = WIN - 1; }
                else if (ww >= WIN){ ff = (f + 1) % 5; ww = 0;       }
                pos = ((ff * 256 + b) * HIN + hh) * WIN + ww;
            }
        }
        nbr[t * 128 + ql] = pos;
    }
    __syncthreads();

    float acc[NT][4];
#pragma unroll
    for (int nt = 0; nt < NT; nt++)
#pragma unroll
        for (int j = 0; j < 4; j++) acc[nt][j] = 0.f;

    int m0 = wid * 16;
    int grp = lane >> 3;
    int rowA = m0 + (lane & 7) + (grp & 1) * 8;
    int colA8 = (grp >> 1) * 8;
    uint32_t aBaseH = sb + OF_AH + (uint32_t)(rowA * LDAv + colA8) * 2;
    uint32_t aBaseL = sb + OF_AL + (uint32_t)(rowA * LDAv + colA8) * 2;
    int rowB = (lane & 7);
    int colB8 = ((lane >> 3) & 1) * 8;
    uint32_t bBaseH = sb + OF_BH + (uint32_t)(rowB * LDAv + colB8) * 2;
    uint32_t bBaseL = sb + OF_BL + (uint32_t)(rowB * LDAv + colB8) * 2;

    __nv_bfloat16* AH = (__nv_bfloat16*)(smem + OF_AH);
    __nv_bfloat16* AL = (__nv_bfloat16*)(smem + OF_AL);
    __nv_bfloat16* BH = (__nv_bfloat16*)(smem + OF_BH);
    __nv_bfloat16* BL = (__nv_bfloat16*)(smem + OF_BL);

#pragma unroll 1
    for (int ci = 0; ci < NCHUNK; ci++) {
        // stage A: [128 m][KCH k], vectorized uint4 (8 bf16 per op)
#pragma unroll
        for (int it = 0; it < AITERS; it++) {
            int e = it * 256 + tid;
            int q = e / GPR, g = e % GPR;
            uint4 vh = {0u, 0u, 0u, 0u}, vl = {0u, 0u, 0u, 0u};
            if (TAPS == 7) {
                if (g < 7) {
                    int pos = nbr[g * 128 + q];
                    if (pos >= 0) {
                        size_t base = (size_t)pos * CDIM + ci * 8;
                        vh = *(const uint4*)(ahi + base);
                        vl = *(const uint4*)(alo + base);
                    }
                }
            } else {
                int pos = nbr[q];
                size_t base = (size_t)pos * CDIM + ci * KCH + g * 8;
                vh = *(const uint4*)(ahi + base);
                vl = *(const uint4*)(alo + base);
            }
            *(uint4*)(AH + q * LDAv + g * 8) = vh;
            *(uint4*)(AL + q * LDAv + g * 8) = vl;
        }
        // stage B: [NTILE o][KCH k]
#pragma unroll
        for (int it = 0; it < BITERS; it++) {
            int e = it * 256 + tid;
            if (e < NTILE * GPR) {
                int o = e / GPR, j = e % GPR;
                size_t src = (size_t)(o0 + o) * KTOT + ci * KCH + j * 8;
                *(uint4*)(BH + o * LDAv + j * 8) = *(const uint4*)(whi + src);
                *(uint4*)(BL + o * LDAv + j * 8) = *(const uint4*)(wlo + src);
            }
        }
        __syncthreads();

#pragma unroll
        for (int ks = 0; ks < KS; ks++) {
            uint32_t aH[4], aL[4];
            ldmA(aH, aBaseH + ks * 32);
            ldmA(aL, aBaseL + ks * 32);
#pragma unroll
            for (int nt = 0; nt < NT; nt++) {
                uint32_t bH[2], bL[2];
                uint32_t boff = (uint32_t)(nt * 8 * LDAv) * 2 + ks * 32;
                ldmB(bH, bBaseH + boff);
                ldmB(bL, bBaseL + boff);
                mma16816(acc[nt], aH, bH);
                mma16816(acc[nt], aL, bH);
                mma16816(acc[nt], aH, bL);
            }
        }
        __syncthreads();
    }

    float* pS = (float*)(smem + OF_PS);
    float* pQ = (float*)(smem + OF_PQ);

    if (!POOL) {
        int r = lane >> 2;
        int cp = (lane & 3) << 1;
#pragma unroll
        for (int nt = 0; nt < NT; nt++) {
            int c0c = nt * 8 + cp;
            int qrow = q0 + m0 + r;
            int oc0 = o0 + c0c;
            float* d0 = (oc0 < OSPLIT) ? (outU + (size_t)oc0 * NPOUT)
                                       : (outV + (size_t)(oc0 - OSPLIT) * NPOUT);
            float* d1 = (oc0 + 1 < OSPLIT) ? (outU + (size_t)(oc0 + 1) * NPOUT)
                                           : (outV + (size_t)(oc0 + 1 - OSPLIT) * NPOUT);
            d0[qrow]     = acc[nt][0];
            d1[qrow]     = acc[nt][1];
            d0[qrow + 8] = acc[nt][2];
            d1[qrow + 8] = acc[nt][3];
            float s0 = acc[nt][0] + acc[nt][2];
            float s1 = acc[nt][1] + acc[nt][3];
            float t0 = acc[nt][0]*acc[nt][0] + acc[nt][2]*acc[nt][2];
            float t1 = acc[nt][1]*acc[nt][1] + acc[nt][3]*acc[nt][3];
#pragma unroll
            for (int d = 4; d <= 16; d <<= 1) {
                s0 += __shfl_xor_sync(0xFFFFFFFFu, s0, d);
                s1 += __shfl_xor_sync(0xFFFFFFFFu, s1, d);
                t0 += __shfl_xor_sync(0xFFFFFFFFu, t0, d);
                t1 += __shfl_xor_sync(0xFFFFFFFFu, t1, d);
            }
            if (r == 0) {
                pS[wid * NTILE + c0c]     = s0;
                pS[wid * NTILE + c0c + 1] = s1;
                pQ[wid * NTILE + c0c]     = t0;
                pQ[wid * NTILE + c0c + 1] = t1;
            }
        }
    } else {
        int cp = (lane & 3) << 1;
        bool writer = ((lane >> 2) & 3) == 0;
        int gsel = lane >> 4;
        int qout0 = blockIdx.x * 32 + wid * 4;
#pragma unroll
        for (int nt = 0; nt < NT; nt++) {
            float v0 = acc[nt][0], v1 = acc[nt][1];
            float v2 = acc[nt][2], v3 = acc[nt][3];
            if (bias) {
                float b0 = bias[o0 + nt * 8 + cp];
                float b1v = bias[o0 + nt * 8 + cp + 1];
                v0 += b0; v2 += b0; v1 += b1v; v3 += b1v;
            }
#pragma unroll
            for (int d = 4; d <= 8; d <<= 1) {
                v0 = fmaxf(v0, __shfl_xor_sync(0xFFFFFFFFu, v0, d));
                v1 = fmaxf(v1, __shfl_xor_sync(0xFFFFFFFFu, v1, d));
                v2 = fmaxf(v2, __shfl_xor_sync(0xFFFFFFFFu, v2, d));
                v3 = fmaxf(v3, __shfl_xor_sync(0xFFFFFFFFu, v3, d));
            }
            if (writer) {
                int oc0 = o0 + nt * 8 + cp;
                float* d0 = (oc0 < OSPLIT) ? (outU + (size_t)oc0 * NPOUT)
                                           : (outV + (size_t)(oc0 - OSPLIT) * NPOUT);
                float* d1 = (oc0 + 1 < OSPLIT) ? (outU + (size_t)(oc0 + 1) * NPOUT)
                                               : (outV + (size_t)(oc0 + 1 - OSPLIT) * NPOUT);
                int qa = qout0 + gsel;
                int qb2 = qout0 + 2 + gsel;
                d0[qa]  = v0;
                d1[qa]  = v1;
                d0[qb2] = v2;
                d1[qb2] = v3;
            }
            float s0 = v0 + v2, s1 = v1 + v3;
            float t0 = v0 * v0 + v2 * v2, t1 = v1 * v1 + v3 * v3;
            s0 += __shfl_xor_sync(0xFFFFFFFFu, s0, 16);
            s1 += __shfl_xor_sync(0xFFFFFFFFu, s1, 16);
            t0 += __shfl_xor_sync(0xFFFFFFFFu, t0, 16);
            t1 += __shfl_xor_sync(0xFFFFFFFFu, t1, 16);
            if (lane < 4) {
                pS[wid * NTILE + nt * 8 + cp]     = s0;
                pS[wid * NTILE + nt * 8 + cp + 1] = s1;
                pQ[wid * NTILE + nt * 8 + cp]     = t0;
                pQ[wid * NTILE + nt * 8 + cp + 1] = t1;
            }
        }
    }
    __syncthreads();
    if (tid < NTILE) {
        float s = 0.f, q = 0.f;
#pragma unroll
        for (int w = 0; w < 8; w++) { s += pS[w * NTILE + tid]; q += pQ[w * NTILE + tid]; }
        psum[(size_t)blockIdx.x * NSTR + o0 + tid] = s;
        psq [(size_t)blockIdx.x * NSTR + o0 + tid] = q;
    }
}

// ------------- final: BN+add+relu, global max over charts+spatial -----------
__global__ __launch_bounds__(256) void maxfin_k(
    const float* __restrict__ w2, const float* __restrict__ v2,
    const float* __restrict__ scC, const float* __restrict__ shC,
    const float* __restrict__ scD, const float* __restrict__ shD,
    float* __restrict__ gmax) {
    int o = blockIdx.x, tid = threadIdx.x;
    __shared__ int mx[256];
    mx[tid] = 0;
    __syncthreads();
    float a = scC[o], c_ = shC[o], d = scD[o], e = shD[o];
    const float* wp = w2 + (size_t)o * NP2;
    const float* vp = v2 + (size_t)o * NP2;
    for (int i = tid; i < NP2; i += 256) {
        float val = fmaxf(a * wp[i] + c_ + d * vp[i] + e, 0.f);
#pragma unroll
        for (int s = 16; s; s >>= 1)
            val = fmaxf(val, __shfl_xor_sync(0xFFFFFFFFu, val, s));
        if ((tid & 31) == 0)
            atomicMax(&mx[(i >> 5) & 255], __float_as_int(val));
    }
    __syncthreads();
    gmax[tid * 256 + o] = __int_as_float(mx[tid]);
}

__global__ void fc_k(const float* __restrict__ gmax, const float* __restrict__ fw,
                     const float* __restrict__ fb, float* __restrict__ out) {
    int b = blockIdx.x, tid = threadIdx.x;
    __shared__ float m[256];
    m[tid] = gmax[b * 256 + tid];
    __syncthreads();
    if (tid < 10) {
        float acc = fb[tid];
        for (int o = 0; o < 256; o++) acc += m[o] * fw[tid * 256 + o];
        out[b * 10 + tid] = acc;
    }
}

// ------------------------- launch ------------------------------------------
#define SM128 85504
#define SM64  62976
#define SMK16 36352

extern "C" void kernel_launch(void* const* d_in, const int* in_sizes, int n_in,
                              void* d_out, int out_size) {
    (void)n_in; (void)out_size;

    const float* x = (const float*)d_in[0];

    float *u1,*v1,*h1,*w1,*u2,*v2,*h2,*w2,*gmax,*ps,*pq,*sc,*sh,*bias2;
    __nv_bfloat16 *whex_hi,*whex_lo,*wb1h_hi,*wb1h_lo,*went_hi,*went_lo;
    __nv_bfloat16 *wc3_hi,*wc3_lo,*wb1c3_hi,*wb1c3_lo,*went2_hi,*went2_lo;
    __nv_bfloat16 *ahi,*alo;
    cudaGetSymbolAddress((void**)&u1, g_u1);
    cudaGetSymbolAddress((void**)&v1, g_v1);
    cudaGetSymbolAddress((void**)&h1, g_h1);
    cudaGetSymbolAddress((void**)&w1, g_w1);
    cudaGetSymbolAddress((void**)&u2, g_u2);
    cudaGetSymbolAddress((void**)&v2, g_v2);
    cudaGetSymbolAddress((void**)&h2, g_h2);
    cudaGetSymbolAddress((void**)&w2, g_w2);
    cudaGetSymbolAddress((void**)&gmax, g_gmax);
    cudaGetSymbolAddress((void**)&ps, g_psum);
    cudaGetSymbolAddress((void**)&pq, g_psq);
    cudaGetSymbolAddress((void**)&sc, g_scale);
    cudaGetSymbolAddress((void**)&sh, g_shift);
    cudaGetSymbolAddress((void**)&bias2, g_bias2);
    cudaGetSymbolAddress((void**)&whex_hi, g_whex_hi);
    cudaGetSymbolAddress((void**)&whex_lo, g_whex_lo);
    cudaGetSymbolAddress((void**)&wb1h_hi, g_wb1h_hi);
    cudaGetSymbolAddress((void**)&wb1h_lo, g_wb1h_lo);
    cudaGetSymbolAddress((void**)&went_hi, g_went_hi);
    cudaGetSymbolAddress((void**)&went_lo, g_went_lo);
    cudaGetSymbolAddress((void**)&wc3_hi, g_wc3_hi);
    cudaGetSymbolAddress((void**)&wc3_lo, g_wc3_lo);
    cudaGetSymbolAddress((void**)&wb1c3_hi, g_wb1c3_hi);
    cudaGetSymbolAddress((void**)&wb1c3_lo, g_wb1c3_lo);
    cudaGetSymbolAddress((void**)&went2_hi, g_went2_hi);
    cudaGetSymbolAddress((void**)&went2_lo, g_went2_lo);
    cudaGetSymbolAddress((void**)&ahi, g_abf_hi);
    cudaGetSymbolAddress((void**)&alo, g_abf_lo);

    // input index tables (runtime disambiguation of metadata order)
    int I_b1c1, I_b1hex, I_b1c3, I_b1ds;
    int I_b1ga, I_b1ba, I_b1gb, I_b1bb, I_b1gc, I_b1bc, I_b1gd, I_b1bd;
    int I_b2c1, I_b2hex, I_b2c3, I_b2ds;
    int I_b2ga, I_b2ba, I_b2gb, I_b2bb, I_b2gc, I_b2bc, I_b2gd, I_b2bd;
    int I_fcw, I_fcb;
    if (in_sizes[5] == 36864) {
        I_b1c1 = 4;  I_b1hex = 5;  I_b1c3 = 6;  I_b1ds = 7;
        I_b1ga = 8;  I_b1ba = 9;  I_b1gb = 10; I_b1bb = 11;
        I_b1gc = 12; I_b1bc = 13; I_b1gd = 14; I_b1bd = 15;
        I_b2c1 = 16; I_b2hex = 17; I_b2c3 = 18; I_b2ds = 19;
        I_b2ga = 20; I_b2ba = 21; I_b2gb = 22; I_b2bb = 23;
        I_b2gc = 24; I_b2bc = 25; I_b2gd = 26; I_b2bd = 27;
        I_fcw = 28;  I_fcb = 29;
    } else {
        I_b1c1 = 4;  I_b1ga = 5;  I_b1ba = 6;  I_b1hex = 7;
        I_b1gb = 8;  I_b1bb = 9;  I_b1c3 = 10; I_b1gc = 11; I_b1bc = 12;
        I_b1ds = 13; I_b1gd = 14; I_b1bd = 15;
        I_b2c1 = 16; I_b2ga = 17; I_b2ba = 18; I_b2hex = 19;
        I_b2gb = 20; I_b2bb = 21; I_b2c3 = 22; I_b2gc = 23; I_b2bc = 24;
        I_b2ds = 25; I_b2gd = 26; I_b2bd = 27;
        I_fcw = 28;  I_fcb = 29;
    }

    // set smem limits for mma instantiations
    cudaFuncSetAttribute(mma_conv_k<16, 128, 1, true, 16, 32, NP1, 128, 64, 16>,
                         cudaFuncAttributeMaxDynamicSharedMemorySize, SMK16);
    cudaFuncSetAttribute(mma_conv_k<512, 64, 7, false, 8, 16, NP1, 64, 64, 64>,
                         cudaFuncAttributeMaxDynamicSharedMemorySize, SM64);
    cudaFuncSetAttribute(mma_conv_k<64, 64, 1, false, 8, 16, NP1, 64, 64, 64>,
                         cudaFuncAttributeMaxDynamicSharedMemorySize, SM64);
    cudaFuncSetAttribute(mma_conv_k<64, 128, 1, true, 8, 16, NP2, 512, 256, 64>,
                         cudaFuncAttributeMaxDynamicSharedMemorySize, SM128);
    cudaFuncSetAttribute(mma_conv_k<2048, 128, 7, false, 4, 8, NP2, 256, 256, 256>,
                         cudaFuncAttributeMaxDynamicSharedMemorySize, SM128);
    cudaFuncSetAttribute(mma_conv_k<256, 128, 1, false, 4, 8, NP2, 256, 256, 256>,
                         cudaFuncAttributeMaxDynamicSharedMemorySize, SM128);

    // weight prep
    hexsplit_k<<<2048, 256>>>((const float*)d_in[I_b2hex], whex_hi, whex_lo, 256, 256);
    hexsplit_k<<<128,  256>>>((const float*)d_in[I_b1hex], wb1h_hi, wb1h_lo, 64, 64);
    split1x1_k<<<64,  256>>>((const float*)d_in[I_b2c1], went_hi, went_lo, 256, 64, 0);
    split1x1_k<<<64,  256>>>((const float*)d_in[I_b2ds], went_hi, went_lo, 256, 64, 256);
    split1x1_k<<<256, 256>>>((const float*)d_in[I_b2c3], wc3_hi, wc3_lo, 256, 256, 0);
    split1x1_k<<<16,  256>>>((const float*)d_in[I_b1c3], wb1c3_hi, wb1c3_lo, 64, 64, 0);

    // stem: hexconv -> relu -> bf16 planes [pos][16] + bn1 stats
    stem_kernel<<<NP0 / 256, 256>>>(x, (const float*)d_in[1], ahi, alo, ps, pq);
    bn_param<<<16, 256>>>(ps, pq, NP0 / 256, 16, 0, 1.f / NP0,
                          (const float*)d_in[2], (const float*)d_in[3], sc + 0, sh + 0);
    foldentry_k<<<1, 128>>>((const float*)d_in[I_b1c1], (const float*)d_in[I_b1ds],
                            sc + 0, sh + 0, went2_hi, went2_lo, bias2);

    // block1 entry (mma, K=16, pooled, bias, N=128 = main||ds)
    mma_conv_k<16, 128, 1, true, 16, 32, NP1, 128, 64, 16>
        <<<dim3(NP0 / 128, 1), 256, SMK16>>>(ahi, alo, went2_hi, went2_lo, bias2,
                                             u1, v1, ps, pq);
    bn_param<<<64, 256>>>(ps, pq, NP0 / 128, 128, 0,  1.f / NP1,
                          (const float*)d_in[I_b1ga], (const float*)d_in[I_b1ba], sc + 16,  sh + 16);
    bn_param<<<64, 256>>>(ps, pq, NP0 / 128, 128, 64, 1.f / NP1,
                          (const float*)d_in[I_b1gd], (const float*)d_in[I_b1bd], sc + 208, sh + 208);

    // block1 hexconv (mma)
    actsplitT_k<<<dim3(NP1 / 32, 2), 256>>>(u1, sc + 16, sh + 16, ahi, alo, NP1, 64);
    mma_conv_k<512, 64, 7, false, 8, 16, NP1, 64, 64, 64>
        <<<dim3(NP1 / 128, 1), 256, SM64>>>(ahi, alo, wb1h_hi, wb1h_lo, nullptr,
                                            h1, nullptr, ps, pq);
    bn_param<<<64, 256>>>(ps, pq, NP1 / 128, 64, 0, 1.f / NP1,
                          (const float*)d_in[I_b1gb], (const float*)d_in[I_b1bb], sc + 80, sh + 80);

    // block1 conv3 1x1 (mma)
    actsplitT_k<<<dim3(NP1 / 32, 2), 256>>>(h1, sc + 80, sh + 80, ahi, alo, NP1, 64);
    mma_conv_k<64, 64, 1, false, 8, 16, NP1, 64, 64, 64>
        <<<dim3(NP1 / 128, 1), 256, SM64>>>(ahi, alo, wb1c3_hi, wb1c3_lo, nullptr,
                                            w1, nullptr, ps, pq);
    bn_param<<<64, 256>>>(ps, pq, NP1 / 128, 64, 0, 1.f / NP1,
                          (const float*)d_in[I_b1gc], (const float*)d_in[I_b1bc], sc + 144, sh + 144);

    // block2 entry (mma, dual input, pooled, N=512 = main||ds)
    actsplit2T_k<<<dim3(NP1 / 32, 2), 256>>>(w1, v1, sc + 144, sh + 144,
                                             sc + 208, sh + 208, ahi, alo, NP1, 64);
    mma_conv_k<64, 128, 1, true, 8, 16, NP2, 512, 256, 64>
        <<<dim3(NP1 / 128, 4), 256, SM128>>>(ahi, alo, went_hi, went_lo, nullptr,
                                             u2, v2, ps, pq);
    bn_param<<<256, 256>>>(ps, pq, NP1 / 128, 512, 0,   1.f / NP2,
                           (const float*)d_in[I_b2ga], (const float*)d_in[I_b2ba], sc + 272,  sh + 272);
    bn_param<<<256, 256>>>(ps, pq, NP1 / 128, 512, 256, 1.f / NP2,
                           (const float*)d_in[I_b2gd], (const float*)d_in[I_b2bd], sc + 1040, sh + 1040);

    // block2 hexconv (mma)
    actsplitT_k<<<dim3(NP2 / 32, 8), 256>>>(u2, sc + 272, sh + 272, ahi, alo, NP2, 256);
    mma_conv_k<2048, 128, 7, false, 4, 8, NP2, 256, 256, 256>
        <<<dim3(NP2 / 128, 2), 256, SM128>>>(ahi, alo, whex_hi, whex_lo, nullptr,
                                             h2, nullptr, ps, pq);
    bn_param<<<256, 256>>>(ps, pq, NP2 / 128, 256, 0, 1.f / NP2,
                           (const float*)d_in[I_b2gb], (const float*)d_in[I_b2bb], sc + 528, sh + 528);

    // block2 conv3 1x1 (mma)
    actsplitT_k<<<dim3(NP2 / 32, 8), 256>>>(h2, sc + 528, sh + 528, ahi, alo, NP2, 256);
    mma_conv_k<256, 128, 1, false, 4, 8, NP2, 256, 256, 256>
        <<<dim3(NP2 / 128, 2), 256, SM128>>>(ahi, alo, wc3_hi, wc3_lo, nullptr,
                                             w2, nullptr, ps, pq);
    bn_param<<<256, 256>>>(ps, pq, NP2 / 128, 256, 0, 1.f / NP2,
                           (const float*)d_in[I_b2gc], (const float*)d_in[I_b2bc], sc + 784, sh + 784);

    // tail
    maxfin_k<<<256, 256>>>(w2, v2, sc + 784, sh + 784, sc + 1040, sh + 1040, gmax);
    fc_k<<<256, 256>>>(gmax, (const float*)d_in[I_fcw], (const float*)d_in[I_fcb], (float*)d_out);
}

// round 13
// speedup vs baseline: 2.1487x; 1.0892x over previous
#include <cuda_runtime.h>
#include <cuda_bf16.h>
#include <cstdint>

// Geometry:
//  stage0 in : [5][256][3][16][32]
//  stem out  : 16ch @16x32, NP0 = 5*256*512 = 655360
//  block1    : 64ch @8x16,  NP1 = 5*256*128 = 163840
//  block2    : 256ch@4x8,   NP2 = 5*256*32  = 40960
// ALL activations position-major: fp32 t[pos*C + c]; bf16 planes [pos][C]

#define NP0 655360
#define NP1 163840
#define NP2 40960

// ------------------------- device scratch ----------------------------------
__device__ float g_u1[64 * NP1];
__device__ float g_v1[64 * NP1];
__device__ float g_h1[64 * NP1];
__device__ float g_w1[64 * NP1];
__device__ float g_u2[256 * NP2];
__device__ float g_v2[256 * NP2];
__device__ float g_h2[256 * NP2];
__device__ float g_w2[256 * NP2];
__device__ float g_gmax[256 * 256];

__device__ float g_psum[1310720];
__device__ float g_psq [1310720];

__device__ float g_scale[1296];
__device__ float g_shift[1296];

// split bf16 weights (hex: k = chunk*64 + t*8 + cl, tap7 = 0)
__device__ __nv_bfloat16 g_whex_hi[256 * 2048];
__device__ __nv_bfloat16 g_whex_lo[256 * 2048];
__device__ __nv_bfloat16 g_wb1h_hi[64 * 512];
__device__ __nv_bfloat16 g_wb1h_lo[64 * 512];
__device__ __nv_bfloat16 g_went_hi[512 * 64];
__device__ __nv_bfloat16 g_went_lo[512 * 64];
__device__ __nv_bfloat16 g_wc3_hi [256 * 256];
__device__ __nv_bfloat16 g_wc3_lo [256 * 256];
__device__ __nv_bfloat16 g_wb1c3_hi[64 * 64];
__device__ __nv_bfloat16 g_wb1c3_lo[64 * 64];
// block1 entry: folded (bn1-scaled) weights [128 o][16 c] + bias
__device__ __nv_bfloat16 g_went2_hi[128 * 16];
__device__ __nv_bfloat16 g_went2_lo[128 * 16];
__device__ float g_bias2[128];

// split bf16 activation planes, position-major [pos][C] (reused sequentially)
__device__ __nv_bfloat16 g_abf_hi[10485760];
__device__ __nv_bfloat16 g_abf_lo[10485760];

// ------------------------- mma helpers -------------------------------------
__device__ __forceinline__ uint32_t smem_u32(const void* p) {
    uint32_t a;
    asm("{ .reg .u64 t; cvta.to.shared.u64 t, %1; cvt.u32.u64 %0, t; }"
        : "=r"(a) : "l"(p));
    return a;
}
__device__ __forceinline__ void ldmA(uint32_t* a, uint32_t addr) {
    asm volatile("ldmatrix.sync.aligned.m8n8.x4.shared.b16 {%0,%1,%2,%3}, [%4];"
        : "=r"(a[0]), "=r"(a[1]), "=r"(a[2]), "=r"(a[3]) : "r"(addr));
}
__device__ __forceinline__ void ldmB(uint32_t* b, uint32_t addr) {
    asm volatile("ldmatrix.sync.aligned.m8n8.x2.shared.b16 {%0,%1}, [%2];"
        : "=r"(b[0]), "=r"(b[1]) : "r"(addr));
}
__device__ __forceinline__ void mma16816(float* d, const uint32_t* a, const uint32_t* b) {
    asm volatile(
        "mma.sync.aligned.m16n8k16.row.col.f32.bf16.bf16.f32 "
        "{%0,%1,%2,%3}, {%4,%5,%6,%7}, {%8,%9}, {%0,%1,%2,%3};"
        : "+f"(d[0]), "+f"(d[1]), "+f"(d[2]), "+f"(d[3])
        : "r"(a[0]), "r"(a[1]), "r"(a[2]), "r"(a[3]), "r"(b[0]), "r"(b[1]));
}

// ------------------------- prep kernels ------------------------------------
// [O][C][3][3] fp32 -> split bf16 [o][(c/8)*64 + t*8 + (c%8)] (tap7 zero)
__global__ void hexsplit_k(const float* __restrict__ src,
                           __nv_bfloat16* __restrict__ hi, __nv_bfloat16* __restrict__ lo,
                           int O, int C) {
    int i = blockIdx.x * 256 + threadIdx.x;
    if (i < O * C * 8) {
        int t = i & 7;
        int c = (i >> 3) % C;
        int o = i / (8 * C);
        float w = (t < 7) ? src[(o * C + c) * 9 + t + 1] : 0.f;
        __nv_bfloat16 h = __float2bfloat16(w);
        int k = (c >> 3) * 64 + t * 8 + (c & 7);
        hi[(size_t)o * (C * 8) + k] = h;
        lo[(size_t)o * (C * 8) + k] = __float2bfloat16(w - __bfloat162float(h));
    }
}

// [O][C] fp32 -> split bf16 rows at rowoff (row stride C)
__global__ void split1x1_k(const float* __restrict__ src,
                           __nv_bfloat16* __restrict__ hi, __nv_bfloat16* __restrict__ lo,
                           int O, int C, int rowoff) {
    int i = blockIdx.x * 256 + threadIdx.x;
    if (i < O * C) {
        float w = src[i];
        __nv_bfloat16 h = __float2bfloat16(w);
        int o = i / C, c = i % C;
        hi[(rowoff + o) * C + c] = h;
        lo[(rowoff + o) * C + c] = __float2bfloat16(w - __bfloat162float(h));
    }
}

// fold bn1 affine into block1-entry weights: w' = w*s_c, bias = sum w*t_c
__global__ void foldentry_k(const float* __restrict__ c1w, const float* __restrict__ dsw,
                            const float* __restrict__ sc0, const float* __restrict__ sh0,
                            __nv_bfloat16* __restrict__ hi, __nv_bfloat16* __restrict__ lo,
                            float* __restrict__ bias) {
    int o = threadIdx.x;  // 128
    const float* src = (o < 64) ? (c1w + o * 16) : (dsw + (o - 64) * 16);
    float b = 0.f;
    for (int c = 0; c < 16; c++) {
        float w = src[c] * sc0[c];
        b += src[c] * sh0[c];
        __nv_bfloat16 h = __float2bfloat16(w);
        hi[o * 16 + c] = h;
        lo[o * 16 + c] = __float2bfloat16(w - __bfloat162float(h));
    }
    bias[o] = b;
}

// relu(sc*x+sh), position-major fp32 [pos][C] -> bf16 hi/lo [pos][C], elementwise
__global__ __launch_bounds__(256) void actsplitP_k(
    const float* __restrict__ x, const float* __restrict__ sc,
    const float* __restrict__ sh,
    __nv_bfloat16* __restrict__ hi, __nv_bfloat16* __restrict__ lo, int C) {
    size_t i = (size_t)blockIdx.x * 256 + threadIdx.x;   // quad index
    float4 v4 = *(const float4*)(x + i * 4);
    int c0 = (int)((i * 4) % C);
    float v[4] = {v4.x, v4.y, v4.z, v4.w};
    __align__(8) __nv_bfloat16 h4[4], l4[4];
#pragma unroll
    for (int j = 0; j < 4; j++) {
        float vv = fmaxf(sc[c0 + j] * v[j] + sh[c0 + j], 0.f);
        __nv_bfloat16 hb = __float2bfloat16(vv);
        h4[j] = hb;
        l4[j] = __float2bfloat16(vv - __bfloat162float(hb));
    }
    *(uint2*)(hi + i * 4) = *(uint2*)h4;
    *(uint2*)(lo + i * 4) = *(uint2*)l4;
}

// relu(s1*a+t1 + s2*b+t2), dual position-major inputs
__global__ __launch_bounds__(256) void actsplit2P_k(
    const float* __restrict__ xa, const float* __restrict__ xb,
    const float* __restrict__ s1, const float* __restrict__ t1,
    const float* __restrict__ s2, const float* __restrict__ t2,
    __nv_bfloat16* __restrict__ hi, __nv_bfloat16* __restrict__ lo, int C) {
    size_t i = (size_t)blockIdx.x * 256 + threadIdx.x;
    float4 a4 = *(const float4*)(xa + i * 4);
    float4 b4 = *(const float4*)(xb + i * 4);
    int c0 = (int)((i * 4) % C);
    float av[4] = {a4.x, a4.y, a4.z, a4.w};
    float bv[4] = {b4.x, b4.y, b4.z, b4.w};
    __align__(8) __nv_bfloat16 h4[4], l4[4];
#pragma unroll
    for (int j = 0; j < 4; j++) {
        float vv = fmaxf(s1[c0 + j] * av[j] + t1[c0 + j]
                       + s2[c0 + j] * bv[j] + t2[c0 + j], 0.f);
        __nv_bfloat16 hb = __float2bfloat16(vv);
        h4[j] = hb;
        l4[j] = __float2bfloat16(vv - __bfloat162float(hb));
    }
    *(uint2*)(hi + i * 4) = *(uint2*)h4;
    *(uint2*)(lo + i * 4) = *(uint2*)l4;
}

// ------------------------- stem: hexconv -> relu -> bf16 planes -------------
__global__ __launch_bounds__(256) void stem_kernel(
    const float* __restrict__ x, const float* __restrict__ wc,
    __nv_bfloat16* __restrict__ ahi, __nv_bfloat16* __restrict__ alo,
    float* __restrict__ psum, float* __restrict__ psq) {
    __shared__ float wsh[432];
    __shared__ float wpS[16][8], wpQ[16][8];
    int tid = threadIdx.x;
    for (int e = tid; e < 432; e += 256) wsh[e] = wc[e];
    __syncthreads();

    int pos = blockIdx.x * 256 + tid;
    int w = pos & 31, h = (pos >> 5) & 15, b = (pos >> 9) & 255, f = pos >> 17;

    float acc[16];
#pragma unroll
    for (int o = 0; o < 16; o++) acc[o] = 0.f;

#pragma unroll
    for (int t = 0; t < 7; t++) {
        int kf = t + 1;
        int dy = kf / 3 - 1, dx = kf % 3 - 1;
        int hh = h + dy;
        float xv0 = 0.f, xv1 = 0.f, xv2 = 0.f;
        if (hh >= 0 && hh < 16) {
            int ww = w + dx, ff = f;
            if (ww < 0)       { ff = (f + 4) % 5; ww = 31; }
            else if (ww > 31) { ff = (f + 1) % 5; ww = 0;  }
            int base = (ff * 256 + b) * 1536 + hh * 32 + ww;
            xv0 = x[base];
            xv1 = x[base + 512];
            xv2 = x[base + 1024];
        }
#pragma unroll
        for (int o = 0; o < 16; o++) {
            acc[o] += wsh[(o * 3 + 0) * 9 + kf] * xv0
                    + wsh[(o * 3 + 1) * 9 + kf] * xv1
                    + wsh[(o * 3 + 2) * 9 + kf] * xv2;
        }
    }

    __align__(16) __nv_bfloat16 h16[16];
    __align__(16) __nv_bfloat16 l16[16];
    int lane = tid & 31, warp = tid >> 5;
#pragma unroll
    for (int o = 0; o < 16; o++) {
        float val = fmaxf(acc[o], 0.f);
        __nv_bfloat16 hb = __float2bfloat16(val);
        h16[o] = hb;
        l16[o] = __float2bfloat16(val - __bfloat162float(hb));
        float s = val, q2 = val * val;
#pragma unroll
        for (int d = 16; d; d >>= 1) {
            s  += __shfl_xor_sync(0xFFFFFFFFu, s,  d);
            q2 += __shfl_xor_sync(0xFFFFFFFFu, q2, d);
        }
        if (lane == 0) { wpS[o][warp] = s; wpQ[o][warp] = q2; }
    }
    *(uint4*)(ahi + (size_t)pos * 16)     = *(uint4*)h16;
    *(uint4*)(ahi + (size_t)pos * 16 + 8) = *(uint4*)(h16 + 8);
    *(uint4*)(alo + (size_t)pos * 16)     = *(uint4*)l16;
    *(uint4*)(alo + (size_t)pos * 16 + 8) = *(uint4*)(l16 + 8);

    __syncthreads();
    if (tid < 16) {
        float s = 0.f, q = 0.f;
#pragma unroll
        for (int wpi = 0; wpi < 8; wpi++) { s += wpS[tid][wpi]; q += wpQ[tid][wpi]; }
        psum[blockIdx.x * 16 + tid] = s;
        psq [blockIdx.x * 16 + tid] = q;
    }
}

// ------------------------- BN param fold ------------------------------------
__global__ void bn_param(const float* __restrict__ ps, const float* __restrict__ pq,
                         int nparts, int cstride, int coff, float invN,
                         const float* __restrict__ g, const float* __restrict__ b,
                         float* __restrict__ sc, float* __restrict__ sh) {
    int c = blockIdx.x, tid = threadIdx.x;
    float s = 0.f, q = 0.f;
    for (int p = tid; p < nparts; p += 256) {
        s += ps[(size_t)p * cstride + coff + c];
        q += pq[(size_t)p * cstride + coff + c];
    }
    __shared__ float rs[256], rq[256];
    rs[tid] = s; rq[tid] = q;
    __syncthreads();
    for (int d = 128; d; d >>= 1) {
        if (tid < d) { rs[tid] += rs[tid + d]; rq[tid] += rq[tid + d]; }
        __syncthreads();
    }
    if (tid == 0) {
        float mean = rs[0] * invN;
        float var  = rq[0] * invN - mean * mean;
        float k = g[c] * rsqrtf(var + 1e-5f);
        sc[c] = k;
        sh[c] = b[c] - mean * k;
    }
}

// ---------------- generic mma.sync split-bf16 conv/GEMM ---------------------
// D[m=128, o=NTILE] = A[m, k] * W[o, k]; A from position-major bf16 planes [pos][CDIM].
// Outputs POSITION-MAJOR fp32: oc<OSPLIT -> outU[q*CU+oc] else outV[q*CV+oc-OSPLIT].
// TAPS=7: k = chunk*64 + t*8 + cl; TAPS=1: k = c. KCH = min(KTOT,64).
template <int KTOT, int NTILE, int TAPS, bool POOL, int HIN, int WIN,
          int NSTR, int OSPLIT, int CDIM, int CU, int CV>
__global__ __launch_bounds__(256) void mma_conv_k(
    const __nv_bfloat16* __restrict__ ahi, const __nv_bfloat16* __restrict__ alo,
    const __nv_bfloat16* __restrict__ whi, const __nv_bfloat16* __restrict__ wlo,
    const float* __restrict__ bias,
    float* __restrict__ outU, float* __restrict__ outV,
    float* __restrict__ psum, float* __restrict__ psq) {
    constexpr int NT = NTILE / 8;
    constexpr int KCH = (KTOT < 64) ? KTOT : 64;
    constexpr int NCHUNK = KTOT / KCH;
    constexpr int LDAv = KCH + 8;
    constexpr int GPR = KCH / 8;
    constexpr int KS = KCH / 16;
    constexpr int AITERS = (128 * GPR) / 256;
    constexpr int BITERS = (NTILE * GPR + 255) / 256;
    constexpr int OF_AH = 3584;
    constexpr int OF_AL = OF_AH + 128 * LDAv * 2;
    constexpr int OF_BH = OF_AL + 128 * LDAv * 2;
    constexpr int OF_BL = OF_BH + NTILE * LDAv * 2;
    constexpr int OF_PS = OF_BL + NTILE * LDAv * 2;
    constexpr int OF_PQ = OF_PS + NTILE * 32;

    extern __shared__ __align__(16) char smem[];
    uint32_t sb = smem_u32(smem);
    int tid = threadIdx.x;
    int wid = tid >> 5, lane = tid & 31;
    int q0 = blockIdx.x * 128;
    int o0 = blockIdx.y * NTILE;

    int* nbr = (int*)(smem);
    for (int e = tid; e < TAPS * 128; e += 256) {
        int t = e >> 7, ql = e & 127;
        int m = q0 + ql;
        int pos;
        if (POOL) {
            constexpr int WO = WIN / 2, HO = HIN / 2;
            int qq = m >> 2, sub = m & 3;
            int w = qq % WO;
            int h = (qq / WO) % HO;
            int fb = qq / (WO * HO);
            pos = (fb * HIN + 2 * h + (sub >> 1)) * WIN + 2 * w + (sub & 1);
        } else if (TAPS == 1) {
            pos = m;
        } else {
            int w = m % WIN;
            int h = (m / WIN) % HIN;
            int b = (m / (WIN * HIN)) & 255;
            int f = m / (WIN * HIN * 256);
            int kf = t + 1;
            int dy = kf / 3 - 1, dx = kf % 3 - 1;
            int hh = h + dy, ww = w + dx, ff = f;
            if (hh < 0 || hh >= HIN) pos = -1;
            else {
                if (ww < 0)        { ff = (f + 4) % 5; ww = WIN - 1; }
                else if (ww >= WIN){ ff = (f + 1) % 5; ww = 0;       }
                pos = ((ff * 256 + b) * HIN + hh) * WIN + ww;
            }
        }
        nbr[t * 128 + ql] = pos;
    }
    __syncthreads();

    float acc[NT][4];
#pragma unroll
    for (int nt = 0; nt < NT; nt++)
#pragma unroll
        for (int j = 0; j < 4; j++) acc[nt][j] = 0.f;

    int m0 = wid * 16;
    int grp = lane >> 3;
    int rowA = m0 + (lane & 7) + (grp & 1) * 8;
    int colA8 = (grp >> 1) * 8;
    uint32_t aBaseH = sb + OF_AH + (uint32_t)(rowA * LDAv + colA8) * 2;
    uint32_t aBaseL = sb + OF_AL + (uint32_t)(rowA * LDAv + colA8) * 2;
    int rowB = (lane & 7);
    int colB8 = ((lane >> 3) & 1) * 8;
    uint32_t bBaseH = sb + OF_BH + (uint32_t)(rowB * LDAv + colB8) * 2;
    uint32_t bBaseL = sb + OF_BL + (uint32_t)(rowB * LDAv + colB8) * 2;

    __nv_bfloat16* AH = (__nv_bfloat16*)(smem + OF_AH);
    __nv_bfloat16* AL = (__nv_bfloat16*)(smem + OF_AL);
    __nv_bfloat16* BH = (__nv_bfloat16*)(smem + OF_BH);
    __nv_bfloat16* BL = (__nv_bfloat16*)(smem + OF_BL);

#pragma unroll 1
    for (int ci = 0; ci < NCHUNK; ci++) {
        // stage A: [128 m][KCH k], vectorized uint4 (8 bf16 per op)
#pragma unroll
        for (int it = 0; it < AITERS; it++) {
            int e = it * 256 + tid;
            int q = e / GPR, g = e % GPR;
            uint4 vh = {0u, 0u, 0u, 0u}, vl = {0u, 0u, 0u, 0u};
            if (TAPS == 7) {
                if (g < 7) {
                    int pos = nbr[g * 128 + q];
                    if (pos >= 0) {
                        size_t base = (size_t)pos * CDIM + ci * 8;
                        vh = *(const uint4*)(ahi + base);
                        vl = *(const uint4*)(alo + base);
                    }
                }
            } else {
                int pos = nbr[q];
                size_t base = (size_t)pos * CDIM + ci * KCH + g * 8;
                vh = *(const uint4*)(ahi + base);
                vl = *(const uint4*)(alo + base);
            }
            *(uint4*)(AH + q * LDAv + g * 8) = vh;
            *(uint4*)(AL + q * LDAv + g * 8) = vl;
        }
        // stage B: [NTILE o][KCH k]
#pragma unroll
        for (int it = 0; it < BITERS; it++) {
            int e = it * 256 + tid;
            if (e < NTILE * GPR) {
                int o = e / GPR, j = e % GPR;
                size_t src = (size_t)(o0 + o) * KTOT + ci * KCH + j * 8;
                *(uint4*)(BH + o * LDAv + j * 8) = *(const uint4*)(whi + src);
                *(uint4*)(BL + o * LDAv + j * 8) = *(const uint4*)(wlo + src);
            }
        }
        __syncthreads();

#pragma unroll
        for (int ks = 0; ks < KS; ks++) {
            uint32_t aH[4], aL[4];
            ldmA(aH, aBaseH + ks * 32);
            ldmA(aL, aBaseL + ks * 32);
#pragma unroll
            for (int nt = 0; nt < NT; nt++) {
                uint32_t bH[2], bL[2];
                uint32_t boff = (uint32_t)(nt * 8 * LDAv) * 2 + ks * 32;
                ldmB(bH, bBaseH + boff);
                ldmB(bL, bBaseL + boff);
                mma16816(acc[nt], aH, bH);
                mma16816(acc[nt], aL, bH);
                mma16816(acc[nt], aH, bL);
            }
        }
        __syncthreads();
    }

    float* pS = (float*)(smem + OF_PS);
    float* pQ = (float*)(smem + OF_PQ);

    if (!POOL) {
        int r = lane >> 2;
        int cp = (lane & 3) << 1;
#pragma unroll
        for (int nt = 0; nt < NT; nt++) {
            int c0c = nt * 8 + cp;
            int qrow = q0 + m0 + r;
            int oc0 = o0 + c0c;
            bool inU = (oc0 < OSPLIT);
            float* base = inU ? (outU + (size_t)qrow * CU + oc0)
                              : (outV + (size_t)qrow * CV + (oc0 - OSPLIT));
            int stride = inU ? CU : CV;
            base[0] = acc[nt][0];
            base[1] = acc[nt][1];
            base[8 * stride]     = acc[nt][2];
            base[8 * stride + 1] = acc[nt][3];
            float s0 = acc[nt][0] + acc[nt][2];
            float s1 = acc[nt][1] + acc[nt][3];
            float t0 = acc[nt][0]*acc[nt][0] + acc[nt][2]*acc[nt][2];
            float t1 = acc[nt][1]*acc[nt][1] + acc[nt][3]*acc[nt][3];
#pragma unroll
            for (int d = 4; d <= 16; d <<= 1) {
                s0 += __shfl_xor_sync(0xFFFFFFFFu, s0, d);
                s1 += __shfl_xor_sync(0xFFFFFFFFu, s1, d);
                t0 += __shfl_xor_sync(0xFFFFFFFFu, t0, d);
                t1 += __shfl_xor_sync(0xFFFFFFFFu, t1, d);
            }
            if (r == 0) {
                pS[wid * NTILE + c0c]     = s0;
                pS[wid * NTILE + c0c + 1] = s1;
                pQ[wid * NTILE + c0c]     = t0;
                pQ[wid * NTILE + c0c + 1] = t1;
            }
        }
    } else {
        int cp = (lane & 3) << 1;
        bool writer = ((lane >> 2) & 3) == 0;
        int gsel = lane >> 4;
        int qout0 = blockIdx.x * 32 + wid * 4;
#pragma unroll
        for (int nt = 0; nt < NT; nt++) {
            float v0 = acc[nt][0], v1 = acc[nt][1];
            float v2 = acc[nt][2], v3 = acc[nt][3];
            if (bias) {
                float b0 = bias[o0 + nt * 8 + cp];
                float b1v = bias[o0 + nt * 8 + cp + 1];
                v0 += b0; v2 += b0; v1 += b1v; v3 += b1v;
            }
#pragma unroll
            for (int d = 4; d <= 8; d <<= 1) {
                v0 = fmaxf(v0, __shfl_xor_sync(0xFFFFFFFFu, v0, d));
                v1 = fmaxf(v1, __shfl_xor_sync(0xFFFFFFFFu, v1, d));
                v2 = fmaxf(v2, __shfl_xor_sync(0xFFFFFFFFu, v2, d));
                v3 = fmaxf(v3, __shfl_xor_sync(0xFFFFFFFFu, v3, d));
            }
            if (writer) {
                int oc0 = o0 + nt * 8 + cp;
                bool inU = (oc0 < OSPLIT);
                int oc = inU ? oc0 : (oc0 - OSPLIT);
                float* outp = inU ? outU : outV;
                int stride = inU ? CU : CV;
                int qa = qout0 + gsel;
                int qb2 = qout0 + 2 + gsel;
                outp[(size_t)qa * stride + oc]      = v0;
                outp[(size_t)qa * stride + oc + 1]  = v1;
                outp[(size_t)qb2 * stride + oc]     = v2;
                outp[(size_t)qb2 * stride + oc + 1] = v3;
            }
            float s0 = v0 + v2, s1 = v1 + v3;
            float t0 = v0 * v0 + v2 * v2, t1 = v1 * v1 + v3 * v3;
            s0 += __shfl_xor_sync(0xFFFFFFFFu, s0, 16);
            s1 += __shfl_xor_sync(0xFFFFFFFFu, s1, 16);
            t0 += __shfl_xor_sync(0xFFFFFFFFu, t0, 16);
            t1 += __shfl_xor_sync(0xFFFFFFFFu, t1, 16);
            if (lane < 4) {
                pS[wid * NTILE + nt * 8 + cp]     = s0;
                pS[wid * NTILE + nt * 8 + cp + 1] = s1;
                pQ[wid * NTILE + nt * 8 + cp]     = t0;
                pQ[wid * NTILE + nt * 8 + cp + 1] = t1;
            }
        }
    }
    __syncthreads();
    if (tid < NTILE) {
        float s = 0.f, q = 0.f;
#pragma unroll
        for (int w = 0; w < 8; w++) { s += pS[w * NTILE + tid]; q += pQ[w * NTILE + tid]; }
        psum[(size_t)blockIdx.x * NSTR + o0 + tid] = s;
        psq [(size_t)blockIdx.x * NSTR + o0 + tid] = q;
    }
}

// ------- final: BN+add+relu, global max (position-major inputs) -------------
__global__ __launch_bounds__(256) void maxfinP_k(
    const float* __restrict__ w2, const float* __restrict__ v2,
    const float* __restrict__ scC, const float* __restrict__ shC,
    const float* __restrict__ scD, const float* __restrict__ shD,
    float* __restrict__ gmax) {
    int b = blockIdx.x, o = threadIdx.x;
    float a = scC[o], c_ = shC[o], d = scD[o], e = shD[o];
    float mx = 0.f;
#pragma unroll 1
    for (int f = 0; f < 5; f++) {
        size_t rowbase = ((size_t)(f * 256 + b) * 32) * 256 + o;
#pragma unroll
        for (int i = 0; i < 32; i++) {
            size_t idx = rowbase + (size_t)i * 256;
            float val = a * w2[idx] + c_ + d * v2[idx] + e;
            mx = fmaxf(mx, fmaxf(val, 0.f));
        }
    }
    gmax[b * 256 + o] = mx;
}

__global__ void fc_k(const float* __restrict__ gmax, const float* __restrict__ fw,
                     const float* __restrict__ fb, float* __restrict__ out) {
    int b = blockIdx.x, tid = threadIdx.x;
    __shared__ float m[256];
    m[tid] = gmax[b * 256 + tid];
    __syncthreads();
    if (tid < 10) {
        float acc = fb[tid];
        for (int o = 0; o < 256; o++) acc += m[o] * fw[tid * 256 + o];
        out[b * 10 + tid] = acc;
    }
}

// ------------------------- launch ------------------------------------------
#define SM128 85504
#define SM64  62976
#define SMK16 36352

extern "C" void kernel_launch(void* const* d_in, const int* in_sizes, int n_in,
                              void* d_out, int out_size) {
    (void)n_in; (void)out_size;

    const float* x = (const float*)d_in[0];

    float *u1,*v1,*h1,*w1,*u2,*v2,*h2,*w2,*gmax,*ps,*pq,*sc,*sh,*bias2;
    __nv_bfloat16 *whex_hi,*whex_lo,*wb1h_hi,*wb1h_lo,*went_hi,*went_lo;
    __nv_bfloat16 *wc3_hi,*wc3_lo,*wb1c3_hi,*wb1c3_lo,*went2_hi,*went2_lo;
    __nv_bfloat16 *ahi,*alo;
    cudaGetSymbolAddress((void**)&u1, g_u1);
    cudaGetSymbolAddress((void**)&v1, g_v1);
    cudaGetSymbolAddress((void**)&h1, g_h1);
    cudaGetSymbolAddress((void**)&w1, g_w1);
    cudaGetSymbolAddress((void**)&u2, g_u2);
    cudaGetSymbolAddress((void**)&v2, g_v2);
    cudaGetSymbolAddress((void**)&h2, g_h2);
    cudaGetSymbolAddress((void**)&w2, g_w2);
    cudaGetSymbolAddress((void**)&gmax, g_gmax);
    cudaGetSymbolAddress((void**)&ps, g_psum);
    cudaGetSymbolAddress((void**)&pq, g_psq);
    cudaGetSymbolAddress((void**)&sc, g_scale);
    cudaGetSymbolAddress((void**)&sh, g_shift);
    cudaGetSymbolAddress((void**)&bias2, g_bias2);
    cudaGetSymbolAddress((void**)&whex_hi, g_whex_hi);
    cudaGetSymbolAddress((void**)&whex_lo, g_whex_lo);
    cudaGetSymbolAddress((void**)&wb1h_hi, g_wb1h_hi);
    cudaGetSymbolAddress((void**)&wb1h_lo, g_wb1h_lo);
    cudaGetSymbolAddress((void**)&went_hi, g_went_hi);
    cudaGetSymbolAddress((void**)&went_lo, g_went_lo);
    cudaGetSymbolAddress((void**)&wc3_hi, g_wc3_hi);
    cudaGetSymbolAddress((void**)&wc3_lo, g_wc3_lo);
    cudaGetSymbolAddress((void**)&wb1c3_hi, g_wb1c3_hi);
    cudaGetSymbolAddress((void**)&wb1c3_lo, g_wb1c3_lo);
    cudaGetSymbolAddress((void**)&went2_hi, g_went2_hi);
    cudaGetSymbolAddress((void**)&went2_lo, g_went2_lo);
    cudaGetSymbolAddress((void**)&ahi, g_abf_hi);
    cudaGetSymbolAddress((void**)&alo, g_abf_lo);

    // input index tables (runtime disambiguation of metadata order)
    int I_b1c1, I_b1hex, I_b1c3, I_b1ds;
    int I_b1ga, I_b1ba, I_b1gb, I_b1bb, I_b1gc, I_b1bc, I_b1gd, I_b1bd;
    int I_b2c1, I_b2hex, I_b2c3, I_b2ds;
    int I_b2ga, I_b2ba, I_b2gb, I_b2bb, I_b2gc, I_b2bc, I_b2gd, I_b2bd;
    int I_fcw, I_fcb;
    if (in_sizes[5] == 36864) {
        I_b1c1 = 4;  I_b1hex = 5;  I_b1c3 = 6;  I_b1ds = 7;
        I_b1ga = 8;  I_b1ba = 9;  I_b1gb = 10; I_b1bb = 11;
        I_b1gc = 12; I_b1bc = 13; I_b1gd = 14; I_b1bd = 15;
        I_b2c1 = 16; I_b2hex = 17; I_b2c3 = 18; I_b2ds = 19;
        I_b2ga = 20; I_b2ba = 21; I_b2gb = 22; I_b2bb = 23;
        I_b2gc = 24; I_b2bc = 25; I_b2gd = 26; I_b2bd = 27;
        I_fcw = 28;  I_fcb = 29;
    } else {
        I_b1c1 = 4;  I_b1ga = 5;  I_b1ba = 6;  I_b1hex = 7;
        I_b1gb = 8;  I_b1bb = 9;  I_b1c3 = 10; I_b1gc = 11; I_b1bc = 12;
        I_b1ds = 13; I_b1gd = 14; I_b1bd = 15;
        I_b2c1 = 16; I_b2ga = 17; I_b2ba = 18; I_b2hex = 19;
        I_b2gb = 20; I_b2bb = 21; I_b2c3 = 22; I_b2gc = 23; I_b2bc = 24;
        I_b2ds = 25; I_b2gd = 26; I_b2bd = 27;
        I_fcw = 28;  I_fcb = 29;
    }

    // set smem limits for mma instantiations
    cudaFuncSetAttribute(mma_conv_k<16, 128, 1, true, 16, 32, 128, 64, 16, 64, 64>,
                         cudaFuncAttributeMaxDynamicSharedMemorySize, SMK16);
    cudaFuncSetAttribute(mma_conv_k<512, 64, 7, false, 8, 16, 64, 64, 64, 64, 1>,
                         cudaFuncAttributeMaxDynamicSharedMemorySize, SM64);
    cudaFuncSetAttribute(mma_conv_k<64, 64, 1, false, 8, 16, 64, 64, 64, 64, 1>,
                         cudaFuncAttributeMaxDynamicSharedMemorySize, SM64);
    cudaFuncSetAttribute(mma_conv_k<64, 128, 1, true, 8, 16, 512, 256, 64, 256, 256>,
                         cudaFuncAttributeMaxDynamicSharedMemorySize, SM128);
    cudaFuncSetAttribute(mma_conv_k<2048, 128, 7, false, 4, 8, 256, 256, 256, 256, 1>,
                         cudaFuncAttributeMaxDynamicSharedMemorySize, SM128);
    cudaFuncSetAttribute(mma_conv_k<256, 128, 1, false, 4, 8, 256, 256, 256, 256, 1>,
                         cudaFuncAttributeMaxDynamicSharedMemorySize, SM128);

    // weight prep
    hexsplit_k<<<2048, 256>>>((const float*)d_in[I_b2hex], whex_hi, whex_lo, 256, 256);
    hexsplit_k<<<128,  256>>>((const float*)d_in[I_b1hex], wb1h_hi, wb1h_lo, 64, 64);
    split1x1_k<<<64,  256>>>((const float*)d_in[I_b2c1], went_hi, went_lo, 256, 64, 0);
    split1x1_k<<<64,  256>>>((const float*)d_in[I_b2ds], went_hi, went_lo, 256, 64, 256);
    split1x1_k<<<256, 256>>>((const float*)d_in[I_b2c3], wc3_hi, wc3_lo, 256, 256, 0);
    split1x1_k<<<16,  256>>>((const float*)d_in[I_b1c3], wb1c3_hi, wb1c3_lo, 64, 64, 0);

    // stem: hexconv -> relu -> bf16 planes [pos][16] + bn1 stats
    stem_kernel<<<NP0 / 256, 256>>>(x, (const float*)d_in[1], ahi, alo, ps, pq);
    bn_param<<<16, 256>>>(ps, pq, NP0 / 256, 16, 0, 1.f / NP0,
                          (const float*)d_in[2], (const float*)d_in[3], sc + 0, sh + 0);
    foldentry_k<<<1, 128>>>((const float*)d_in[I_b1c1], (const float*)d_in[I_b1ds],
                            sc + 0, sh + 0, went2_hi, went2_lo, bias2);

    // block1 entry (mma, K=16, pooled, bias, N=128 = main||ds)
    mma_conv_k<16, 128, 1, true, 16, 32, 128, 64, 16, 64, 64>
        <<<dim3(NP0 / 128, 1), 256, SMK16>>>(ahi, alo, went2_hi, went2_lo, bias2,
                                             u1, v1, ps, pq);
    bn_param<<<64, 256>>>(ps, pq, NP0 / 128, 128, 0,  1.f / NP1,
                          (const float*)d_in[I_b1ga], (const float*)d_in[I_b1ba], sc + 16,  sh + 16);
    bn_param<<<64, 256>>>(ps, pq, NP0 / 128, 128, 64, 1.f / NP1,
                          (const float*)d_in[I_b1gd], (const float*)d_in[I_b1bd], sc + 208, sh + 208);

    // block1 hexconv (mma)
    actsplitP_k<<<NP1 * 64 / 1024, 256>>>(u1, sc + 16, sh + 16, ahi, alo, 64);
    mma_conv_k<512, 64, 7, false, 8, 16, 64, 64, 64, 64, 1>
        <<<dim3(NP1 / 128, 1), 256, SM64>>>(ahi, alo, wb1h_hi, wb1h_lo, nullptr,
                                            h1, nullptr, ps, pq);
    bn_param<<<64, 256>>>(ps, pq, NP1 / 128, 64, 0, 1.f / NP1,
                          (const float*)d_in[I_b1gb], (const float*)d_in[I_b1bb], sc + 80, sh + 80);

    // block1 conv3 1x1 (mma)
    actsplitP_k<<<NP1 * 64 / 1024, 256>>>(h1, sc + 80, sh + 80, ahi, alo, 64);
    mma_conv_k<64, 64, 1, false, 8, 16, 64, 64, 64, 64, 1>
        <<<dim3(NP1 / 128, 1), 256, SM64>>>(ahi, alo, wb1c3_hi, wb1c3_lo, nullptr,
                                            w1, nullptr, ps, pq);
    bn_param<<<64, 256>>>(ps, pq, NP1 / 128, 64, 0, 1.f / NP1,
                          (const float*)d_in[I_b1gc], (const float*)d_in[I_b1bc], sc + 144, sh + 144);

    // block2 entry (mma, dual input, pooled, N=512 = main||ds)
    actsplit2P_k<<<NP1 * 64 / 1024, 256>>>(w1, v1, sc + 144, sh + 144,
                                           sc + 208, sh + 208, ahi, alo, 64);
    mma_conv_k<64, 128, 1, true, 8, 16, 512, 256, 64, 256, 256>
        <<<dim3(NP1 / 128, 4), 256, SM128>>>(ahi, alo, went_hi, went_lo, nullptr,
                                             u2, v2, ps, pq);
    bn_param<<<256, 256>>>(ps, pq, NP1 / 128, 512, 0,   1.f / NP2,
                           (const float*)d_in[I_b2ga], (const float*)d_in[I_b2ba], sc + 272,  sh + 272);
    bn_param<<<256, 256>>>(ps, pq, NP1 / 128, 512, 256, 1.f / NP2,
                           (const float*)d_in[I_b2gd], (const float*)d_in[I_b2bd], sc + 1040, sh + 1040);

    // block2 hexconv (mma)
    actsplitP_k<<<NP2 * 256 / 1024, 256>>>(u2, sc + 272, sh + 272, ahi, alo, 256);
    mma_conv_k<2048, 128, 7, false, 4, 8, 256, 256, 256, 256, 1>
        <<<dim3(NP2 / 128, 2), 256, SM128>>>(ahi, alo, whex_hi, whex_lo, nullptr,
                                             h2, nullptr, ps, pq);
    bn_param<<<256, 256>>>(ps, pq, NP2 / 128, 256, 0, 1.f / NP2,
                           (const float*)d_in[I_b2gb], (const float*)d_in[I_b2bb], sc + 528, sh + 528);

    // block2 conv3 1x1 (mma)
    actsplitP_k<<<NP2 * 256 / 1024, 256>>>(h2, sc + 528, sh + 528, ahi, alo, 256);
    mma_conv_k<256, 128, 1, false, 4, 8, 256, 256, 256, 256, 1>
        <<<dim3(NP2 / 128, 2), 256, SM128>>>(ahi, alo, wc3_hi, wc3_lo, nullptr,
                                             w2, nullptr, ps, pq);
    bn_param<<<256, 256>>>(ps, pq, NP2 / 128, 256, 0, 1.f / NP2,
                           (const float*)d_in[I_b2gc], (const float*)d_in[I_b2bc], sc + 784, sh + 784);

    // tail
    maxfinP_k<<<256, 256>>>(w2, v2, sc + 784, sh + 784, sc + 1040, sh + 1040, gmax);
    fc_k<<<256, 256>>>(gmax, (const float*)d_in[I_fcw], (const float*)d_in[I_fcb], (float*)d_out);
}